// round 2
// baseline (speedup 1.0000x reference)
#include <cuda_runtime.h>
#include <cuda_bf16.h>
#include <cstdint>

// ---------------------------------------------------------------------------
// Problem constants (fixed by setup_inputs)
// ---------------------------------------------------------------------------
#define BB      2
#define SS      2048
#define DM      1024
#define NH      16
#define NKV     4
#define DK      64
#define DFF     4096
#define QKVC    1536          // DM + 2*NKV*DK
#define ROWS    (BB*SS)       // 4096

// ---------------------------------------------------------------------------
// Scratch (static device allocations; allowed by harness rules)
// ---------------------------------------------------------------------------
__device__ float g_qkv    [ROWS * QKVC];   // 25 MB
__device__ float g_ctx    [ROWS * DM];
__device__ float g_attnout[ROWS * DM];
__device__ float g_x1     [ROWS * DM];
__device__ float g_h      [ROWS * DFF];    // 67 MB
__device__ float g_glu    [ROWS * (DFF/2)];
__device__ float g_ffn    [ROWS * DM];

// ---------------------------------------------------------------------------
// SGEMM: C[M,N] = A[M,K] @ B[K,N] + bias[N]
// 128x128 tile, BK=8, 256 threads, 8x8 micro-tile (split 4+4 for conflict-free
// float4 smem access). M%128==0, N%128==0, K%8==0 guaranteed by shapes.
// ---------------------------------------------------------------------------
__global__ __launch_bounds__(256)
void sgemm_bias(int M, int N, int K,
                const float* __restrict__ A,
                const float* __restrict__ B,
                const float* __restrict__ bias,
                float* __restrict__ C)
{
    __shared__ float As[8][128];
    __shared__ float Bs[8][128];

    const int t  = threadIdx.x;
    const int tx = t & 15;
    const int ty = t >> 4;
    const int bm = blockIdx.y * 128;
    const int bn = blockIdx.x * 128;

    // load mapping
    const int a_row = t >> 1;          // 0..127
    const int a_k   = (t & 1) * 4;     // 0 or 4
    const int b_k   = t >> 5;          // 0..7
    const int b_n   = (t & 31) * 4;    // 0..124

    const float* Ag = A + (size_t)(bm + a_row) * K + a_k;
    const float* Bg = B + (size_t)b_k * N + bn + b_n;

    float acc[8][8];
#pragma unroll
    for (int i = 0; i < 8; i++)
#pragma unroll
        for (int j = 0; j < 8; j++) acc[i][j] = 0.f;

    for (int k0 = 0; k0 < K; k0 += 8) {
        float4 av = *(const float4*)(Ag + k0);
        float4 bv = *(const float4*)(Bg + (size_t)k0 * N);

        As[a_k + 0][a_row] = av.x;
        As[a_k + 1][a_row] = av.y;
        As[a_k + 2][a_row] = av.z;
        As[a_k + 3][a_row] = av.w;
        *(float4*)&Bs[b_k][b_n] = bv;
        __syncthreads();

#pragma unroll
        for (int kk = 0; kk < 8; kk++) {
            float4 a0 = *(const float4*)&As[kk][ty * 4];
            float4 a1 = *(const float4*)&As[kk][64 + ty * 4];
            float4 b0 = *(const float4*)&Bs[kk][tx * 4];
            float4 b1 = *(const float4*)&Bs[kk][64 + tx * 4];
            float ar[8] = {a0.x, a0.y, a0.z, a0.w, a1.x, a1.y, a1.z, a1.w};
            float br[8] = {b0.x, b0.y, b0.z, b0.w, b1.x, b1.y, b1.z, b1.w};
#pragma unroll
            for (int i = 0; i < 8; i++)
#pragma unroll
                for (int j = 0; j < 8; j++)
                    acc[i][j] += ar[i] * br[j];
        }
        __syncthreads();
    }

    // bias
    float bj[8];
#pragma unroll
    for (int j = 0; j < 4; j++) {
        bj[j]     = bias[bn + tx * 4 + j];
        bj[j + 4] = bias[bn + 64 + tx * 4 + j];
    }

#pragma unroll
    for (int i = 0; i < 8; i++) {
        int row = bm + ((i < 4) ? (ty * 4 + i) : (64 + ty * 4 + (i - 4)));
        float* Crow = C + (size_t)row * N + bn;
        float4 r0 = make_float4(acc[i][0] + bj[0], acc[i][1] + bj[1],
                                acc[i][2] + bj[2], acc[i][3] + bj[3]);
        float4 r1 = make_float4(acc[i][4] + bj[4], acc[i][5] + bj[5],
                                acc[i][6] + bj[6], acc[i][7] + bj[7]);
        *(float4*)(Crow + tx * 4)      = r0;
        *(float4*)(Crow + 64 + tx * 4) = r1;
    }
}

// ---------------------------------------------------------------------------
// Flash attention (fp32), GQA + ALiBi + key mask, non-causal.
// Grid: (S/64, NH, B). Block: 256 threads (16x16). q-tile = 64, k-tile = 64.
// Writes ctx in [B,S,H*DK] layout (ready for ctx @ Wo).
// ---------------------------------------------------------------------------
#define PS_STRIDE 72
#define FLASH_SMEM ((3 * 64 * 64 + 64 * PS_STRIDE + SS) * 4)

__global__ __launch_bounds__(256)
void flash_attn(const float* __restrict__ qkv,
                const int* __restrict__ attn_mask,
                float* __restrict__ ctx)
{
    extern __shared__ float sm[];
    float* Qt = sm;                 // [64 d][64 q]  (d-major, prescaled)
    float* Kt = Qt + 64 * 64;       // [64 d][64 k]
    float* Vs = Kt + 64 * 64;       // [64 k][64 d]
    float* Ps = Vs + 64 * 64;       // [64 k][72]  (k-major P^T)
    float* mb = Ps + 64 * PS_STRIDE; // [S] mask bias

    const int t  = threadIdx.x;
    const int tx = t & 15;
    const int ty = t >> 4;
    const int q0 = blockIdx.x * 64;
    const int h  = blockIdx.y;
    const int b  = blockIdx.z;
    const int kv = h >> 2;

    const float slope = exp2f(-(float)(h + 1));   // ALIBI_ALPHA = 1
    const float scale = 0.125f;                    // 1/sqrt(64)

    // mask bias
    for (int k = t; k < SS; k += 256)
        mb[k] = (attn_mask[b * SS + k] == 0) ? -1e9f : 0.f;

    // load Q tile transposed + prescaled
    {
        const int qc = t >> 2;
        const int ds = (t & 3) * 16;
        const float* src = qkv + (size_t)(b * SS + q0 + qc) * QKVC + h * DK + ds;
#pragma unroll
        for (int e = 0; e < 4; e++) {
            float4 v = *(const float4*)(src + e * 4);
            int d = ds + e * 4;
            Qt[(d + 0) * 64 + qc] = v.x * scale;
            Qt[(d + 1) * 64 + qc] = v.y * scale;
            Qt[(d + 2) * 64 + qc] = v.z * scale;
            Qt[(d + 3) * 64 + qc] = v.w * scale;
        }
    }

    float m_i[4], l_i[4], o[4][4];
#pragma unroll
    for (int i = 0; i < 4; i++) {
        m_i[i] = -1e30f;
        l_i[i] = 0.f;
#pragma unroll
        for (int j = 0; j < 4; j++) o[i][j] = 0.f;
    }

    for (int kt = 0; kt < SS / 64; kt++) {
        const int k0 = kt * 64;
        // load K transposed, V natural
        {
            const int kc = t >> 2;
            const int ds = (t & 3) * 16;
            const float* srcK = qkv + (size_t)(b * SS + k0 + kc) * QKVC + DM + kv * DK + ds;
            const float* srcV = qkv + (size_t)(b * SS + k0 + kc) * QKVC + DM + NKV * DK + kv * DK + ds;
#pragma unroll
            for (int e = 0; e < 4; e++) {
                int d = ds + e * 4;
                float4 kf = *(const float4*)(srcK + e * 4);
                Kt[(d + 0) * 64 + kc] = kf.x;
                Kt[(d + 1) * 64 + kc] = kf.y;
                Kt[(d + 2) * 64 + kc] = kf.z;
                Kt[(d + 3) * 64 + kc] = kf.w;
                float4 vf = *(const float4*)(srcV + e * 4);
                *(float4*)&Vs[kc * 64 + d] = vf;
            }
        }
        __syncthreads();

        // scores s = (Q*scale) @ K^T
        float s[4][4];
#pragma unroll
        for (int i = 0; i < 4; i++)
#pragma unroll
            for (int j = 0; j < 4; j++) s[i][j] = 0.f;

#pragma unroll 8
        for (int kk = 0; kk < 64; kk++) {
            float4 qf = *(const float4*)(Qt + kk * 64 + ty * 4);
            float4 kf = *(const float4*)(Kt + kk * 64 + tx * 4);
            float qa[4] = {qf.x, qf.y, qf.z, qf.w};
            float ka[4] = {kf.x, kf.y, kf.z, kf.w};
#pragma unroll
            for (int i = 0; i < 4; i++)
#pragma unroll
                for (int j = 0; j < 4; j++)
                    s[i][j] += qa[i] * ka[j];
        }

        // ALiBi + mask
#pragma unroll
        for (int i = 0; i < 4; i++) {
            float qpos = (float)(q0 + ty * 4 + i);
#pragma unroll
            for (int j = 0; j < 4; j++) {
                int kidx = k0 + tx * 4 + j;
                s[i][j] += slope * (qpos - (float)kidx) + mb[kidx];
            }
        }

        // online softmax (row groups share ty; reduce across 16 tx lanes)
#pragma unroll
        for (int i = 0; i < 4; i++) {
            float mx = fmaxf(fmaxf(s[i][0], s[i][1]), fmaxf(s[i][2], s[i][3]));
            mx = fmaxf(mx, __shfl_xor_sync(0xffffffffu, mx, 1, 16));
            mx = fmaxf(mx, __shfl_xor_sync(0xffffffffu, mx, 2, 16));
            mx = fmaxf(mx, __shfl_xor_sync(0xffffffffu, mx, 4, 16));
            mx = fmaxf(mx, __shfl_xor_sync(0xffffffffu, mx, 8, 16));
            float mn = fmaxf(m_i[i], mx);
            float al = __expf(m_i[i] - mn);
            m_i[i] = mn;
            float rs = 0.f;
#pragma unroll
            for (int j = 0; j < 4; j++) {
                s[i][j] = __expf(s[i][j] - mn);
                rs += s[i][j];
            }
            rs += __shfl_xor_sync(0xffffffffu, rs, 1, 16);
            rs += __shfl_xor_sync(0xffffffffu, rs, 2, 16);
            rs += __shfl_xor_sync(0xffffffffu, rs, 4, 16);
            rs += __shfl_xor_sync(0xffffffffu, rs, 8, 16);
            l_i[i] = l_i[i] * al + rs;
#pragma unroll
            for (int j = 0; j < 4; j++) o[i][j] *= al;
        }

        // store P transposed: Ps[kcol][qrow]
#pragma unroll
        for (int j = 0; j < 4; j++) {
            float4 col = make_float4(s[0][j], s[1][j], s[2][j], s[3][j]);
            *(float4*)(Ps + (tx * 4 + j) * PS_STRIDE + ty * 4) = col;
        }
        __syncthreads();

        // O += P @ V
#pragma unroll 8
        for (int kk = 0; kk < 64; kk++) {
            float4 pf = *(const float4*)(Ps + kk * PS_STRIDE + ty * 4);
            float4 vf = *(const float4*)(Vs + kk * 64 + tx * 4);
            float pa[4] = {pf.x, pf.y, pf.z, pf.w};
            float va[4] = {vf.x, vf.y, vf.z, vf.w};
#pragma unroll
            for (int i = 0; i < 4; i++)
#pragma unroll
                for (int j = 0; j < 4; j++)
                    o[i][j] += pa[i] * va[j];
        }
        __syncthreads();
    }

    // write ctx [B,S,H*DK]
#pragma unroll
    for (int i = 0; i < 4; i++) {
        float inv = 1.f / l_i[i];
        float4 w = make_float4(o[i][0] * inv, o[i][1] * inv,
                               o[i][2] * inv, o[i][3] * inv);
        *(float4*)(ctx + (size_t)(b * SS + q0 + ty * 4 + i) * DM + h * DK + tx * 4) = w;
    }
}

// ---------------------------------------------------------------------------
// y = LayerNorm(a + (pad ? 0 : r)) * gamma + beta, row length 1024
// Grid: ROWS blocks, 256 threads, one float4 per thread.
// ---------------------------------------------------------------------------
__global__ __launch_bounds__(256)
void add_ln_kernel(const float* __restrict__ a,
                   const float* __restrict__ r,
                   const unsigned char* __restrict__ pad,
                   const float* __restrict__ gamma,
                   const float* __restrict__ beta,
                   float* __restrict__ out)
{
    __shared__ float s_sum[8], s_sq[8];
    const int row = blockIdx.x;
    const int t = threadIdx.x;

    float4 va = *(const float4*)(a + (size_t)row * DM + t * 4);
    float4 vr = *(const float4*)(r + (size_t)row * DM + t * 4);
    if (pad && pad[row]) vr = make_float4(0.f, 0.f, 0.f, 0.f);
    float4 v = make_float4(va.x + vr.x, va.y + vr.y, va.z + vr.z, va.w + vr.w);

    float sum = v.x + v.y + v.z + v.w;
    float sq  = v.x * v.x + v.y * v.y + v.z * v.z + v.w * v.w;
#pragma unroll
    for (int off = 16; off > 0; off >>= 1) {
        sum += __shfl_xor_sync(0xffffffffu, sum, off);
        sq  += __shfl_xor_sync(0xffffffffu, sq, off);
    }
    if ((t & 31) == 0) { s_sum[t >> 5] = sum; s_sq[t >> 5] = sq; }
    __syncthreads();
    sum = 0.f; sq = 0.f;
#pragma unroll
    for (int w = 0; w < 8; w++) { sum += s_sum[w]; sq += s_sq[w]; }

    const float mean = sum * (1.f / (float)DM);
    const float var  = sq * (1.f / (float)DM) - mean * mean;
    const float rs   = rsqrtf(var + 1e-5f);

    float4 gg = *(const float4*)(gamma + t * 4);
    float4 bb = *(const float4*)(beta + t * 4);
    float4 y = make_float4((v.x - mean) * rs * gg.x + bb.x,
                           (v.y - mean) * rs * gg.y + bb.y,
                           (v.z - mean) * rs * gg.z + bb.z,
                           (v.w - mean) * rs * gg.w + bb.w);
    *(float4*)(out + (size_t)row * DM + t * 4) = y;
}

// ---------------------------------------------------------------------------
// SwiGLU: g[row, c] = silu(h[row, c]) * h[row, 2048 + c], zero where pad
// ---------------------------------------------------------------------------
__global__ __launch_bounds__(256)
void glu_kernel(const float* __restrict__ h,
                const unsigned char* __restrict__ pad,
                float* __restrict__ g)
{
    const int idx = blockIdx.x * 256 + threadIdx.x;      // float4 index
    const int row = idx / (DFF / 2 / 4);
    const int c4  = idx % (DFF / 2 / 4);
    float4 a = *(const float4*)(h + (size_t)row * DFF + c4 * 4);
    float4 b = *(const float4*)(h + (size_t)row * DFF + DFF / 2 + c4 * 4);
    float4 y;
    y.x = (a.x / (1.f + __expf(-a.x))) * b.x;
    y.y = (a.y / (1.f + __expf(-a.y))) * b.y;
    y.z = (a.z / (1.f + __expf(-a.z))) * b.z;
    y.w = (a.w / (1.f + __expf(-a.w))) * b.w;
    if (pad[row]) y = make_float4(0.f, 0.f, 0.f, 0.f);
    *(float4*)(g + (size_t)row * (DFF / 2) + c4 * 4) = y;
}

// ---------------------------------------------------------------------------
// Launch
// ---------------------------------------------------------------------------
extern "C" void kernel_launch(void* const* d_in, const int* in_sizes, int n_in,
                              void* d_out, int out_size)
{
    const float* x          = (const float*)d_in[0];
    const int*   attn_mask  = (const int*)d_in[1];
    const unsigned char* seq_mask = (const unsigned char*)d_in[2];
    const float* Wc  = (const float*)d_in[3];
    const float* bc  = (const float*)d_in[4];
    const float* Wo  = (const float*)d_in[5];
    const float* bo  = (const float*)d_in[6];
    const float* W1  = (const float*)d_in[7];
    const float* b1  = (const float*)d_in[8];
    const float* W2  = (const float*)d_in[9];
    const float* b2  = (const float*)d_in[10];
    const float* g1  = (const float*)d_in[11];
    const float* be1 = (const float*)d_in[12];
    const float* g2  = (const float*)d_in[13];
    const float* be2 = (const float*)d_in[14];
    float* out = (float*)d_out;

    float *qkv, *ctx, *attnout, *x1, *h, *glu, *ffn;
    cudaGetSymbolAddress((void**)&qkv,     g_qkv);
    cudaGetSymbolAddress((void**)&ctx,     g_ctx);
    cudaGetSymbolAddress((void**)&attnout, g_attnout);
    cudaGetSymbolAddress((void**)&x1,      g_x1);
    cudaGetSymbolAddress((void**)&h,       g_h);
    cudaGetSymbolAddress((void**)&glu,     g_glu);
    cudaGetSymbolAddress((void**)&ffn,     g_ffn);

    cudaFuncSetAttribute(flash_attn, cudaFuncAttributeMaxDynamicSharedMemorySize,
                         FLASH_SMEM);

    // 1) qkv = x @ Wc + bc
    sgemm_bias<<<dim3(QKVC / 128, ROWS / 128), 256>>>(ROWS, QKVC, DM, x, Wc, bc, qkv);

    // 2) attention -> ctx
    flash_attn<<<dim3(SS / 64, NH, BB), 256, FLASH_SMEM>>>(qkv, attn_mask, ctx);

    // 3) attn_out = ctx @ Wo + bo
    sgemm_bias<<<dim3(DM / 128, ROWS / 128), 256>>>(ROWS, DM, DM, ctx, Wo, bo, attnout);

    // 4) x1 = LN(x + attn_out)
    add_ln_kernel<<<ROWS, 256>>>(x, attnout, nullptr, g1, be1, x1);

    // 5) h = x1 @ W1 + b1
    sgemm_bias<<<dim3(DFF / 128, ROWS / 128), 256>>>(ROWS, DFF, DM, x1, W1, b1, h);

    // 6) glu = silu(h1)*h2 (pad-zeroed)
    glu_kernel<<<(ROWS * (DFF / 2) / 4) / 256, 256>>>(h, seq_mask, glu);

    // 7) ffn = glu @ W2 + b2
    sgemm_bias<<<dim3(DM / 128, ROWS / 128), 256>>>(ROWS, DM, DFF / 2, glu, W2, b2, ffn);

    // 8) out = LN(x1 + (pad ? 0 : ffn))
    add_ln_kernel<<<ROWS, 256>>>(x1, ffn, seq_mask, g2, be2, out);
}

// round 5
// speedup vs baseline: 1.5915x; 1.5915x over previous
#include <cuda_runtime.h>
#include <cuda_bf16.h>
#include <cstdint>

// ---------------------------------------------------------------------------
// Problem constants (fixed by setup_inputs)
// ---------------------------------------------------------------------------
#define BB      2
#define SS      2048
#define DM      1024
#define NH      16
#define NKV     4
#define DK      64
#define DFF     4096
#define QKVC    1536          // DM + 2*NKV*DK
#define ROWS    (BB*SS)       // 4096

// ---------------------------------------------------------------------------
// Scratch (static device allocations; allowed by harness rules)
// ---------------------------------------------------------------------------
__device__ float g_qkv    [ROWS * QKVC];
__device__ float g_ctx    [ROWS * DM];
__device__ float g_attnout[ROWS * DM];
__device__ float g_x1     [ROWS * DM];
__device__ float g_h      [ROWS * DFF];
__device__ float g_glu    [ROWS * (DFF/2)];
__device__ float g_ffn    [ROWS * DM];

// ---------------------------------------------------------------------------
// tf32 tensor-core GEMM: C[M,N] = A[M,K] @ B[K,N] + bias[N]
// Block tile 128x128, BK=16, 256 threads (8 warps, 2x4), warp tile 64x32.
// A smem [128][20] row-major; B smem [128][20] stored n-major (transposed),
// both fragment-loaded with ldmatrix.x4. fp32 accumulate.
// Requires M%128==0, N%128==0, K%16==0 (true for all shapes here).
// ---------------------------------------------------------------------------
#define GPAD 20

__device__ __forceinline__ float to_tf32(float x) {
    float r;
    asm("cvt.rna.tf32.f32 %0, %1;" : "=f"(r) : "f"(x));
    return r;
}

__device__ __forceinline__ void ldsm4(uint32_t& r0, uint32_t& r1,
                                      uint32_t& r2, uint32_t& r3,
                                      uint32_t addr) {
    asm volatile("ldmatrix.sync.aligned.m8n8.x4.shared.b16 {%0,%1,%2,%3}, [%4];"
                 : "=r"(r0), "=r"(r1), "=r"(r2), "=r"(r3) : "r"(addr));
}

__device__ __forceinline__ void mma_tf32(float* c, const uint32_t* a,
                                         uint32_t b0, uint32_t b1) {
    asm volatile(
        "mma.sync.aligned.m16n8k8.row.col.f32.tf32.tf32.f32 "
        "{%0,%1,%2,%3}, {%4,%5,%6,%7}, {%8,%9}, {%0,%1,%2,%3};"
        : "+f"(c[0]), "+f"(c[1]), "+f"(c[2]), "+f"(c[3])
        : "r"(a[0]), "r"(a[1]), "r"(a[2]), "r"(a[3]), "r"(b0), "r"(b1));
}

__global__ __launch_bounds__(256)
void tf32_gemm_bias(int M, int N, int K,
                    const float* __restrict__ A,
                    const float* __restrict__ B,
                    const float* __restrict__ bias,
                    float* __restrict__ C)
{
    __shared__ float As[2][128][GPAD];
    __shared__ float Bs[2][128][GPAD];

    const int t    = threadIdx.x;
    const int lane = t & 31;
    const int w    = t >> 5;
    const int wm   = (w >> 2) * 64;   // warp m offset within tile
    const int wn   = (w & 3) * 32;    // warp n offset within tile
    const int bm   = blockIdx.y * 128;
    const int bn   = blockIdx.x * 128;

    // A load mapping: thread -> rows (t>>2) and (t>>2)+64, cols (t&3)*4..+3
    const int a_row = t >> 2;
    const int a_col = (t & 3) * 4;
    const float* Ag = A + (size_t)(bm + a_row) * K + a_col;

    // B load mapping: thread -> column n = t&127, k rows (t>>7)*8 .. +7
    const int b_n = t & 127;
    const int b_k = (t >> 7) * 8;
    const float* Bg = B + (size_t)b_k * N + bn + b_n;

    float acc[4][4][4];
#pragma unroll
    for (int i = 0; i < 4; i++)
#pragma unroll
        for (int j = 0; j < 4; j++)
#pragma unroll
            for (int r = 0; r < 4; r++) acc[i][j][r] = 0.f;

    // fragment smem addresses (computed once)
    uint32_t a_base = (uint32_t)__cvta_generic_to_shared(&As[0][0][0]);
    uint32_t b_base = (uint32_t)__cvta_generic_to_shared(&Bs[0][0][0]);
    const uint32_t buf_stride = 128 * GPAD * 4;

    const int a_frag_row = wm + (lane & 15);          // + ma*16
    const int a_frag_kw  = (lane >> 4) << 2;          // + ks*8
    const int b_frag_n   = wn + ((lane >> 4) << 3) + (lane & 7);  // + nb*16
    const int b_frag_kw  = ((lane >> 3) & 1) << 2;    // + ks*8

    const int nk = K / 16;

    // ---- prologue: load stage 0 ----
    {
        float4 ra0 = *(const float4*)(Ag);
        float4 ra1 = *(const float4*)(Ag + (size_t)64 * K);
        float rb[8];
#pragma unroll
        for (int j = 0; j < 8; j++) rb[j] = Bg[(size_t)j * N];

        float4 wa0 = make_float4(to_tf32(ra0.x), to_tf32(ra0.y), to_tf32(ra0.z), to_tf32(ra0.w));
        float4 wa1 = make_float4(to_tf32(ra1.x), to_tf32(ra1.y), to_tf32(ra1.z), to_tf32(ra1.w));
        *(float4*)&As[0][a_row][a_col]      = wa0;
        *(float4*)&As[0][a_row + 64][a_col] = wa1;
        float4 wb0 = make_float4(to_tf32(rb[0]), to_tf32(rb[1]), to_tf32(rb[2]), to_tf32(rb[3]));
        float4 wb1 = make_float4(to_tf32(rb[4]), to_tf32(rb[5]), to_tf32(rb[6]), to_tf32(rb[7]));
        *(float4*)&Bs[0][b_n][b_k]     = wb0;
        *(float4*)&Bs[0][b_n][b_k + 4] = wb1;
    }
    __syncthreads();

    for (int kt = 0; kt < nk; kt++) {
        const int buf = kt & 1;

        // prefetch next stage into registers
        float4 ra0, ra1;
        float rb[8];
        if (kt + 1 < nk) {
            const int k0 = (kt + 1) * 16;
            ra0 = *(const float4*)(Ag + k0);
            ra1 = *(const float4*)(Ag + (size_t)64 * K + k0);
#pragma unroll
            for (int j = 0; j < 8; j++) rb[j] = Bg[(size_t)(k0 + j) * N];
        }

        // compute current stage
        const uint32_t abuf = a_base + buf * buf_stride;
        const uint32_t bbuf = b_base + buf * buf_stride;
#pragma unroll
        for (int ks = 0; ks < 2; ks++) {
            uint32_t af[4][4];
#pragma unroll
            for (int ma = 0; ma < 4; ma++) {
                uint32_t addr = abuf +
                    ((a_frag_row + ma * 16) * GPAD + ks * 8 + a_frag_kw) * 4;
                ldsm4(af[ma][0], af[ma][1], af[ma][2], af[ma][3], addr);
            }
            uint32_t bf[2][4];
#pragma unroll
            for (int nb = 0; nb < 2; nb++) {
                uint32_t addr = bbuf +
                    ((b_frag_n + nb * 16) * GPAD + ks * 8 + b_frag_kw) * 4;
                ldsm4(bf[nb][0], bf[nb][1], bf[nb][2], bf[nb][3], addr);
            }
#pragma unroll
            for (int ma = 0; ma < 4; ma++) {
#pragma unroll
                for (int nb = 0; nb < 2; nb++) {
                    mma_tf32(acc[ma][nb * 2 + 0], af[ma], bf[nb][0], bf[nb][1]);
                    mma_tf32(acc[ma][nb * 2 + 1], af[ma], bf[nb][2], bf[nb][3]);
                }
            }
        }

        // store next stage
        if (kt + 1 < nk) {
            const int nb_ = buf ^ 1;
            float4 wa0 = make_float4(to_tf32(ra0.x), to_tf32(ra0.y), to_tf32(ra0.z), to_tf32(ra0.w));
            float4 wa1 = make_float4(to_tf32(ra1.x), to_tf32(ra1.y), to_tf32(ra1.z), to_tf32(ra1.w));
            *(float4*)&As[nb_][a_row][a_col]      = wa0;
            *(float4*)&As[nb_][a_row + 64][a_col] = wa1;
            float4 wb0 = make_float4(to_tf32(rb[0]), to_tf32(rb[1]), to_tf32(rb[2]), to_tf32(rb[3]));
            float4 wb1 = make_float4(to_tf32(rb[4]), to_tf32(rb[5]), to_tf32(rb[6]), to_tf32(rb[7]));
            *(float4*)&Bs[nb_][b_n][b_k]     = wb0;
            *(float4*)&Bs[nb_][b_n][b_k + 4] = wb1;
        }
        __syncthreads();
    }

    // ---- epilogue: bias + store ----
#pragma unroll
    for (int ma = 0; ma < 4; ma++) {
        const int row0 = bm + wm + ma * 16 + (lane >> 2);
#pragma unroll
        for (int na = 0; na < 4; na++) {
            const int col = bn + wn + na * 8 + (lane & 3) * 2;
            const float b0 = bias[col];
            const float b1 = bias[col + 1];
            float2 v0 = make_float2(acc[ma][na][0] + b0, acc[ma][na][1] + b1);
            float2 v1 = make_float2(acc[ma][na][2] + b0, acc[ma][na][3] + b1);
            *(float2*)(C + (size_t)row0 * N + col)       = v0;
            *(float2*)(C + (size_t)(row0 + 8) * N + col) = v1;
        }
    }
}

// ---------------------------------------------------------------------------
// Flash attention (fp32), GQA + ALiBi + key mask, non-causal.
// Grid: (S/64, NH, B). Block: 256 threads (16x16). q-tile = 64, k-tile = 64.
// ---------------------------------------------------------------------------
#define PS_STRIDE 72
#define FLASH_SMEM ((3 * 64 * 64 + 64 * PS_STRIDE + SS) * 4)

__global__ __launch_bounds__(256)
void flash_attn(const float* __restrict__ qkv,
                const int* __restrict__ attn_mask,
                float* __restrict__ ctx)
{
    extern __shared__ float sm[];
    float* Qt = sm;
    float* Kt = Qt + 64 * 64;
    float* Vs = Kt + 64 * 64;
    float* Ps = Vs + 64 * 64;
    float* mb = Ps + 64 * PS_STRIDE;

    const int t  = threadIdx.x;
    const int tx = t & 15;
    const int ty = t >> 4;
    const int q0 = blockIdx.x * 64;
    const int h  = blockIdx.y;
    const int b  = blockIdx.z;
    const int kv = h >> 2;

    const float slope = exp2f(-(float)(h + 1));
    const float scale = 0.125f;

    for (int k = t; k < SS; k += 256)
        mb[k] = (attn_mask[b * SS + k] == 0) ? -1e9f : 0.f;

    {
        const int qc = t >> 2;
        const int ds = (t & 3) * 16;
        const float* src = qkv + (size_t)(b * SS + q0 + qc) * QKVC + h * DK + ds;
#pragma unroll
        for (int e = 0; e < 4; e++) {
            float4 v = *(const float4*)(src + e * 4);
            int d = ds + e * 4;
            Qt[(d + 0) * 64 + qc] = v.x * scale;
            Qt[(d + 1) * 64 + qc] = v.y * scale;
            Qt[(d + 2) * 64 + qc] = v.z * scale;
            Qt[(d + 3) * 64 + qc] = v.w * scale;
        }
    }

    float m_i[4], l_i[4], o[4][4];
#pragma unroll
    for (int i = 0; i < 4; i++) {
        m_i[i] = -1e30f;
        l_i[i] = 0.f;
#pragma unroll
        for (int j = 0; j < 4; j++) o[i][j] = 0.f;
    }

    for (int kt = 0; kt < SS / 64; kt++) {
        const int k0 = kt * 64;
        {
            const int kc = t >> 2;
            const int ds = (t & 3) * 16;
            const float* srcK = qkv + (size_t)(b * SS + k0 + kc) * QKVC + DM + kv * DK + ds;
            const float* srcV = qkv + (size_t)(b * SS + k0 + kc) * QKVC + DM + NKV * DK + kv * DK + ds;
#pragma unroll
            for (int e = 0; e < 4; e++) {
                int d = ds + e * 4;
                float4 kf = *(const float4*)(srcK + e * 4);
                Kt[(d + 0) * 64 + kc] = kf.x;
                Kt[(d + 1) * 64 + kc] = kf.y;
                Kt[(d + 2) * 64 + kc] = kf.z;
                Kt[(d + 3) * 64 + kc] = kf.w;
                float4 vf = *(const float4*)(srcV + e * 4);
                *(float4*)&Vs[kc * 64 + d] = vf;
            }
        }
        __syncthreads();

        float s[4][4];
#pragma unroll
        for (int i = 0; i < 4; i++)
#pragma unroll
            for (int j = 0; j < 4; j++) s[i][j] = 0.f;

#pragma unroll 8
        for (int kk = 0; kk < 64; kk++) {
            float4 qf = *(const float4*)(Qt + kk * 64 + ty * 4);
            float4 kf = *(const float4*)(Kt + kk * 64 + tx * 4);
            float qa[4] = {qf.x, qf.y, qf.z, qf.w};
            float ka[4] = {kf.x, kf.y, kf.z, kf.w};
#pragma unroll
            for (int i = 0; i < 4; i++)
#pragma unroll
                for (int j = 0; j < 4; j++)
                    s[i][j] += qa[i] * ka[j];
        }

#pragma unroll
        for (int i = 0; i < 4; i++) {
            float qpos = (float)(q0 + ty * 4 + i);
#pragma unroll
            for (int j = 0; j < 4; j++) {
                int kidx = k0 + tx * 4 + j;
                s[i][j] += slope * (qpos - (float)kidx) + mb[kidx];
            }
        }

#pragma unroll
        for (int i = 0; i < 4; i++) {
            float mx = fmaxf(fmaxf(s[i][0], s[i][1]), fmaxf(s[i][2], s[i][3]));
            mx = fmaxf(mx, __shfl_xor_sync(0xffffffffu, mx, 1, 16));
            mx = fmaxf(mx, __shfl_xor_sync(0xffffffffu, mx, 2, 16));
            mx = fmaxf(mx, __shfl_xor_sync(0xffffffffu, mx, 4, 16));
            mx = fmaxf(mx, __shfl_xor_sync(0xffffffffu, mx, 8, 16));
            float mn = fmaxf(m_i[i], mx);
            float al = __expf(m_i[i] - mn);
            m_i[i] = mn;
            float rs = 0.f;
#pragma unroll
            for (int j = 0; j < 4; j++) {
                s[i][j] = __expf(s[i][j] - mn);
                rs += s[i][j];
            }
            rs += __shfl_xor_sync(0xffffffffu, rs, 1, 16);
            rs += __shfl_xor_sync(0xffffffffu, rs, 2, 16);
            rs += __shfl_xor_sync(0xffffffffu, rs, 4, 16);
            rs += __shfl_xor_sync(0xffffffffu, rs, 8, 16);
            l_i[i] = l_i[i] * al + rs;
#pragma unroll
            for (int j = 0; j < 4; j++) o[i][j] *= al;
        }

#pragma unroll
        for (int j = 0; j < 4; j++) {
            float4 col = make_float4(s[0][j], s[1][j], s[2][j], s[3][j]);
            *(float4*)(Ps + (tx * 4 + j) * PS_STRIDE + ty * 4) = col;
        }
        __syncthreads();

#pragma unroll 8
        for (int kk = 0; kk < 64; kk++) {
            float4 pf = *(const float4*)(Ps + kk * PS_STRIDE + ty * 4);
            float4 vf = *(const float4*)(Vs + kk * 64 + tx * 4);
            float pa[4] = {pf.x, pf.y, pf.z, pf.w};
            float va[4] = {vf.x, vf.y, vf.z, vf.w};
#pragma unroll
            for (int i = 0; i < 4; i++)
#pragma unroll
                for (int j = 0; j < 4; j++)
                    o[i][j] += pa[i] * va[j];
        }
        __syncthreads();
    }

#pragma unroll
    for (int i = 0; i < 4; i++) {
        float inv = 1.f / l_i[i];
        float4 wv = make_float4(o[i][0] * inv, o[i][1] * inv,
                                o[i][2] * inv, o[i][3] * inv);
        *(float4*)(ctx + (size_t)(b * SS + q0 + ty * 4 + i) * DM + h * DK + tx * 4) = wv;
    }
}

// ---------------------------------------------------------------------------
// y = LayerNorm(a + (pad ? 0 : r)) * gamma + beta, row length 1024
// ---------------------------------------------------------------------------
__global__ __launch_bounds__(256)
void add_ln_kernel(const float* __restrict__ a,
                   const float* __restrict__ r,
                   const unsigned char* __restrict__ pad,
                   const float* __restrict__ gamma,
                   const float* __restrict__ beta,
                   float* __restrict__ out)
{
    __shared__ float s_sum[8], s_sq[8];
    const int row = blockIdx.x;
    const int t = threadIdx.x;

    float4 va = *(const float4*)(a + (size_t)row * DM + t * 4);
    float4 vr = *(const float4*)(r + (size_t)row * DM + t * 4);
    if (pad && pad[row]) vr = make_float4(0.f, 0.f, 0.f, 0.f);
    float4 v = make_float4(va.x + vr.x, va.y + vr.y, va.z + vr.z, va.w + vr.w);

    float sum = v.x + v.y + v.z + v.w;
    float sq  = v.x * v.x + v.y * v.y + v.z * v.z + v.w * v.w;
#pragma unroll
    for (int off = 16; off > 0; off >>= 1) {
        sum += __shfl_xor_sync(0xffffffffu, sum, off);
        sq  += __shfl_xor_sync(0xffffffffu, sq, off);
    }
    if ((t & 31) == 0) { s_sum[t >> 5] = sum; s_sq[t >> 5] = sq; }
    __syncthreads();
    sum = 0.f; sq = 0.f;
#pragma unroll
    for (int wv = 0; wv < 8; wv++) { sum += s_sum[wv]; sq += s_sq[wv]; }

    const float mean = sum * (1.f / (float)DM);
    const float var  = sq * (1.f / (float)DM) - mean * mean;
    const float rs   = rsqrtf(var + 1e-5f);

    float4 gg = *(const float4*)(gamma + t * 4);
    float4 bb = *(const float4*)(beta + t * 4);
    float4 y = make_float4((v.x - mean) * rs * gg.x + bb.x,
                           (v.y - mean) * rs * gg.y + bb.y,
                           (v.z - mean) * rs * gg.z + bb.z,
                           (v.w - mean) * rs * gg.w + bb.w);
    *(float4*)(out + (size_t)row * DM + t * 4) = y;
}

// ---------------------------------------------------------------------------
// SwiGLU: g[row, c] = silu(h[row, c]) * h[row, 2048 + c], zero where pad
// ---------------------------------------------------------------------------
__global__ __launch_bounds__(256)
void glu_kernel(const float* __restrict__ h,
                const unsigned char* __restrict__ pad,
                float* __restrict__ g)
{
    const int idx = blockIdx.x * 256 + threadIdx.x;
    const int row = idx / (DFF / 2 / 4);
    const int c4  = idx % (DFF / 2 / 4);
    float4 a = *(const float4*)(h + (size_t)row * DFF + c4 * 4);
    float4 b = *(const float4*)(h + (size_t)row * DFF + DFF / 2 + c4 * 4);
    float4 y;
    y.x = (a.x / (1.f + __expf(-a.x))) * b.x;
    y.y = (a.y / (1.f + __expf(-a.y))) * b.y;
    y.z = (a.z / (1.f + __expf(-a.z))) * b.z;
    y.w = (a.w / (1.f + __expf(-a.w))) * b.w;
    if (pad[row]) y = make_float4(0.f, 0.f, 0.f, 0.f);
    *(float4*)(g + (size_t)row * (DFF / 2) + c4 * 4) = y;
}

// ---------------------------------------------------------------------------
// Launch
// ---------------------------------------------------------------------------
extern "C" void kernel_launch(void* const* d_in, const int* in_sizes, int n_in,
                              void* d_out, int out_size)
{
    const float* x          = (const float*)d_in[0];
    const int*   attn_mask  = (const int*)d_in[1];
    const unsigned char* seq_mask = (const unsigned char*)d_in[2];
    const float* Wc  = (const float*)d_in[3];
    const float* bc  = (const float*)d_in[4];
    const float* Wo  = (const float*)d_in[5];
    const float* bo  = (const float*)d_in[6];
    const float* W1  = (const float*)d_in[7];
    const float* b1  = (const float*)d_in[8];
    const float* W2  = (const float*)d_in[9];
    const float* b2  = (const float*)d_in[10];
    const float* g1  = (const float*)d_in[11];
    const float* be1 = (const float*)d_in[12];
    const float* g2  = (const float*)d_in[13];
    const float* be2 = (const float*)d_in[14];
    float* out = (float*)d_out;

    float *qkv, *ctx, *attnout, *x1, *h, *glu, *ffn;
    cudaGetSymbolAddress((void**)&qkv,     g_qkv);
    cudaGetSymbolAddress((void**)&ctx,     g_ctx);
    cudaGetSymbolAddress((void**)&attnout, g_attnout);
    cudaGetSymbolAddress((void**)&x1,      g_x1);
    cudaGetSymbolAddress((void**)&h,       g_h);
    cudaGetSymbolAddress((void**)&glu,     g_glu);
    cudaGetSymbolAddress((void**)&ffn,     g_ffn);

    cudaFuncSetAttribute(flash_attn, cudaFuncAttributeMaxDynamicSharedMemorySize,
                         FLASH_SMEM);

    // 1) qkv = x @ Wc + bc
    tf32_gemm_bias<<<dim3(QKVC / 128, ROWS / 128), 256>>>(ROWS, QKVC, DM, x, Wc, bc, qkv);

    // 2) attention -> ctx
    flash_attn<<<dim3(SS / 64, NH, BB), 256, FLASH_SMEM>>>(qkv, attn_mask, ctx);

    // 3) attn_out = ctx @ Wo + bo
    tf32_gemm_bias<<<dim3(DM / 128, ROWS / 128), 256>>>(ROWS, DM, DM, ctx, Wo, bo, attnout);

    // 4) x1 = LN(x + attn_out)
    add_ln_kernel<<<ROWS, 256>>>(x, attnout, nullptr, g1, be1, x1);

    // 5) h = x1 @ W1 + b1
    tf32_gemm_bias<<<dim3(DFF / 128, ROWS / 128), 256>>>(ROWS, DFF, DM, x1, W1, b1, h);

    // 6) glu = silu(h1)*h2 (pad-zeroed)
    glu_kernel<<<(ROWS * (DFF / 2) / 4) / 256, 256>>>(h, seq_mask, glu);

    // 7) ffn = glu @ W2 + b2
    tf32_gemm_bias<<<dim3(DM / 128, ROWS / 128), 256>>>(ROWS, DM, DFF / 2, glu, W2, b2, ffn);

    // 8) out = LN(x1 + (pad ? 0 : ffn))
    add_ln_kernel<<<ROWS, 256>>>(x1, ffn, seq_mask, g2, be2, out);
}

// round 6
// speedup vs baseline: 2.3373x; 1.4686x over previous
#include <cuda_runtime.h>
#include <cuda_bf16.h>
#include <cstdint>

// ---------------------------------------------------------------------------
// Problem constants (fixed by setup_inputs)
// ---------------------------------------------------------------------------
#define BB      2
#define SS      2048
#define DM      1024
#define NH      16
#define NKV     4
#define DK      64
#define DFF     4096
#define QKVC    1536          // DM + 2*NKV*DK
#define ROWS    (BB*SS)       // 4096

// ---------------------------------------------------------------------------
// Scratch (static device allocations; allowed by harness rules)
// ---------------------------------------------------------------------------
__device__ float g_qkv    [ROWS * QKVC];
__device__ float g_ctx    [ROWS * DM];
__device__ float g_attnout[ROWS * DM];
__device__ float g_x1     [ROWS * DM];
__device__ float g_h      [ROWS * DFF];
__device__ float g_glu    [ROWS * (DFF/2)];
__device__ float g_ffn    [ROWS * DM];

// ---------------------------------------------------------------------------
// tf32 helpers (shared by GEMM and attention)
// ---------------------------------------------------------------------------
__device__ __forceinline__ float to_tf32(float x) {
    float r;
    asm("cvt.rna.tf32.f32 %0, %1;" : "=f"(r) : "f"(x));
    return r;
}

__device__ __forceinline__ void ldsm4(uint32_t& r0, uint32_t& r1,
                                      uint32_t& r2, uint32_t& r3,
                                      uint32_t addr) {
    asm volatile("ldmatrix.sync.aligned.m8n8.x4.shared.b16 {%0,%1,%2,%3}, [%4];"
                 : "=r"(r0), "=r"(r1), "=r"(r2), "=r"(r3) : "r"(addr));
}

__device__ __forceinline__ void mma_tf32(float* c, const uint32_t* a,
                                         uint32_t b0, uint32_t b1) {
    asm volatile(
        "mma.sync.aligned.m16n8k8.row.col.f32.tf32.tf32.f32 "
        "{%0,%1,%2,%3}, {%4,%5,%6,%7}, {%8,%9}, {%0,%1,%2,%3};"
        : "+f"(c[0]), "+f"(c[1]), "+f"(c[2]), "+f"(c[3])
        : "r"(a[0]), "r"(a[1]), "r"(a[2]), "r"(a[3]), "r"(b0), "r"(b1));
}

// ---------------------------------------------------------------------------
// tf32 tensor-core GEMM: C[M,N] = A[M,K] @ B[K,N] + bias[N]
// Block tile 128x128, BK=16, 256 threads (8 warps, 2x4), warp tile 64x32.
// ---------------------------------------------------------------------------
#define GPAD 20

__global__ __launch_bounds__(256)
void tf32_gemm_bias(int M, int N, int K,
                    const float* __restrict__ A,
                    const float* __restrict__ B,
                    const float* __restrict__ bias,
                    float* __restrict__ C)
{
    __shared__ float As[2][128][GPAD];
    __shared__ float Bs[2][128][GPAD];

    const int t    = threadIdx.x;
    const int lane = t & 31;
    const int w    = t >> 5;
    const int wm   = (w >> 2) * 64;
    const int wn   = (w & 3) * 32;
    const int bm   = blockIdx.y * 128;
    const int bn   = blockIdx.x * 128;

    const int a_row = t >> 2;
    const int a_col = (t & 3) * 4;
    const float* Ag = A + (size_t)(bm + a_row) * K + a_col;

    const int b_n = t & 127;
    const int b_k = (t >> 7) * 8;
    const float* Bg = B + (size_t)b_k * N + bn + b_n;

    float acc[4][4][4];
#pragma unroll
    for (int i = 0; i < 4; i++)
#pragma unroll
        for (int j = 0; j < 4; j++)
#pragma unroll
            for (int r = 0; r < 4; r++) acc[i][j][r] = 0.f;

    uint32_t a_base = (uint32_t)__cvta_generic_to_shared(&As[0][0][0]);
    uint32_t b_base = (uint32_t)__cvta_generic_to_shared(&Bs[0][0][0]);
    const uint32_t buf_stride = 128 * GPAD * 4;

    const int a_frag_row = wm + (lane & 15);
    const int a_frag_kw  = (lane >> 4) << 2;
    const int b_frag_n   = wn + ((lane >> 4) << 3) + (lane & 7);
    const int b_frag_kw  = ((lane >> 3) & 1) << 2;

    const int nk = K / 16;

    {
        float4 ra0 = *(const float4*)(Ag);
        float4 ra1 = *(const float4*)(Ag + (size_t)64 * K);
        float rb[8];
#pragma unroll
        for (int j = 0; j < 8; j++) rb[j] = Bg[(size_t)j * N];

        float4 wa0 = make_float4(to_tf32(ra0.x), to_tf32(ra0.y), to_tf32(ra0.z), to_tf32(ra0.w));
        float4 wa1 = make_float4(to_tf32(ra1.x), to_tf32(ra1.y), to_tf32(ra1.z), to_tf32(ra1.w));
        *(float4*)&As[0][a_row][a_col]      = wa0;
        *(float4*)&As[0][a_row + 64][a_col] = wa1;
        float4 wb0 = make_float4(to_tf32(rb[0]), to_tf32(rb[1]), to_tf32(rb[2]), to_tf32(rb[3]));
        float4 wb1 = make_float4(to_tf32(rb[4]), to_tf32(rb[5]), to_tf32(rb[6]), to_tf32(rb[7]));
        *(float4*)&Bs[0][b_n][b_k]     = wb0;
        *(float4*)&Bs[0][b_n][b_k + 4] = wb1;
    }
    __syncthreads();

    for (int kt = 0; kt < nk; kt++) {
        const int buf = kt & 1;

        float4 ra0, ra1;
        float rb[8];
        if (kt + 1 < nk) {
            const int k0 = (kt + 1) * 16;
            ra0 = *(const float4*)(Ag + k0);
            ra1 = *(const float4*)(Ag + (size_t)64 * K + k0);
#pragma unroll
            for (int j = 0; j < 8; j++) rb[j] = Bg[(size_t)(k0 + j) * N];
        }

        const uint32_t abuf = a_base + buf * buf_stride;
        const uint32_t bbuf = b_base + buf * buf_stride;
#pragma unroll
        for (int ks = 0; ks < 2; ks++) {
            uint32_t af[4][4];
#pragma unroll
            for (int ma = 0; ma < 4; ma++) {
                uint32_t addr = abuf +
                    ((a_frag_row + ma * 16) * GPAD + ks * 8 + a_frag_kw) * 4;
                ldsm4(af[ma][0], af[ma][1], af[ma][2], af[ma][3], addr);
            }
            uint32_t bf[2][4];
#pragma unroll
            for (int nb = 0; nb < 2; nb++) {
                uint32_t addr = bbuf +
                    ((b_frag_n + nb * 16) * GPAD + ks * 8 + b_frag_kw) * 4;
                ldsm4(bf[nb][0], bf[nb][1], bf[nb][2], bf[nb][3], addr);
            }
#pragma unroll
            for (int ma = 0; ma < 4; ma++) {
#pragma unroll
                for (int nb = 0; nb < 2; nb++) {
                    mma_tf32(acc[ma][nb * 2 + 0], af[ma], bf[nb][0], bf[nb][1]);
                    mma_tf32(acc[ma][nb * 2 + 1], af[ma], bf[nb][2], bf[nb][3]);
                }
            }
        }

        if (kt + 1 < nk) {
            const int nb_ = buf ^ 1;
            float4 wa0 = make_float4(to_tf32(ra0.x), to_tf32(ra0.y), to_tf32(ra0.z), to_tf32(ra0.w));
            float4 wa1 = make_float4(to_tf32(ra1.x), to_tf32(ra1.y), to_tf32(ra1.z), to_tf32(ra1.w));
            *(float4*)&As[nb_][a_row][a_col]      = wa0;
            *(float4*)&As[nb_][a_row + 64][a_col] = wa1;
            float4 wb0 = make_float4(to_tf32(rb[0]), to_tf32(rb[1]), to_tf32(rb[2]), to_tf32(rb[3]));
            float4 wb1 = make_float4(to_tf32(rb[4]), to_tf32(rb[5]), to_tf32(rb[6]), to_tf32(rb[7]));
            *(float4*)&Bs[nb_][b_n][b_k]     = wb0;
            *(float4*)&Bs[nb_][b_n][b_k + 4] = wb1;
        }
        __syncthreads();
    }

#pragma unroll
    for (int ma = 0; ma < 4; ma++) {
        const int row0 = bm + wm + ma * 16 + (lane >> 2);
#pragma unroll
        for (int na = 0; na < 4; na++) {
            const int col = bn + wn + na * 8 + (lane & 3) * 2;
            const float b0 = bias[col];
            const float b1 = bias[col + 1];
            float2 v0 = make_float2(acc[ma][na][0] + b0, acc[ma][na][1] + b1);
            float2 v1 = make_float2(acc[ma][na][2] + b0, acc[ma][na][3] + b1);
            *(float2*)(C + (size_t)row0 * N + col)       = v0;
            *(float2*)(C + (size_t)(row0 + 8) * N + col) = v1;
        }
    }
}

// ---------------------------------------------------------------------------
// Flash attention on tensor cores (tf32 mma), GQA + ALiBi + key mask.
// Grid: (S/64, NH, B). Block: 128 threads (4 warps).
// q-tile 64 (16 rows/warp), k-tile 64, D_K 64.
//   Qs[64][68] row-major (q,d)  -> mma A fragments (hoisted to regs)
//   Ks[64][68] row-major (key,d)-> mma B fragments (scores)
//   Vt[64][68] row-major (d,key)-> mma B fragments (PV)
//   Ps[64][68] row-major (q,key)-> P round-trip for A fragments
//   cb[2048]  combined column bias: maskbias[k] - slope*k
// ---------------------------------------------------------------------------
#define FPAD 68
#define FLASH_SMEM ((4 * 64 * FPAD + SS) * 4)

__global__ __launch_bounds__(128)
void flash_attn_mma(const float* __restrict__ qkv,
                    const int* __restrict__ attn_mask,
                    float* __restrict__ ctx)
{
    extern __shared__ float sm[];
    float* Qs = sm;
    float* Ks = Qs + 64 * FPAD;
    float* Vt = Ks + 64 * FPAD;
    float* Ps = Vt + 64 * FPAD;
    float* cb = Ps + 64 * FPAD;

    const int t    = threadIdx.x;
    const int lane = t & 31;
    const int w    = t >> 5;
    const int q0   = blockIdx.x * 64;
    const int h    = blockIdx.y;
    const int b    = blockIdx.z;
    const int kv   = h >> 2;

    const float slope = exp2f(-(float)(h + 1));   // ALIBI_ALPHA = 1
    const float scale = 0.125f;                    // 1/sqrt(64)

    // combined column bias: mask + alibi column part
    for (int k = t; k < SS; k += 128) {
        float mbv = (attn_mask[b * SS + k] == 0) ? -1e9f : 0.f;
        cb[k] = mbv - slope * (float)k;
    }

    // load Q tile: row-major, scaled, tf32
    {
        const int qr = t >> 1;
        const int dc = (t & 1) * 32;
        const float* src = qkv + (size_t)(b * SS + q0 + qr) * QKVC + h * DK + dc;
        float* dst = Qs + qr * FPAD + dc;
#pragma unroll
        for (int e = 0; e < 8; e++) {
            float4 v = *(const float4*)(src + e * 4);
            dst[e * 4 + 0] = to_tf32(v.x * scale);
            dst[e * 4 + 1] = to_tf32(v.y * scale);
            dst[e * 4 + 2] = to_tf32(v.z * scale);
            dst[e * 4 + 3] = to_tf32(v.w * scale);
        }
    }
    __syncthreads();

    // fragment addressing (identical pattern to the validated GEMM)
    const uint32_t qs_base = (uint32_t)__cvta_generic_to_shared(Qs);
    const uint32_t ks_base = (uint32_t)__cvta_generic_to_shared(Ks);
    const uint32_t vt_base = (uint32_t)__cvta_generic_to_shared(Vt);
    const uint32_t ps_base = (uint32_t)__cvta_generic_to_shared(Ps);

    const int a_frag_row = w * 16 + (lane & 15);
    const int a_frag_kw  = (lane >> 4) << 2;
    const int b_frag_n   = ((lane >> 4) << 3) + (lane & 7);
    const int b_frag_kw  = ((lane >> 3) & 1) << 2;

    // hoist Q fragments (A stays fixed for the whole k loop)
    uint32_t qf[8][4];
#pragma unroll
    for (int ks = 0; ks < 8; ks++) {
        uint32_t addr = qs_base + (a_frag_row * FPAD + ks * 8 + a_frag_kw) * 4;
        ldsm4(qf[ks][0], qf[ks][1], qf[ks][2], qf[ks][3], addr);
    }

    // state
    float o[8][4];
#pragma unroll
    for (int nt = 0; nt < 8; nt++)
#pragma unroll
        for (int r = 0; r < 4; r++) o[nt][r] = 0.f;
    float m0 = -1e30f, m1 = -1e30f, l0 = 0.f, l1 = 0.f;

    const float rowq0 = (float)(q0 + w * 16 + (lane >> 2));
    const float rowt0_base = slope * rowq0;
    const float rowt1_base = rowt0_base + slope * 8.f;

    for (int kt = 0; kt < SS / 64; kt++) {
        const int k0 = kt * 64;

        // load K (natural) and V (transposed), tf32
        {
            const int kr = t >> 1;
            const int dc = (t & 1) * 32;
            const float* srcK = qkv + (size_t)(b * SS + k0 + kr) * QKVC + DM + kv * DK + dc;
            const float* srcV = qkv + (size_t)(b * SS + k0 + kr) * QKVC + DM + NKV * DK + kv * DK + dc;
            float* dstK = Ks + kr * FPAD + dc;
#pragma unroll
            for (int e = 0; e < 8; e++) {
                float4 kf = *(const float4*)(srcK + e * 4);
                dstK[e * 4 + 0] = to_tf32(kf.x);
                dstK[e * 4 + 1] = to_tf32(kf.y);
                dstK[e * 4 + 2] = to_tf32(kf.z);
                dstK[e * 4 + 3] = to_tf32(kf.w);
                float4 vf = *(const float4*)(srcV + e * 4);
                const int d = dc + e * 4;
                Vt[(d + 0) * FPAD + kr] = to_tf32(vf.x);
                Vt[(d + 1) * FPAD + kr] = to_tf32(vf.y);
                Vt[(d + 2) * FPAD + kr] = to_tf32(vf.z);
                Vt[(d + 3) * FPAD + kr] = to_tf32(vf.w);
            }
        }
        __syncthreads();

        // ---- scores: S = Q @ K^T  (m16 x n64 x k64 per warp) ----
        float s[8][4];
#pragma unroll
        for (int nt = 0; nt < 8; nt++)
#pragma unroll
            for (int r = 0; r < 4; r++) s[nt][r] = 0.f;

#pragma unroll
        for (int ks = 0; ks < 8; ks++) {
            uint32_t bf[4][4];
#pragma unroll
            for (int nb = 0; nb < 4; nb++) {
                uint32_t addr = ks_base +
                    ((b_frag_n + nb * 16) * FPAD + ks * 8 + b_frag_kw) * 4;
                ldsm4(bf[nb][0], bf[nb][1], bf[nb][2], bf[nb][3], addr);
            }
#pragma unroll
            for (int nb = 0; nb < 4; nb++) {
                mma_tf32(s[nb * 2 + 0], qf[ks], bf[nb][0], bf[nb][1]);
                mma_tf32(s[nb * 2 + 1], qf[ks], bf[nb][2], bf[nb][3]);
            }
        }

        // ---- ALiBi + mask ----
#pragma unroll
        for (int nt = 0; nt < 8; nt++) {
            const int col = k0 + nt * 8 + (lane & 3) * 2;
            float2 c2 = *(const float2*)(cb + col);
            s[nt][0] += rowt0_base + c2.x;
            s[nt][1] += rowt0_base + c2.y;
            s[nt][2] += rowt1_base + c2.x;
            s[nt][3] += rowt1_base + c2.y;
        }

        // ---- online softmax (rows lane>>2 and lane>>2 + 8) ----
        {
            float mx0 = -1e30f, mx1 = -1e30f;
#pragma unroll
            for (int nt = 0; nt < 8; nt++) {
                mx0 = fmaxf(mx0, fmaxf(s[nt][0], s[nt][1]));
                mx1 = fmaxf(mx1, fmaxf(s[nt][2], s[nt][3]));
            }
            mx0 = fmaxf(mx0, __shfl_xor_sync(0xffffffffu, mx0, 1));
            mx0 = fmaxf(mx0, __shfl_xor_sync(0xffffffffu, mx0, 2));
            mx1 = fmaxf(mx1, __shfl_xor_sync(0xffffffffu, mx1, 1));
            mx1 = fmaxf(mx1, __shfl_xor_sync(0xffffffffu, mx1, 2));

            const float mn0 = fmaxf(m0, mx0);
            const float mn1 = fmaxf(m1, mx1);
            const float al0 = __expf(m0 - mn0);
            const float al1 = __expf(m1 - mn1);
            m0 = mn0; m1 = mn1;

            float rs0 = 0.f, rs1 = 0.f;
#pragma unroll
            for (int nt = 0; nt < 8; nt++) {
                s[nt][0] = __expf(s[nt][0] - mn0);
                s[nt][1] = __expf(s[nt][1] - mn0);
                s[nt][2] = __expf(s[nt][2] - mn1);
                s[nt][3] = __expf(s[nt][3] - mn1);
                rs0 += s[nt][0] + s[nt][1];
                rs1 += s[nt][2] + s[nt][3];
            }
            rs0 += __shfl_xor_sync(0xffffffffu, rs0, 1);
            rs0 += __shfl_xor_sync(0xffffffffu, rs0, 2);
            rs1 += __shfl_xor_sync(0xffffffffu, rs1, 1);
            rs1 += __shfl_xor_sync(0xffffffffu, rs1, 2);
            l0 = l0 * al0 + rs0;
            l1 = l1 * al1 + rs1;

#pragma unroll
            for (int nt = 0; nt < 8; nt++) {
                o[nt][0] *= al0; o[nt][1] *= al0;
                o[nt][2] *= al1; o[nt][3] *= al1;
            }
        }

        // ---- P round-trip through per-warp-private smem (tf32) ----
        {
            const int pr0 = w * 16 + (lane >> 2);
            const int pc  = (lane & 3) * 2;
#pragma unroll
            for (int nt = 0; nt < 8; nt++) {
                *(float2*)(Ps + pr0 * FPAD + nt * 8 + pc) =
                    make_float2(to_tf32(s[nt][0]), to_tf32(s[nt][1]));
                *(float2*)(Ps + (pr0 + 8) * FPAD + nt * 8 + pc) =
                    make_float2(to_tf32(s[nt][2]), to_tf32(s[nt][3]));
            }
        }
        __syncwarp();

        // ---- O += P @ V  (m16 x n64(d) x k64(key) per warp) ----
#pragma unroll
        for (int ks = 0; ks < 8; ks++) {
            uint32_t pf[4];
            {
                uint32_t addr = ps_base + (a_frag_row * FPAD + ks * 8 + a_frag_kw) * 4;
                ldsm4(pf[0], pf[1], pf[2], pf[3], addr);
            }
            uint32_t vf[4][4];
#pragma unroll
            for (int nb = 0; nb < 4; nb++) {
                uint32_t addr = vt_base +
                    ((b_frag_n + nb * 16) * FPAD + ks * 8 + b_frag_kw) * 4;
                ldsm4(vf[nb][0], vf[nb][1], vf[nb][2], vf[nb][3], addr);
            }
#pragma unroll
            for (int nb = 0; nb < 4; nb++) {
                mma_tf32(o[nb * 2 + 0], pf, vf[nb][0], vf[nb][1]);
                mma_tf32(o[nb * 2 + 1], pf, vf[nb][2], vf[nb][3]);
            }
        }
        __syncthreads();   // protect Ks/Vt before next tile load
    }

    // ---- normalize + write ctx [B,S,H*DK] ----
    {
        const float inv0 = 1.f / l0;
        const float inv1 = 1.f / l1;
        const int gr0 = b * SS + q0 + w * 16 + (lane >> 2);
#pragma unroll
        for (int nt = 0; nt < 8; nt++) {
            const int col = h * DK + nt * 8 + (lane & 3) * 2;
            *(float2*)(ctx + (size_t)gr0 * DM + col) =
                make_float2(o[nt][0] * inv0, o[nt][1] * inv0);
            *(float2*)(ctx + (size_t)(gr0 + 8) * DM + col) =
                make_float2(o[nt][2] * inv1, o[nt][3] * inv1);
        }
    }
}

// ---------------------------------------------------------------------------
// y = LayerNorm(a + (pad ? 0 : r)) * gamma + beta, row length 1024
// ---------------------------------------------------------------------------
__global__ __launch_bounds__(256)
void add_ln_kernel(const float* __restrict__ a,
                   const float* __restrict__ r,
                   const unsigned char* __restrict__ pad,
                   const float* __restrict__ gamma,
                   const float* __restrict__ beta,
                   float* __restrict__ out)
{
    __shared__ float s_sum[8], s_sq[8];
    const int row = blockIdx.x;
    const int t = threadIdx.x;

    float4 va = *(const float4*)(a + (size_t)row * DM + t * 4);
    float4 vr = *(const float4*)(r + (size_t)row * DM + t * 4);
    if (pad && pad[row]) vr = make_float4(0.f, 0.f, 0.f, 0.f);
    float4 v = make_float4(va.x + vr.x, va.y + vr.y, va.z + vr.z, va.w + vr.w);

    float sum = v.x + v.y + v.z + v.w;
    float sq  = v.x * v.x + v.y * v.y + v.z * v.z + v.w * v.w;
#pragma unroll
    for (int off = 16; off > 0; off >>= 1) {
        sum += __shfl_xor_sync(0xffffffffu, sum, off);
        sq  += __shfl_xor_sync(0xffffffffu, sq, off);
    }
    if ((t & 31) == 0) { s_sum[t >> 5] = sum; s_sq[t >> 5] = sq; }
    __syncthreads();
    sum = 0.f; sq = 0.f;
#pragma unroll
    for (int wv = 0; wv < 8; wv++) { sum += s_sum[wv]; sq += s_sq[wv]; }

    const float mean = sum * (1.f / (float)DM);
    const float var  = sq * (1.f / (float)DM) - mean * mean;
    const float rs   = rsqrtf(var + 1e-5f);

    float4 gg = *(const float4*)(gamma + t * 4);
    float4 bb = *(const float4*)(beta + t * 4);
    float4 y = make_float4((v.x - mean) * rs * gg.x + bb.x,
                           (v.y - mean) * rs * gg.y + bb.y,
                           (v.z - mean) * rs * gg.z + bb.z,
                           (v.w - mean) * rs * gg.w + bb.w);
    *(float4*)(out + (size_t)row * DM + t * 4) = y;
}

// ---------------------------------------------------------------------------
// SwiGLU: g[row, c] = silu(h[row, c]) * h[row, 2048 + c], zero where pad
// ---------------------------------------------------------------------------
__global__ __launch_bounds__(256)
void glu_kernel(const float* __restrict__ h,
                const unsigned char* __restrict__ pad,
                float* __restrict__ g)
{
    const int idx = blockIdx.x * 256 + threadIdx.x;
    const int row = idx / (DFF / 2 / 4);
    const int c4  = idx % (DFF / 2 / 4);
    float4 a = *(const float4*)(h + (size_t)row * DFF + c4 * 4);
    float4 b = *(const float4*)(h + (size_t)row * DFF + DFF / 2 + c4 * 4);
    float4 y;
    y.x = (a.x / (1.f + __expf(-a.x))) * b.x;
    y.y = (a.y / (1.f + __expf(-a.y))) * b.y;
    y.z = (a.z / (1.f + __expf(-a.z))) * b.z;
    y.w = (a.w / (1.f + __expf(-a.w))) * b.w;
    if (pad[row]) y = make_float4(0.f, 0.f, 0.f, 0.f);
    *(float4*)(g + (size_t)row * (DFF / 2) + c4 * 4) = y;
}

// ---------------------------------------------------------------------------
// Launch
// ---------------------------------------------------------------------------
extern "C" void kernel_launch(void* const* d_in, const int* in_sizes, int n_in,
                              void* d_out, int out_size)
{
    const float* x          = (const float*)d_in[0];
    const int*   attn_mask  = (const int*)d_in[1];
    const unsigned char* seq_mask = (const unsigned char*)d_in[2];
    const float* Wc  = (const float*)d_in[3];
    const float* bc  = (const float*)d_in[4];
    const float* Wo  = (const float*)d_in[5];
    const float* bo  = (const float*)d_in[6];
    const float* W1  = (const float*)d_in[7];
    const float* b1  = (const float*)d_in[8];
    const float* W2  = (const float*)d_in[9];
    const float* b2  = (const float*)d_in[10];
    const float* g1  = (const float*)d_in[11];
    const float* be1 = (const float*)d_in[12];
    const float* g2  = (const float*)d_in[13];
    const float* be2 = (const float*)d_in[14];
    float* out = (float*)d_out;

    float *qkv, *ctx, *attnout, *x1, *h, *glu, *ffn;
    cudaGetSymbolAddress((void**)&qkv,     g_qkv);
    cudaGetSymbolAddress((void**)&ctx,     g_ctx);
    cudaGetSymbolAddress((void**)&attnout, g_attnout);
    cudaGetSymbolAddress((void**)&x1,      g_x1);
    cudaGetSymbolAddress((void**)&h,       g_h);
    cudaGetSymbolAddress((void**)&glu,     g_glu);
    cudaGetSymbolAddress((void**)&ffn,     g_ffn);

    cudaFuncSetAttribute(flash_attn_mma, cudaFuncAttributeMaxDynamicSharedMemorySize,
                         FLASH_SMEM);

    // 1) qkv = x @ Wc + bc
    tf32_gemm_bias<<<dim3(QKVC / 128, ROWS / 128), 256>>>(ROWS, QKVC, DM, x, Wc, bc, qkv);

    // 2) attention -> ctx (tensor cores)
    flash_attn_mma<<<dim3(SS / 64, NH, BB), 128, FLASH_SMEM>>>(qkv, attn_mask, ctx);

    // 3) attn_out = ctx @ Wo + bo
    tf32_gemm_bias<<<dim3(DM / 128, ROWS / 128), 256>>>(ROWS, DM, DM, ctx, Wo, bo, attnout);

    // 4) x1 = LN(x + attn_out)
    add_ln_kernel<<<ROWS, 256>>>(x, attnout, nullptr, g1, be1, x1);

    // 5) h = x1 @ W1 + b1
    tf32_gemm_bias<<<dim3(DFF / 128, ROWS / 128), 256>>>(ROWS, DFF, DM, x1, W1, b1, h);

    // 6) glu = silu(h1)*h2 (pad-zeroed)
    glu_kernel<<<(ROWS * (DFF / 2) / 4) / 256, 256>>>(h, seq_mask, glu);

    // 7) ffn = glu @ W2 + b2
    tf32_gemm_bias<<<dim3(DM / 128, ROWS / 128), 256>>>(ROWS, DM, DFF / 2, glu, W2, b2, ffn);

    // 8) out = LN(x1 + (pad ? 0 : ffn))
    add_ln_kernel<<<ROWS, 256>>>(x1, ffn, seq_mask, g2, be2, out);
}

// round 7
// speedup vs baseline: 2.3745x; 1.0159x over previous
#include <cuda_runtime.h>
#include <cuda_bf16.h>
#include <cstdint>

// ---------------------------------------------------------------------------
// Problem constants (fixed by setup_inputs)
// ---------------------------------------------------------------------------
#define BB      2
#define SS      2048
#define DM      1024
#define NH      16
#define NKV     4
#define DK      64
#define DFF     4096
#define QKVC    1536          // DM + 2*NKV*DK
#define ROWS    (BB*SS)       // 4096

// ---------------------------------------------------------------------------
// Scratch (static device allocations; allowed by harness rules)
// ---------------------------------------------------------------------------
__device__ float g_qkv    [ROWS * QKVC];
__device__ float g_ctx    [ROWS * DM];
__device__ float g_attnout[ROWS * DM];
__device__ float g_x1     [ROWS * DM];
__device__ float g_h      [ROWS * DFF];
__device__ float g_glu    [ROWS * (DFF/2)];
__device__ float g_ffn    [ROWS * DM];
// tf32-rounded / transposed operands
__device__ float g_xr     [ROWS * DM];          // rounded x
__device__ float g_wct    [QKVC * DM];          // Wc^T  [n][k]
__device__ float g_wot    [DM * DM];            // Wo^T
__device__ float g_w1t    [DFF * DM];           // W1^T
__device__ float g_w2t    [DM * (DFF/2)];       // W2^T

// ---------------------------------------------------------------------------
// tf32 helpers
// ---------------------------------------------------------------------------
__device__ __forceinline__ float to_tf32(float x) {
    float r;
    asm("cvt.rna.tf32.f32 %0, %1;" : "=f"(r) : "f"(x));
    return r;
}

__device__ __forceinline__ void ldsm4(uint32_t& r0, uint32_t& r1,
                                      uint32_t& r2, uint32_t& r3,
                                      uint32_t addr) {
    asm volatile("ldmatrix.sync.aligned.m8n8.x4.shared.b16 {%0,%1,%2,%3}, [%4];"
                 : "=r"(r0), "=r"(r1), "=r"(r2), "=r"(r3) : "r"(addr));
}

__device__ __forceinline__ void mma_tf32(float* c, const uint32_t* a,
                                         uint32_t b0, uint32_t b1) {
    asm volatile(
        "mma.sync.aligned.m16n8k8.row.col.f32.tf32.tf32.f32 "
        "{%0,%1,%2,%3}, {%4,%5,%6,%7}, {%8,%9}, {%0,%1,%2,%3};"
        : "+f"(c[0]), "+f"(c[1]), "+f"(c[2]), "+f"(c[3])
        : "r"(a[0]), "r"(a[1]), "r"(a[2]), "r"(a[3]), "r"(b0), "r"(b1));
}

__device__ __forceinline__ void cp_async16(uint32_t smem_addr, const void* gptr) {
    asm volatile("cp.async.cg.shared.global [%0], [%1], 16;"
                 :: "r"(smem_addr), "l"(gptr));
}
#define CP_COMMIT()  asm volatile("cp.async.commit_group;")
#define CP_WAIT(n)   asm volatile("cp.async.wait_group %0;" :: "n"(n))

// ---------------------------------------------------------------------------
// Pre-pass: tf32-round copy (grid-stride float4)
// ---------------------------------------------------------------------------
__global__ __launch_bounds__(256)
void round_copy(const float* __restrict__ in, float* __restrict__ out, int n4)
{
    int i = blockIdx.x * 256 + threadIdx.x;
    if (i >= n4) return;
    float4 v = ((const float4*)in)[i];
    v.x = to_tf32(v.x); v.y = to_tf32(v.y);
    v.z = to_tf32(v.z); v.w = to_tf32(v.w);
    ((float4*)out)[i] = v;
}

// ---------------------------------------------------------------------------
// Pre-pass: Wt[n][k] = tf32(W[k][n])   (W: [K][N] row-major)
// ---------------------------------------------------------------------------
__global__ __launch_bounds__(256)
void transpose_round(const float* __restrict__ W, float* __restrict__ Wt,
                     int K, int N)
{
    __shared__ float tile[32][33];
    const int n0 = blockIdx.x * 32;
    const int k0 = blockIdx.y * 32;
    const int tx = threadIdx.x;
    const int ty = threadIdx.y;
#pragma unroll
    for (int i = 0; i < 32; i += 8)
        tile[ty + i][tx] = W[(size_t)(k0 + ty + i) * N + n0 + tx];
    __syncthreads();
#pragma unroll
    for (int i = 0; i < 32; i += 8)
        Wt[(size_t)(n0 + ty + i) * K + k0 + tx] = to_tf32(tile[tx][ty + i]);
}

// ---------------------------------------------------------------------------
// tf32 tensor-core GEMM with 3-stage cp.async pipeline.
// C[M,N] = A[M,K] @ Bt[N,K]^T + bias[N]
// A and Bt must already be tf32-rounded. Block tile 128x128, BK=16,
// 256 threads (8 warps 2x4), warp tile 64x32.
// ---------------------------------------------------------------------------
#define GPAD   20
#define STAGES 3
#define GEMM_SMEM (STAGES * 2 * 128 * GPAD * 4)

__global__ __launch_bounds__(256, 2)
void tf32_gemm_cp(int M, int N, int K,
                  const float* __restrict__ A,
                  const float* __restrict__ Bt,
                  const float* __restrict__ bias,
                  float* __restrict__ C)
{
    extern __shared__ float smem[];
    float* As = smem;                               // [STAGES][128][GPAD]
    float* Bs = smem + STAGES * 128 * GPAD;         // [STAGES][128][GPAD]

    const int t    = threadIdx.x;
    const int lane = t & 31;
    const int w    = t >> 5;
    const int wm   = (w >> 2) * 64;
    const int wn   = (w & 3) * 32;
    const int bm   = blockIdx.y * 128;
    const int bn   = blockIdx.x * 128;

    // loader mapping: each thread owns one row (m or n) and half its k-range
    const int l_row = t >> 1;           // 0..127
    const int l_k   = (t & 1) * 8;      // 0 or 8
    const float* Ag = A  + (size_t)(bm + l_row) * K + l_k;
    const float* Bg = Bt + (size_t)(bn + l_row) * K + l_k;

    const uint32_t sa = (uint32_t)__cvta_generic_to_shared(As);
    const uint32_t sb = (uint32_t)__cvta_generic_to_shared(Bs);
    const uint32_t buf_stride = 128 * GPAD * 4;
    const uint32_t l_off = (l_row * GPAD + l_k) * 4;

    const int nk = K / 16;

    // fragment addressing
    const int a_frag_row = wm + (lane & 15);
    const int a_frag_kw  = (lane >> 4) << 2;
    const int b_frag_n   = wn + ((lane >> 4) << 3) + (lane & 7);
    const int b_frag_kw  = ((lane >> 3) & 1) << 2;

    float acc[4][4][4];
#pragma unroll
    for (int i = 0; i < 4; i++)
#pragma unroll
        for (int j = 0; j < 4; j++)
#pragma unroll
            for (int r = 0; r < 4; r++) acc[i][j][r] = 0.f;

    // prologue: stages 0..STAGES-2
#pragma unroll
    for (int s = 0; s < STAGES - 1; s++) {
        const float* ag = Ag + s * 16;
        const float* bg = Bg + s * 16;
        cp_async16(sa + s * buf_stride + l_off,      ag);
        cp_async16(sa + s * buf_stride + l_off + 16, ag + 4);
        cp_async16(sb + s * buf_stride + l_off,      bg);
        cp_async16(sb + s * buf_stride + l_off + 16, bg + 4);
        CP_COMMIT();
    }

    for (int kt = 0; kt < nk; kt++) {
        CP_WAIT(STAGES - 2);
        __syncthreads();

        // issue load for stage kt+STAGES-1 (overwrites stage read at kt-1)
        const int nxt = kt + STAGES - 1;
        if (nxt < nk) {
            const int s = nxt % STAGES;
            const float* ag = Ag + nxt * 16;
            const float* bg = Bg + nxt * 16;
            cp_async16(sa + s * buf_stride + l_off,      ag);
            cp_async16(sa + s * buf_stride + l_off + 16, ag + 4);
            cp_async16(sb + s * buf_stride + l_off,      bg);
            cp_async16(sb + s * buf_stride + l_off + 16, bg + 4);
        }
        CP_COMMIT();

        // compute stage kt%STAGES
        const uint32_t abuf = sa + (kt % STAGES) * buf_stride;
        const uint32_t bbuf = sb + (kt % STAGES) * buf_stride;
#pragma unroll
        for (int ks = 0; ks < 2; ks++) {
            uint32_t af[4][4];
#pragma unroll
            for (int ma = 0; ma < 4; ma++) {
                uint32_t addr = abuf +
                    ((a_frag_row + ma * 16) * GPAD + ks * 8 + a_frag_kw) * 4;
                ldsm4(af[ma][0], af[ma][1], af[ma][2], af[ma][3], addr);
            }
            uint32_t bf[2][4];
#pragma unroll
            for (int nb = 0; nb < 2; nb++) {
                uint32_t addr = bbuf +
                    ((b_frag_n + nb * 16) * GPAD + ks * 8 + b_frag_kw) * 4;
                ldsm4(bf[nb][0], bf[nb][1], bf[nb][2], bf[nb][3], addr);
            }
#pragma unroll
            for (int ma = 0; ma < 4; ma++) {
#pragma unroll
                for (int nb = 0; nb < 2; nb++) {
                    mma_tf32(acc[ma][nb * 2 + 0], af[ma], bf[nb][0], bf[nb][1]);
                    mma_tf32(acc[ma][nb * 2 + 1], af[ma], bf[nb][2], bf[nb][3]);
                }
            }
        }
    }

    // epilogue: bias + store
#pragma unroll
    for (int ma = 0; ma < 4; ma++) {
        const int row0 = bm + wm + ma * 16 + (lane >> 2);
#pragma unroll
        for (int na = 0; na < 4; na++) {
            const int col = bn + wn + na * 8 + (lane & 3) * 2;
            const float b0 = bias[col];
            const float b1 = bias[col + 1];
            float2 v0 = make_float2(acc[ma][na][0] + b0, acc[ma][na][1] + b1);
            float2 v1 = make_float2(acc[ma][na][2] + b0, acc[ma][na][3] + b1);
            *(float2*)(C + (size_t)row0 * N + col)       = v0;
            *(float2*)(C + (size_t)(row0 + 8) * N + col) = v1;
        }
    }
}

// ---------------------------------------------------------------------------
// Flash attention on tensor cores (tf32 mma), GQA + ALiBi + key mask.
// Grid: (S/64, NH, B). Block: 128 threads (4 warps). ctx written tf32-rounded.
// ---------------------------------------------------------------------------
#define FPAD 68
#define FLASH_SMEM ((4 * 64 * FPAD + SS) * 4)

__global__ __launch_bounds__(128)
void flash_attn_mma(const float* __restrict__ qkv,
                    const int* __restrict__ attn_mask,
                    float* __restrict__ ctx)
{
    extern __shared__ float sm[];
    float* Qs = sm;
    float* Ks = Qs + 64 * FPAD;
    float* Vt = Ks + 64 * FPAD;
    float* Ps = Vt + 64 * FPAD;
    float* cb = Ps + 64 * FPAD;

    const int t    = threadIdx.x;
    const int lane = t & 31;
    const int w    = t >> 5;
    const int q0   = blockIdx.x * 64;
    const int h    = blockIdx.y;
    const int b    = blockIdx.z;
    const int kv   = h >> 2;

    const float slope = exp2f(-(float)(h + 1));
    const float scale = 0.125f;

    for (int k = t; k < SS; k += 128) {
        float mbv = (attn_mask[b * SS + k] == 0) ? -1e9f : 0.f;
        cb[k] = mbv - slope * (float)k;
    }

    {
        const int qr = t >> 1;
        const int dc = (t & 1) * 32;
        const float* src = qkv + (size_t)(b * SS + q0 + qr) * QKVC + h * DK + dc;
        float* dst = Qs + qr * FPAD + dc;
#pragma unroll
        for (int e = 0; e < 8; e++) {
            float4 v = *(const float4*)(src + e * 4);
            dst[e * 4 + 0] = to_tf32(v.x * scale);
            dst[e * 4 + 1] = to_tf32(v.y * scale);
            dst[e * 4 + 2] = to_tf32(v.z * scale);
            dst[e * 4 + 3] = to_tf32(v.w * scale);
        }
    }
    __syncthreads();

    const uint32_t qs_base = (uint32_t)__cvta_generic_to_shared(Qs);
    const uint32_t ks_base = (uint32_t)__cvta_generic_to_shared(Ks);
    const uint32_t vt_base = (uint32_t)__cvta_generic_to_shared(Vt);
    const uint32_t ps_base = (uint32_t)__cvta_generic_to_shared(Ps);

    const int a_frag_row = w * 16 + (lane & 15);
    const int a_frag_kw  = (lane >> 4) << 2;
    const int b_frag_n   = ((lane >> 4) << 3) + (lane & 7);
    const int b_frag_kw  = ((lane >> 3) & 1) << 2;

    uint32_t qf[8][4];
#pragma unroll
    for (int ks = 0; ks < 8; ks++) {
        uint32_t addr = qs_base + (a_frag_row * FPAD + ks * 8 + a_frag_kw) * 4;
        ldsm4(qf[ks][0], qf[ks][1], qf[ks][2], qf[ks][3], addr);
    }

    float o[8][4];
#pragma unroll
    for (int nt = 0; nt < 8; nt++)
#pragma unroll
        for (int r = 0; r < 4; r++) o[nt][r] = 0.f;
    float m0 = -1e30f, m1 = -1e30f, l0 = 0.f, l1 = 0.f;

    const float rowq0 = (float)(q0 + w * 16 + (lane >> 2));
    const float rowt0_base = slope * rowq0;
    const float rowt1_base = rowt0_base + slope * 8.f;

    for (int kt = 0; kt < SS / 64; kt++) {
        const int k0 = kt * 64;

        {
            const int kr = t >> 1;
            const int dc = (t & 1) * 32;
            const float* srcK = qkv + (size_t)(b * SS + k0 + kr) * QKVC + DM + kv * DK + dc;
            const float* srcV = qkv + (size_t)(b * SS + k0 + kr) * QKVC + DM + NKV * DK + kv * DK + dc;
            float* dstK = Ks + kr * FPAD + dc;
#pragma unroll
            for (int e = 0; e < 8; e++) {
                float4 kf = *(const float4*)(srcK + e * 4);
                dstK[e * 4 + 0] = to_tf32(kf.x);
                dstK[e * 4 + 1] = to_tf32(kf.y);
                dstK[e * 4 + 2] = to_tf32(kf.z);
                dstK[e * 4 + 3] = to_tf32(kf.w);
                float4 vf = *(const float4*)(srcV + e * 4);
                const int d = dc + e * 4;
                Vt[(d + 0) * FPAD + kr] = to_tf32(vf.x);
                Vt[(d + 1) * FPAD + kr] = to_tf32(vf.y);
                Vt[(d + 2) * FPAD + kr] = to_tf32(vf.z);
                Vt[(d + 3) * FPAD + kr] = to_tf32(vf.w);
            }
        }
        __syncthreads();

        float s[8][4];
#pragma unroll
        for (int nt = 0; nt < 8; nt++)
#pragma unroll
            for (int r = 0; r < 4; r++) s[nt][r] = 0.f;

#pragma unroll
        for (int ks = 0; ks < 8; ks++) {
            uint32_t bf[4][4];
#pragma unroll
            for (int nb = 0; nb < 4; nb++) {
                uint32_t addr = ks_base +
                    ((b_frag_n + nb * 16) * FPAD + ks * 8 + b_frag_kw) * 4;
                ldsm4(bf[nb][0], bf[nb][1], bf[nb][2], bf[nb][3], addr);
            }
#pragma unroll
            for (int nb = 0; nb < 4; nb++) {
                mma_tf32(s[nb * 2 + 0], qf[ks], bf[nb][0], bf[nb][1]);
                mma_tf32(s[nb * 2 + 1], qf[ks], bf[nb][2], bf[nb][3]);
            }
        }

#pragma unroll
        for (int nt = 0; nt < 8; nt++) {
            const int col = k0 + nt * 8 + (lane & 3) * 2;
            float2 c2 = *(const float2*)(cb + col);
            s[nt][0] += rowt0_base + c2.x;
            s[nt][1] += rowt0_base + c2.y;
            s[nt][2] += rowt1_base + c2.x;
            s[nt][3] += rowt1_base + c2.y;
        }

        {
            float mx0 = -1e30f, mx1 = -1e30f;
#pragma unroll
            for (int nt = 0; nt < 8; nt++) {
                mx0 = fmaxf(mx0, fmaxf(s[nt][0], s[nt][1]));
                mx1 = fmaxf(mx1, fmaxf(s[nt][2], s[nt][3]));
            }
            mx0 = fmaxf(mx0, __shfl_xor_sync(0xffffffffu, mx0, 1));
            mx0 = fmaxf(mx0, __shfl_xor_sync(0xffffffffu, mx0, 2));
            mx1 = fmaxf(mx1, __shfl_xor_sync(0xffffffffu, mx1, 1));
            mx1 = fmaxf(mx1, __shfl_xor_sync(0xffffffffu, mx1, 2));

            const float mn0 = fmaxf(m0, mx0);
            const float mn1 = fmaxf(m1, mx1);
            const float al0 = __expf(m0 - mn0);
            const float al1 = __expf(m1 - mn1);
            m0 = mn0; m1 = mn1;

            float rs0 = 0.f, rs1 = 0.f;
#pragma unroll
            for (int nt = 0; nt < 8; nt++) {
                s[nt][0] = __expf(s[nt][0] - mn0);
                s[nt][1] = __expf(s[nt][1] - mn0);
                s[nt][2] = __expf(s[nt][2] - mn1);
                s[nt][3] = __expf(s[nt][3] - mn1);
                rs0 += s[nt][0] + s[nt][1];
                rs1 += s[nt][2] + s[nt][3];
            }
            rs0 += __shfl_xor_sync(0xffffffffu, rs0, 1);
            rs0 += __shfl_xor_sync(0xffffffffu, rs0, 2);
            rs1 += __shfl_xor_sync(0xffffffffu, rs1, 1);
            rs1 += __shfl_xor_sync(0xffffffffu, rs1, 2);
            l0 = l0 * al0 + rs0;
            l1 = l1 * al1 + rs1;

#pragma unroll
            for (int nt = 0; nt < 8; nt++) {
                o[nt][0] *= al0; o[nt][1] *= al0;
                o[nt][2] *= al1; o[nt][3] *= al1;
            }
        }

        {
            const int pr0 = w * 16 + (lane >> 2);
            const int pc  = (lane & 3) * 2;
#pragma unroll
            for (int nt = 0; nt < 8; nt++) {
                *(float2*)(Ps + pr0 * FPAD + nt * 8 + pc) =
                    make_float2(to_tf32(s[nt][0]), to_tf32(s[nt][1]));
                *(float2*)(Ps + (pr0 + 8) * FPAD + nt * 8 + pc) =
                    make_float2(to_tf32(s[nt][2]), to_tf32(s[nt][3]));
            }
        }
        __syncwarp();

#pragma unroll
        for (int ks = 0; ks < 8; ks++) {
            uint32_t pf[4];
            {
                uint32_t addr = ps_base + (a_frag_row * FPAD + ks * 8 + a_frag_kw) * 4;
                ldsm4(pf[0], pf[1], pf[2], pf[3], addr);
            }
            uint32_t vf[4][4];
#pragma unroll
            for (int nb = 0; nb < 4; nb++) {
                uint32_t addr = vt_base +
                    ((b_frag_n + nb * 16) * FPAD + ks * 8 + b_frag_kw) * 4;
                ldsm4(vf[nb][0], vf[nb][1], vf[nb][2], vf[nb][3], addr);
            }
#pragma unroll
            for (int nb = 0; nb < 4; nb++) {
                mma_tf32(o[nb * 2 + 0], pf, vf[nb][0], vf[nb][1]);
                mma_tf32(o[nb * 2 + 1], pf, vf[nb][2], vf[nb][3]);
            }
        }
        __syncthreads();
    }

    // normalize + write ctx (tf32-rounded: feeds the Wo GEMM)
    {
        const float inv0 = 1.f / l0;
        const float inv1 = 1.f / l1;
        const int gr0 = b * SS + q0 + w * 16 + (lane >> 2);
#pragma unroll
        for (int nt = 0; nt < 8; nt++) {
            const int col = h * DK + nt * 8 + (lane & 3) * 2;
            *(float2*)(ctx + (size_t)gr0 * DM + col) =
                make_float2(to_tf32(o[nt][0] * inv0), to_tf32(o[nt][1] * inv0));
            *(float2*)(ctx + (size_t)(gr0 + 8) * DM + col) =
                make_float2(to_tf32(o[nt][2] * inv1), to_tf32(o[nt][3] * inv1));
        }
    }
}

// ---------------------------------------------------------------------------
// y = LayerNorm(a + (pad ? 0 : r)) * gamma + beta, row length 1024
// round_out != 0 -> store tf32-rounded (output feeds a GEMM)
// ---------------------------------------------------------------------------
__global__ __launch_bounds__(256)
void add_ln_kernel(const float* __restrict__ a,
                   const float* __restrict__ r,
                   const unsigned char* __restrict__ pad,
                   const float* __restrict__ gamma,
                   const float* __restrict__ beta,
                   float* __restrict__ out,
                   int round_out)
{
    __shared__ float s_sum[8], s_sq[8];
    const int row = blockIdx.x;
    const int t = threadIdx.x;

    float4 va = *(const float4*)(a + (size_t)row * DM + t * 4);
    float4 vr = *(const float4*)(r + (size_t)row * DM + t * 4);
    if (pad && pad[row]) vr = make_float4(0.f, 0.f, 0.f, 0.f);
    float4 v = make_float4(va.x + vr.x, va.y + vr.y, va.z + vr.z, va.w + vr.w);

    float sum = v.x + v.y + v.z + v.w;
    float sq  = v.x * v.x + v.y * v.y + v.z * v.z + v.w * v.w;
#pragma unroll
    for (int off = 16; off > 0; off >>= 1) {
        sum += __shfl_xor_sync(0xffffffffu, sum, off);
        sq  += __shfl_xor_sync(0xffffffffu, sq, off);
    }
    if ((t & 31) == 0) { s_sum[t >> 5] = sum; s_sq[t >> 5] = sq; }
    __syncthreads();
    sum = 0.f; sq = 0.f;
#pragma unroll
    for (int wv = 0; wv < 8; wv++) { sum += s_sum[wv]; sq += s_sq[wv]; }

    const float mean = sum * (1.f / (float)DM);
    const float var  = sq * (1.f / (float)DM) - mean * mean;
    const float rs   = rsqrtf(var + 1e-5f);

    float4 gg = *(const float4*)(gamma + t * 4);
    float4 bb = *(const float4*)(beta + t * 4);
    float4 y = make_float4((v.x - mean) * rs * gg.x + bb.x,
                           (v.y - mean) * rs * gg.y + bb.y,
                           (v.z - mean) * rs * gg.z + bb.z,
                           (v.w - mean) * rs * gg.w + bb.w);
    if (round_out) {
        y.x = to_tf32(y.x); y.y = to_tf32(y.y);
        y.z = to_tf32(y.z); y.w = to_tf32(y.w);
    }
    *(float4*)(out + (size_t)row * DM + t * 4) = y;
}

// ---------------------------------------------------------------------------
// SwiGLU: g[row, c] = silu(h[row, c]) * h[row, 2048 + c], tf32-rounded output
// ---------------------------------------------------------------------------
__global__ __launch_bounds__(256)
void glu_kernel(const float* __restrict__ h,
                const unsigned char* __restrict__ pad,
                float* __restrict__ g)
{
    const int idx = blockIdx.x * 256 + threadIdx.x;
    const int row = idx / (DFF / 2 / 4);
    const int c4  = idx % (DFF / 2 / 4);
    float4 a = *(const float4*)(h + (size_t)row * DFF + c4 * 4);
    float4 b = *(const float4*)(h + (size_t)row * DFF + DFF / 2 + c4 * 4);
    float4 y;
    y.x = to_tf32((a.x / (1.f + __expf(-a.x))) * b.x);
    y.y = to_tf32((a.y / (1.f + __expf(-a.y))) * b.y);
    y.z = to_tf32((a.z / (1.f + __expf(-a.z))) * b.z);
    y.w = to_tf32((a.w / (1.f + __expf(-a.w))) * b.w);
    if (pad[row]) y = make_float4(0.f, 0.f, 0.f, 0.f);
    *(float4*)(g + (size_t)row * (DFF / 2) + c4 * 4) = y;
}

// ---------------------------------------------------------------------------
// Launch
// ---------------------------------------------------------------------------
extern "C" void kernel_launch(void* const* d_in, const int* in_sizes, int n_in,
                              void* d_out, int out_size)
{
    const float* x          = (const float*)d_in[0];
    const int*   attn_mask  = (const int*)d_in[1];
    const unsigned char* seq_mask = (const unsigned char*)d_in[2];
    const float* Wc  = (const float*)d_in[3];
    const float* bc  = (const float*)d_in[4];
    const float* Wo  = (const float*)d_in[5];
    const float* bo  = (const float*)d_in[6];
    const float* W1  = (const float*)d_in[7];
    const float* b1  = (const float*)d_in[8];
    const float* W2  = (const float*)d_in[9];
    const float* b2  = (const float*)d_in[10];
    const float* g1  = (const float*)d_in[11];
    const float* be1 = (const float*)d_in[12];
    const float* g2  = (const float*)d_in[13];
    const float* be2 = (const float*)d_in[14];
    float* out = (float*)d_out;

    float *qkv, *ctx, *attnout, *x1, *h, *glu, *ffn;
    float *xr, *wct, *wot, *w1t, *w2t;
    cudaGetSymbolAddress((void**)&qkv,     g_qkv);
    cudaGetSymbolAddress((void**)&ctx,     g_ctx);
    cudaGetSymbolAddress((void**)&attnout, g_attnout);
    cudaGetSymbolAddress((void**)&x1,      g_x1);
    cudaGetSymbolAddress((void**)&h,       g_h);
    cudaGetSymbolAddress((void**)&glu,     g_glu);
    cudaGetSymbolAddress((void**)&ffn,     g_ffn);
    cudaGetSymbolAddress((void**)&xr,      g_xr);
    cudaGetSymbolAddress((void**)&wct,     g_wct);
    cudaGetSymbolAddress((void**)&wot,     g_wot);
    cudaGetSymbolAddress((void**)&w1t,     g_w1t);
    cudaGetSymbolAddress((void**)&w2t,     g_w2t);

    cudaFuncSetAttribute(flash_attn_mma, cudaFuncAttributeMaxDynamicSharedMemorySize,
                         FLASH_SMEM);
    cudaFuncSetAttribute(tf32_gemm_cp, cudaFuncAttributeMaxDynamicSharedMemorySize,
                         GEMM_SMEM);

    // ---- pre-pass: tf32 rounding + weight transposes ----
    round_copy<<<(ROWS * DM / 4 + 255) / 256, 256>>>(x, xr, ROWS * DM / 4);
    transpose_round<<<dim3(QKVC / 32, DM / 32),      dim3(32, 8)>>>(Wc, wct, DM, QKVC);
    transpose_round<<<dim3(DM / 32, DM / 32),        dim3(32, 8)>>>(Wo, wot, DM, DM);
    transpose_round<<<dim3(DFF / 32, DM / 32),       dim3(32, 8)>>>(W1, w1t, DM, DFF);
    transpose_round<<<dim3(DM / 32, (DFF/2) / 32),   dim3(32, 8)>>>(W2, w2t, DFF / 2, DM);

    // 1) qkv = x @ Wc + bc
    tf32_gemm_cp<<<dim3(QKVC / 128, ROWS / 128), 256, GEMM_SMEM>>>(ROWS, QKVC, DM, xr, wct, bc, qkv);

    // 2) attention -> ctx (tensor cores)
    flash_attn_mma<<<dim3(SS / 64, NH, BB), 128, FLASH_SMEM>>>(qkv, attn_mask, ctx);

    // 3) attn_out = ctx @ Wo + bo
    tf32_gemm_cp<<<dim3(DM / 128, ROWS / 128), 256, GEMM_SMEM>>>(ROWS, DM, DM, ctx, wot, bo, attnout);

    // 4) x1 = LN(x + attn_out), rounded (feeds W1 GEMM)
    add_ln_kernel<<<ROWS, 256>>>(x, attnout, nullptr, g1, be1, x1, 1);

    // 5) h = x1 @ W1 + b1
    tf32_gemm_cp<<<dim3(DFF / 128, ROWS / 128), 256, GEMM_SMEM>>>(ROWS, DFF, DM, x1, w1t, b1, h);

    // 6) glu = silu(h1)*h2 (pad-zeroed, rounded)
    glu_kernel<<<(ROWS * (DFF / 2) / 4) / 256, 256>>>(h, seq_mask, glu);

    // 7) ffn = glu @ W2 + b2
    tf32_gemm_cp<<<dim3(DM / 128, ROWS / 128), 256, GEMM_SMEM>>>(ROWS, DM, DFF / 2, glu, w2t, b2, ffn);

    // 8) out = LN(x1 + (pad ? 0 : ffn)), full precision
    add_ln_kernel<<<ROWS, 256>>>(x1, ffn, seq_mask, g2, be2, out, 0);
}

// round 9
// speedup vs baseline: 2.5508x; 1.0742x over previous
#include <cuda_runtime.h>
#include <cuda_bf16.h>
#include <cstdint>

// ---------------------------------------------------------------------------
// Problem constants (fixed by setup_inputs)
// ---------------------------------------------------------------------------
#define BB      2
#define SS      2048
#define DM      1024
#define NH      16
#define NKV     4
#define DK      64
#define DFF     4096
#define QKVC    1536          // DM + 2*NKV*DK
#define ROWS    (BB*SS)       // 4096

// ---------------------------------------------------------------------------
// Scratch (static device allocations; allowed by harness rules)
// ---------------------------------------------------------------------------
__device__ float g_qkv    [ROWS * QKVC];
__device__ float g_ctx    [ROWS * DM];
__device__ float g_attnout[ROWS * DM];
__device__ float g_x1     [ROWS * DM];
__device__ float g_h      [ROWS * DFF];
__device__ float g_glu    [ROWS * (DFF/2)];
__device__ float g_ffn    [ROWS * DM];
// tf32-rounded / transposed operands
__device__ float g_xr     [ROWS * DM];          // rounded x
__device__ float g_wct    [QKVC * DM];          // Wc^T  [n][k]
__device__ float g_wot    [DM * DM];            // Wo^T
__device__ float g_w1t    [DFF * DM];           // W1^T
__device__ float g_w2t    [DM * (DFF/2)];       // W2^T

// ---------------------------------------------------------------------------
// tf32 helpers
// ---------------------------------------------------------------------------
__device__ __forceinline__ float to_tf32(float x) {
    float r;
    asm("cvt.rna.tf32.f32 %0, %1;" : "=f"(r) : "f"(x));
    return r;
}

__device__ __forceinline__ void ldsm4(uint32_t& r0, uint32_t& r1,
                                      uint32_t& r2, uint32_t& r3,
                                      uint32_t addr) {
    asm volatile("ldmatrix.sync.aligned.m8n8.x4.shared.b16 {%0,%1,%2,%3}, [%4];"
                 : "=r"(r0), "=r"(r1), "=r"(r2), "=r"(r3) : "r"(addr));
}

__device__ __forceinline__ void mma_tf32(float* c, const uint32_t* a,
                                         uint32_t b0, uint32_t b1) {
    asm volatile(
        "mma.sync.aligned.m16n8k8.row.col.f32.tf32.tf32.f32 "
        "{%0,%1,%2,%3}, {%4,%5,%6,%7}, {%8,%9}, {%0,%1,%2,%3};"
        : "+f"(c[0]), "+f"(c[1]), "+f"(c[2]), "+f"(c[3])
        : "r"(a[0]), "r"(a[1]), "r"(a[2]), "r"(a[3]), "r"(b0), "r"(b1));
}

__device__ __forceinline__ void cp_async16(uint32_t smem_addr, const void* gptr) {
    asm volatile("cp.async.cg.shared.global [%0], [%1], 16;"
                 :: "r"(smem_addr), "l"(gptr));
}
#define CP_COMMIT()  asm volatile("cp.async.commit_group;")
#define CP_WAIT(n)   asm volatile("cp.async.wait_group %0;" :: "n"(n))

// ---------------------------------------------------------------------------
// Pre-pass: tf32-round copy (grid-stride float4)
// ---------------------------------------------------------------------------
__global__ __launch_bounds__(256)
void round_copy(const float* __restrict__ in, float* __restrict__ out, int n4)
{
    int i = blockIdx.x * 256 + threadIdx.x;
    if (i >= n4) return;
    float4 v = ((const float4*)in)[i];
    v.x = to_tf32(v.x); v.y = to_tf32(v.y);
    v.z = to_tf32(v.z); v.w = to_tf32(v.w);
    ((float4*)out)[i] = v;
}

// ---------------------------------------------------------------------------
// Pre-pass: Wt[n][k] = tf32(W[k][n])   (W: [K][N] row-major)
// ---------------------------------------------------------------------------
__global__ __launch_bounds__(256)
void transpose_round(const float* __restrict__ W, float* __restrict__ Wt,
                     int K, int N)
{
    __shared__ float tile[32][33];
    const int n0 = blockIdx.x * 32;
    const int k0 = blockIdx.y * 32;
    const int tx = threadIdx.x;
    const int ty = threadIdx.y;
#pragma unroll
    for (int i = 0; i < 32; i += 8)
        tile[ty + i][tx] = W[(size_t)(k0 + ty + i) * N + n0 + tx];
    __syncthreads();
#pragma unroll
    for (int i = 0; i < 32; i += 8)
        Wt[(size_t)(n0 + ty + i) * K + k0 + tx] = to_tf32(tile[tx][ty + i]);
}

// ---------------------------------------------------------------------------
// tf32 GEMM, warp tile 64x64: C[M,N] = A[M,K] @ Bt[N,K]^T + bias[N]
// Block tile 128x128, BK=16, 128 threads (4 warps, 2x2), 3-stage cp.async.
// ---------------------------------------------------------------------------
#define GPAD   20
#define STAGES 3
#define GEMM_SMEM (STAGES * 2 * 128 * GPAD * 4)

__global__ __launch_bounds__(128, 2)
void tf32_gemm_w64(int M, int N, int K,
                   const float* __restrict__ A,
                   const float* __restrict__ Bt,
                   const float* __restrict__ bias,
                   float* __restrict__ C)
{
    extern __shared__ float smem[];
    float* As = smem;                               // [STAGES][128][GPAD]
    float* Bs = smem + STAGES * 128 * GPAD;         // [STAGES][128][GPAD]

    const int t    = threadIdx.x;
    const int lane = t & 31;
    const int w    = t >> 5;
    const int wm   = (w >> 1) * 64;
    const int wn   = (w & 1) * 64;
    const int bm   = blockIdx.y * 128;
    const int bn   = blockIdx.x * 128;

    // loader: each thread owns one A row and one B row (full k16)
    const float* Ag = A  + (size_t)(bm + t) * K;
    const float* Bg = Bt + (size_t)(bn + t) * K;

    const uint32_t sa = (uint32_t)__cvta_generic_to_shared(As);
    const uint32_t sb = (uint32_t)__cvta_generic_to_shared(Bs);
    const uint32_t buf_stride = 128 * GPAD * 4;
    const uint32_t l_off = (t * GPAD) * 4;

    const int nk = K / 16;

    // fragment addressing
    const int a_frag_row = wm + (lane & 15);
    const int a_frag_kw  = (lane >> 4) << 2;
    const int b_frag_n   = wn + ((lane >> 4) << 3) + (lane & 7);
    const int b_frag_kw  = ((lane >> 3) & 1) << 2;

    float acc[4][8][4];
#pragma unroll
    for (int i = 0; i < 4; i++)
#pragma unroll
        for (int j = 0; j < 8; j++)
#pragma unroll
            for (int r = 0; r < 4; r++) acc[i][j][r] = 0.f;

    // prologue: stages 0..STAGES-2
#pragma unroll
    for (int s = 0; s < STAGES - 1; s++) {
        const float* ag = Ag + s * 16;
        const float* bg = Bg + s * 16;
#pragma unroll
        for (int c = 0; c < 4; c++) {
            cp_async16(sa + s * buf_stride + l_off + c * 16, ag + c * 4);
            cp_async16(sb + s * buf_stride + l_off + c * 16, bg + c * 4);
        }
        CP_COMMIT();
    }

    for (int kt = 0; kt < nk; kt++) {
        CP_WAIT(STAGES - 2);
        __syncthreads();

        const int nxt = kt + STAGES - 1;
        if (nxt < nk) {
            const int s = nxt % STAGES;
            const float* ag = Ag + nxt * 16;
            const float* bg = Bg + nxt * 16;
#pragma unroll
            for (int c = 0; c < 4; c++) {
                cp_async16(sa + s * buf_stride + l_off + c * 16, ag + c * 4);
                cp_async16(sb + s * buf_stride + l_off + c * 16, bg + c * 4);
            }
        }
        CP_COMMIT();

        const uint32_t abuf = sa + (kt % STAGES) * buf_stride;
        const uint32_t bbuf = sb + (kt % STAGES) * buf_stride;
#pragma unroll
        for (int ks = 0; ks < 2; ks++) {
            uint32_t af[4][4];
#pragma unroll
            for (int ma = 0; ma < 4; ma++) {
                uint32_t addr = abuf +
                    ((a_frag_row + ma * 16) * GPAD + ks * 8 + a_frag_kw) * 4;
                ldsm4(af[ma][0], af[ma][1], af[ma][2], af[ma][3], addr);
            }
            uint32_t bf[4][4];
#pragma unroll
            for (int nb = 0; nb < 4; nb++) {
                uint32_t addr = bbuf +
                    ((b_frag_n + nb * 16) * GPAD + ks * 8 + b_frag_kw) * 4;
                ldsm4(bf[nb][0], bf[nb][1], bf[nb][2], bf[nb][3], addr);
            }
#pragma unroll
            for (int ma = 0; ma < 4; ma++) {
#pragma unroll
                for (int nb = 0; nb < 4; nb++) {
                    mma_tf32(acc[ma][nb * 2 + 0], af[ma], bf[nb][0], bf[nb][1]);
                    mma_tf32(acc[ma][nb * 2 + 1], af[ma], bf[nb][2], bf[nb][3]);
                }
            }
        }
    }

    // epilogue: bias + store
#pragma unroll
    for (int ma = 0; ma < 4; ma++) {
        const int row0 = bm + wm + ma * 16 + (lane >> 2);
#pragma unroll
        for (int na = 0; na < 8; na++) {
            const int col = bn + wn + na * 8 + (lane & 3) * 2;
            const float b0 = bias[col];
            const float b1 = bias[col + 1];
            float2 v0 = make_float2(acc[ma][na][0] + b0, acc[ma][na][1] + b1);
            float2 v1 = make_float2(acc[ma][na][2] + b0, acc[ma][na][3] + b1);
            *(float2*)(C + (size_t)row0 * N + col)       = v0;
            *(float2*)(C + (size_t)(row0 + 8) * N + col) = v1;
        }
    }
}

// ---------------------------------------------------------------------------
// Flash attention, tensor cores, 4 heads per block (one KV group).
// Grid: (S/64, NKV, B). Block: 256 threads (8 warps).
// Warp w: head = g*4 + (w>>1), q rows (w&1)*32 .. +31 (warp m-tile 32).
//   Qs[256][68]  rows = head_local*64 + qrow  (warp w owns rows w*32..w*32+31)
//   Ks[64][68]   (key,d)   Vt[64][68] (d,key)   Ps[256][68]   mb[2048]
// ---------------------------------------------------------------------------
#define FPAD 68
#define FLASH_SMEM ((512 * FPAD + 128 * FPAD + SS) * 4)

__global__ __launch_bounds__(256)
void flash_attn_mma4h(const float* __restrict__ qkv,
                      const int* __restrict__ attn_mask,
                      float* __restrict__ ctx)
{
    extern __shared__ float sm[];
    float* Qs = sm;                   // 256 x FPAD
    float* Ps = Qs + 256 * FPAD;      // 256 x FPAD
    float* Ks = Ps + 256 * FPAD;      // 64  x FPAD
    float* Vt = Ks + 64 * FPAD;       // 64  x FPAD
    float* mb = Vt + 64 * FPAD;       // SS

    const int t    = threadIdx.x;
    const int lane = t & 31;
    const int w    = t >> 5;
    const int q0   = blockIdx.x * 64;
    const int g    = blockIdx.y;          // kv group
    const int b    = blockIdx.z;
    const int head = g * 4 + (w >> 1);

    const float slope = exp2f(-(float)(head + 1));   // ALIBI_ALPHA = 1
    const float scale = 0.125f;                       // 1/sqrt(64)

    // mask bias
    for (int k = t; k < SS; k += 256)
        mb[k] = (attn_mask[b * SS + k] == 0) ? -1e9f : 0.f;

    // load Q: thread t -> row t of Qs (= head_local t>>6, qrow t&63)
    {
        const int hl = t >> 6;
        const int qr = t & 63;
        const float* src = qkv + (size_t)(b * SS + q0 + qr) * QKVC + (g * 4 + hl) * DK;
        float* dst = Qs + t * FPAD;
#pragma unroll
        for (int e = 0; e < 16; e++) {
            float4 v = *(const float4*)(src + e * 4);
            dst[e * 4 + 0] = to_tf32(v.x * scale);
            dst[e * 4 + 1] = to_tf32(v.y * scale);
            dst[e * 4 + 2] = to_tf32(v.z * scale);
            dst[e * 4 + 3] = to_tf32(v.w * scale);
        }
    }
    __syncthreads();

    const uint32_t qs_base = (uint32_t)__cvta_generic_to_shared(Qs);
    const uint32_t ks_base = (uint32_t)__cvta_generic_to_shared(Ks);
    const uint32_t vt_base = (uint32_t)__cvta_generic_to_shared(Vt);
    const uint32_t ps_base = (uint32_t)__cvta_generic_to_shared(Ps);

    const int a_frag_row = w * 32 + (lane & 15);      // + ma*16
    const int a_frag_kw  = (lane >> 4) << 2;
    const int b_frag_n   = ((lane >> 4) << 3) + (lane & 7);  // + nb*16
    const int b_frag_kw  = ((lane >> 3) & 1) << 2;

    // hoist Q fragments: m32 x k64 per warp
    uint32_t qf[8][2][4];
#pragma unroll
    for (int ks = 0; ks < 8; ks++)
#pragma unroll
        for (int ma = 0; ma < 2; ma++) {
            uint32_t addr = qs_base +
                ((a_frag_row + ma * 16) * FPAD + ks * 8 + a_frag_kw) * 4;
            ldsm4(qf[ks][ma][0], qf[ks][ma][1], qf[ks][ma][2], qf[ks][ma][3], addr);
        }

    // state: 4 row groups per thread (ma in {0,1} x accumulator halves)
    float o[2][8][4];
#pragma unroll
    for (int ma = 0; ma < 2; ma++)
#pragma unroll
        for (int nt = 0; nt < 8; nt++)
#pragma unroll
            for (int r = 0; r < 4; r++) o[ma][nt][r] = 0.f;
    float m_[2][2] = {{-1e30f, -1e30f}, {-1e30f, -1e30f}};
    float l_[2][2] = {{0.f, 0.f}, {0.f, 0.f}};

    // query positions for the 4 row groups
    const float qbase = (float)(q0 + (w & 1) * 32 + (lane >> 2));
    const float qp[2][2] = {{qbase, qbase + 8.f}, {qbase + 16.f, qbase + 24.f}};

    for (int kt = 0; kt < SS / 64; kt++) {
        const int k0 = kt * 64;

        // load K (natural) / V (transposed), tf32; thread -> kr=t>>2, 16 cols
        {
            const int kr = t >> 2;
            const int dc = (t & 3) * 16;
            const float* srcK = qkv + (size_t)(b * SS + k0 + kr) * QKVC + DM + g * DK + dc;
            const float* srcV = qkv + (size_t)(b * SS + k0 + kr) * QKVC + DM + NKV * DK + g * DK + dc;
            float* dstK = Ks + kr * FPAD + dc;
#pragma unroll
            for (int e = 0; e < 4; e++) {
                float4 kf = *(const float4*)(srcK + e * 4);
                dstK[e * 4 + 0] = to_tf32(kf.x);
                dstK[e * 4 + 1] = to_tf32(kf.y);
                dstK[e * 4 + 2] = to_tf32(kf.z);
                dstK[e * 4 + 3] = to_tf32(kf.w);
                float4 vf = *(const float4*)(srcV + e * 4);
                const int d = dc + e * 4;
                Vt[(d + 0) * FPAD + kr] = to_tf32(vf.x);
                Vt[(d + 1) * FPAD + kr] = to_tf32(vf.y);
                Vt[(d + 2) * FPAD + kr] = to_tf32(vf.z);
                Vt[(d + 3) * FPAD + kr] = to_tf32(vf.w);
            }
        }
        __syncthreads();

        // ---- scores: S = Q @ K^T (m32 x n64 x k64) ----
        float s[2][8][4];
#pragma unroll
        for (int ma = 0; ma < 2; ma++)
#pragma unroll
            for (int nt = 0; nt < 8; nt++)
#pragma unroll
                for (int r = 0; r < 4; r++) s[ma][nt][r] = 0.f;

#pragma unroll
        for (int ks = 0; ks < 8; ks++) {
            uint32_t bf[4][4];
#pragma unroll
            for (int nb = 0; nb < 4; nb++) {
                uint32_t addr = ks_base +
                    ((b_frag_n + nb * 16) * FPAD + ks * 8 + b_frag_kw) * 4;
                ldsm4(bf[nb][0], bf[nb][1], bf[nb][2], bf[nb][3], addr);
            }
#pragma unroll
            for (int nb = 0; nb < 4; nb++)
#pragma unroll
                for (int ma = 0; ma < 2; ma++) {
                    mma_tf32(s[ma][nb * 2 + 0], qf[ks][ma], bf[nb][0], bf[nb][1]);
                    mma_tf32(s[ma][nb * 2 + 1], qf[ks][ma], bf[nb][2], bf[nb][3]);
                }
        }

        // ---- ALiBi + mask ----
#pragma unroll
        for (int nt = 0; nt < 8; nt++) {
            const int col = k0 + nt * 8 + (lane & 3) * 2;
            float2 c2 = *(const float2*)(mb + col);
            const float c0 = (float)col, c1 = (float)(col + 1);
#pragma unroll
            for (int ma = 0; ma < 2; ma++) {
                s[ma][nt][0] += slope * (qp[ma][0] - c0) + c2.x;
                s[ma][nt][1] += slope * (qp[ma][0] - c1) + c2.y;
                s[ma][nt][2] += slope * (qp[ma][1] - c0) + c2.x;
                s[ma][nt][3] += slope * (qp[ma][1] - c1) + c2.y;
            }
        }

        // ---- online softmax (4 row groups) ----
#pragma unroll
        for (int ma = 0; ma < 2; ma++) {
            float mx0 = -1e30f, mx1 = -1e30f;
#pragma unroll
            for (int nt = 0; nt < 8; nt++) {
                mx0 = fmaxf(mx0, fmaxf(s[ma][nt][0], s[ma][nt][1]));
                mx1 = fmaxf(mx1, fmaxf(s[ma][nt][2], s[ma][nt][3]));
            }
            mx0 = fmaxf(mx0, __shfl_xor_sync(0xffffffffu, mx0, 1));
            mx0 = fmaxf(mx0, __shfl_xor_sync(0xffffffffu, mx0, 2));
            mx1 = fmaxf(mx1, __shfl_xor_sync(0xffffffffu, mx1, 1));
            mx1 = fmaxf(mx1, __shfl_xor_sync(0xffffffffu, mx1, 2));

            const float mn0 = fmaxf(m_[ma][0], mx0);
            const float mn1 = fmaxf(m_[ma][1], mx1);
            const float al0 = __expf(m_[ma][0] - mn0);
            const float al1 = __expf(m_[ma][1] - mn1);
            m_[ma][0] = mn0; m_[ma][1] = mn1;

            float rs0 = 0.f, rs1 = 0.f;
#pragma unroll
            for (int nt = 0; nt < 8; nt++) {
                s[ma][nt][0] = __expf(s[ma][nt][0] - mn0);
                s[ma][nt][1] = __expf(s[ma][nt][1] - mn0);
                s[ma][nt][2] = __expf(s[ma][nt][2] - mn1);
                s[ma][nt][3] = __expf(s[ma][nt][3] - mn1);
                rs0 += s[ma][nt][0] + s[ma][nt][1];
                rs1 += s[ma][nt][2] + s[ma][nt][3];
            }
            rs0 += __shfl_xor_sync(0xffffffffu, rs0, 1);
            rs0 += __shfl_xor_sync(0xffffffffu, rs0, 2);
            rs1 += __shfl_xor_sync(0xffffffffu, rs1, 1);
            rs1 += __shfl_xor_sync(0xffffffffu, rs1, 2);
            l_[ma][0] = l_[ma][0] * al0 + rs0;
            l_[ma][1] = l_[ma][1] * al1 + rs1;

#pragma unroll
            for (int nt = 0; nt < 8; nt++) {
                o[ma][nt][0] *= al0; o[ma][nt][1] *= al0;
                o[ma][nt][2] *= al1; o[ma][nt][3] *= al1;
            }
        }

        // ---- P round-trip through per-warp-private smem (tf32) ----
        {
            const int pr = w * 32 + (lane >> 2);
            const int pc = (lane & 3) * 2;
#pragma unroll
            for (int ma = 0; ma < 2; ma++)
#pragma unroll
                for (int nt = 0; nt < 8; nt++) {
                    *(float2*)(Ps + (pr + ma * 16) * FPAD + nt * 8 + pc) =
                        make_float2(to_tf32(s[ma][nt][0]), to_tf32(s[ma][nt][1]));
                    *(float2*)(Ps + (pr + ma * 16 + 8) * FPAD + nt * 8 + pc) =
                        make_float2(to_tf32(s[ma][nt][2]), to_tf32(s[ma][nt][3]));
                }
        }
        __syncwarp();

        // ---- O += P @ V  (m32 x n64(d) x k64(key)) ----
#pragma unroll
        for (int ks = 0; ks < 8; ks++) {
            uint32_t pf[2][4];
#pragma unroll
            for (int ma = 0; ma < 2; ma++) {
                uint32_t addr = ps_base +
                    ((a_frag_row + ma * 16) * FPAD + ks * 8 + a_frag_kw) * 4;
                ldsm4(pf[ma][0], pf[ma][1], pf[ma][2], pf[ma][3], addr);
            }
            uint32_t vf[4][4];
#pragma unroll
            for (int nb = 0; nb < 4; nb++) {
                uint32_t addr = vt_base +
                    ((b_frag_n + nb * 16) * FPAD + ks * 8 + b_frag_kw) * 4;
                ldsm4(vf[nb][0], vf[nb][1], vf[nb][2], vf[nb][3], addr);
            }
#pragma unroll
            for (int nb = 0; nb < 4; nb++)
#pragma unroll
                for (int ma = 0; ma < 2; ma++) {
                    mma_tf32(o[ma][nb * 2 + 0], pf[ma], vf[nb][0], vf[nb][1]);
                    mma_tf32(o[ma][nb * 2 + 1], pf[ma], vf[nb][2], vf[nb][3]);
                }
        }
        __syncthreads();   // protect Ks/Vt before next tile load
    }

    // ---- normalize + write ctx [B,S,H*DK] (tf32-rounded, feeds Wo GEMM) ----
#pragma unroll
    for (int ma = 0; ma < 2; ma++) {
        const float inv0 = 1.f / l_[ma][0];
        const float inv1 = 1.f / l_[ma][1];
        const int gr = b * SS + q0 + (w & 1) * 32 + ma * 16 + (lane >> 2);
#pragma unroll
        for (int nt = 0; nt < 8; nt++) {
            const int col = head * DK + nt * 8 + (lane & 3) * 2;
            *(float2*)(ctx + (size_t)gr * DM + col) =
                make_float2(to_tf32(o[ma][nt][0] * inv0), to_tf32(o[ma][nt][1] * inv0));
            *(float2*)(ctx + (size_t)(gr + 8) * DM + col) =
                make_float2(to_tf32(o[ma][nt][2] * inv1), to_tf32(o[ma][nt][3] * inv1));
        }
    }
}

// ---------------------------------------------------------------------------
// y = LayerNorm(a + (pad ? 0 : r)) * gamma + beta, row length 1024
// ---------------------------------------------------------------------------
__global__ __launch_bounds__(256)
void add_ln_kernel(const float* __restrict__ a,
                   const float* __restrict__ r,
                   const unsigned char* __restrict__ pad,
                   const float* __restrict__ gamma,
                   const float* __restrict__ beta,
                   float* __restrict__ out,
                   int round_out)
{
    __shared__ float s_sum[8], s_sq[8];
    const int row = blockIdx.x;
    const int t = threadIdx.x;

    float4 va = *(const float4*)(a + (size_t)row * DM + t * 4);
    float4 vr = *(const float4*)(r + (size_t)row * DM + t * 4);
    if (pad && pad[row]) vr = make_float4(0.f, 0.f, 0.f, 0.f);
    float4 v = make_float4(va.x + vr.x, va.y + vr.y, va.z + vr.z, va.w + vr.w);

    float sum = v.x + v.y + v.z + v.w;
    float sq  = v.x * v.x + v.y * v.y + v.z * v.z + v.w * v.w;
#pragma unroll
    for (int off = 16; off > 0; off >>= 1) {
        sum += __shfl_xor_sync(0xffffffffu, sum, off);
        sq  += __shfl_xor_sync(0xffffffffu, sq, off);
    }
    if ((t & 31) == 0) { s_sum[t >> 5] = sum; s_sq[t >> 5] = sq; }
    __syncthreads();
    sum = 0.f; sq = 0.f;
#pragma unroll
    for (int wv = 0; wv < 8; wv++) { sum += s_sum[wv]; sq += s_sq[wv]; }

    const float mean = sum * (1.f / (float)DM);
    const float var  = sq * (1.f / (float)DM) - mean * mean;
    const float rs   = rsqrtf(var + 1e-5f);

    float4 gg = *(const float4*)(gamma + t * 4);
    float4 bb = *(const float4*)(beta + t * 4);
    float4 y = make_float4((v.x - mean) * rs * gg.x + bb.x,
                           (v.y - mean) * rs * gg.y + bb.y,
                           (v.z - mean) * rs * gg.z + bb.z,
                           (v.w - mean) * rs * gg.w + bb.w);
    if (round_out) {
        y.x = to_tf32(y.x); y.y = to_tf32(y.y);
        y.z = to_tf32(y.z); y.w = to_tf32(y.w);
    }
    *(float4*)(out + (size_t)row * DM + t * 4) = y;
}

// ---------------------------------------------------------------------------
// SwiGLU: g[row, c] = silu(h[row, c]) * h[row, 2048 + c], tf32-rounded output
// ---------------------------------------------------------------------------
__global__ __launch_bounds__(256)
void glu_kernel(const float* __restrict__ h,
                const unsigned char* __restrict__ pad,
                float* __restrict__ g)
{
    const int idx = blockIdx.x * 256 + threadIdx.x;
    const int row = idx / (DFF / 2 / 4);
    const int c4  = idx % (DFF / 2 / 4);
    float4 a = *(const float4*)(h + (size_t)row * DFF + c4 * 4);
    float4 b = *(const float4*)(h + (size_t)row * DFF + DFF / 2 + c4 * 4);
    float4 y;
    y.x = to_tf32((a.x / (1.f + __expf(-a.x))) * b.x);
    y.y = to_tf32((a.y / (1.f + __expf(-a.y))) * b.y);
    y.z = to_tf32((a.z / (1.f + __expf(-a.z))) * b.z);
    y.w = to_tf32((a.w / (1.f + __expf(-a.w))) * b.w);
    if (pad[row]) y = make_float4(0.f, 0.f, 0.f, 0.f);
    *(float4*)(g + (size_t)row * (DFF / 2) + c4 * 4) = y;
}

// ---------------------------------------------------------------------------
// Launch
// ---------------------------------------------------------------------------
extern "C" void kernel_launch(void* const* d_in, const int* in_sizes, int n_in,
                              void* d_out, int out_size)
{
    const float* x          = (const float*)d_in[0];
    const int*   attn_mask  = (const int*)d_in[1];
    const unsigned char* seq_mask = (const unsigned char*)d_in[2];
    const float* Wc  = (const float*)d_in[3];
    const float* bc  = (const float*)d_in[4];
    const float* Wo  = (const float*)d_in[5];
    const float* bo  = (const float*)d_in[6];
    const float* W1  = (const float*)d_in[7];
    const float* b1  = (const float*)d_in[8];
    const float* W2  = (const float*)d_in[9];
    const float* b2  = (const float*)d_in[10];
    const float* g1  = (const float*)d_in[11];
    const float* be1 = (const float*)d_in[12];
    const float* g2  = (const float*)d_in[13];
    const float* be2 = (const float*)d_in[14];
    float* out = (float*)d_out;

    float *qkv, *ctx, *attnout, *x1, *h, *glu, *ffn;
    float *xr, *wct, *wot, *w1t, *w2t;
    cudaGetSymbolAddress((void**)&qkv,     g_qkv);
    cudaGetSymbolAddress((void**)&ctx,     g_ctx);
    cudaGetSymbolAddress((void**)&attnout, g_attnout);
    cudaGetSymbolAddress((void**)&x1,      g_x1);
    cudaGetSymbolAddress((void**)&h,       g_h);
    cudaGetSymbolAddress((void**)&glu,     g_glu);
    cudaGetSymbolAddress((void**)&ffn,     g_ffn);
    cudaGetSymbolAddress((void**)&xr,      g_xr);
    cudaGetSymbolAddress((void**)&wct,     g_wct);
    cudaGetSymbolAddress((void**)&wot,     g_wot);
    cudaGetSymbolAddress((void**)&w1t,     g_w1t);
    cudaGetSymbolAddress((void**)&w2t,     g_w2t);

    cudaFuncSetAttribute(flash_attn_mma4h, cudaFuncAttributeMaxDynamicSharedMemorySize,
                         FLASH_SMEM);
    cudaFuncSetAttribute(tf32_gemm_w64, cudaFuncAttributeMaxDynamicSharedMemorySize,
                         GEMM_SMEM);

    // ---- pre-pass: tf32 rounding + weight transposes ----
    round_copy<<<(ROWS * DM / 4 + 255) / 256, 256>>>(x, xr, ROWS * DM / 4);
    transpose_round<<<dim3(QKVC / 32, DM / 32),      dim3(32, 8)>>>(Wc, wct, DM, QKVC);
    transpose_round<<<dim3(DM / 32, DM / 32),        dim3(32, 8)>>>(Wo, wot, DM, DM);
    transpose_round<<<dim3(DFF / 32, DM / 32),       dim3(32, 8)>>>(W1, w1t, DM, DFF);
    transpose_round<<<dim3(DM / 32, (DFF/2) / 32),   dim3(32, 8)>>>(W2, w2t, DFF / 2, DM);

    // 1) qkv = x @ Wc + bc
    tf32_gemm_w64<<<dim3(QKVC / 128, ROWS / 128), 128, GEMM_SMEM>>>(ROWS, QKVC, DM, xr, wct, bc, qkv);

    // 2) attention -> ctx (tensor cores, 4 heads per block)
    flash_attn_mma4h<<<dim3(SS / 64, NKV, BB), 256, FLASH_SMEM>>>(qkv, attn_mask, ctx);

    // 3) attn_out = ctx @ Wo + bo
    tf32_gemm_w64<<<dim3(DM / 128, ROWS / 128), 128, GEMM_SMEM>>>(ROWS, DM, DM, ctx, wot, bo, attnout);

    // 4) x1 = LN(x + attn_out), rounded (feeds W1 GEMM)
    add_ln_kernel<<<ROWS, 256>>>(x, attnout, nullptr, g1, be1, x1, 1);

    // 5) h = x1 @ W1 + b1
    tf32_gemm_w64<<<dim3(DFF / 128, ROWS / 128), 128, GEMM_SMEM>>>(ROWS, DFF, DM, x1, w1t, b1, h);

    // 6) glu = silu(h1)*h2 (pad-zeroed, rounded)
    glu_kernel<<<(ROWS * (DFF / 2) / 4) / 256, 256>>>(h, seq_mask, glu);

    // 7) ffn = glu @ W2 + b2
    tf32_gemm_w64<<<dim3(DM / 128, ROWS / 128), 128, GEMM_SMEM>>>(ROWS, DM, DFF / 2, glu, w2t, b2, ffn);

    // 8) out = LN(x1 + (pad ? 0 : ffn)), full precision
    add_ln_kernel<<<ROWS, 256>>>(x1, ffn, seq_mask, g2, be2, out, 0);
}

// round 10
// speedup vs baseline: 4.2789x; 1.6775x over previous
#include <cuda_runtime.h>
#include <cuda_fp16.h>
#include <cstdint>

// ---------------------------------------------------------------------------
// Problem constants (fixed by setup_inputs)
// ---------------------------------------------------------------------------
#define BB      2
#define SS      2048
#define DM      1024
#define NH      16
#define NKV     4
#define DK      64
#define DFF     4096
#define QKVC    1536          // DM + 2*NKV*DK
#define ROWS    (BB*SS)       // 4096

// ---------------------------------------------------------------------------
// Scratch (static device allocations; allowed by harness rules)
// ---------------------------------------------------------------------------
__device__ float  g_qkv    [ROWS * QKVC];
__device__ __half g_ctxh   [ROWS * DM];
__device__ float  g_attnout[ROWS * DM];
__device__ float  g_x1     [ROWS * DM];
__device__ __half g_x1h    [ROWS * DM];
__device__ float  g_h      [ROWS * DFF];
__device__ __half g_gluh   [ROWS * (DFF/2)];
__device__ float  g_ffn    [ROWS * DM];
// half operands
__device__ __half g_xh     [ROWS * DM];
__device__ __half g_wct    [QKVC * DM];          // Wc^T [n][k]
__device__ __half g_wot    [DM * DM];
__device__ __half g_w1t    [DFF * DM];
__device__ __half g_w2t    [DM * (DFF/2)];

// ---------------------------------------------------------------------------
// helpers
// ---------------------------------------------------------------------------
__device__ __forceinline__ void ldsm4(uint32_t& r0, uint32_t& r1,
                                      uint32_t& r2, uint32_t& r3,
                                      uint32_t addr) {
    asm volatile("ldmatrix.sync.aligned.m8n8.x4.shared.b16 {%0,%1,%2,%3}, [%4];"
                 : "=r"(r0), "=r"(r1), "=r"(r2), "=r"(r3) : "r"(addr));
}

__device__ __forceinline__ void mma_f16(float* c, const uint32_t* a,
                                        uint32_t b0, uint32_t b1) {
    asm volatile(
        "mma.sync.aligned.m16n8k16.row.col.f32.f16.f16.f32 "
        "{%0,%1,%2,%3}, {%4,%5,%6,%7}, {%8,%9}, {%0,%1,%2,%3};"
        : "+f"(c[0]), "+f"(c[1]), "+f"(c[2]), "+f"(c[3])
        : "r"(a[0]), "r"(a[1]), "r"(a[2]), "r"(a[3]), "r"(b0), "r"(b1));
}

__device__ __forceinline__ void cp_async16(uint32_t smem_addr, const void* gptr) {
    asm volatile("cp.async.cg.shared.global [%0], [%1], 16;"
                 :: "r"(smem_addr), "l"(gptr));
}
#define CP_COMMIT()  asm volatile("cp.async.commit_group;")
#define CP_WAIT(n)   asm volatile("cp.async.wait_group %0;" :: "n"(n))

// ---------------------------------------------------------------------------
// Pre-pass: f32 -> f16 copy (float4 granularity)
// ---------------------------------------------------------------------------
__global__ __launch_bounds__(256)
void round_to_half(const float* __restrict__ in, __half* __restrict__ out, int n4)
{
    int i = blockIdx.x * 256 + threadIdx.x;
    if (i >= n4) return;
    float4 v = ((const float4*)in)[i];
    __half2* o = (__half2*)(out + (size_t)i * 4);
    o[0] = __floats2half2_rn(v.x, v.y);
    o[1] = __floats2half2_rn(v.z, v.w);
}

// ---------------------------------------------------------------------------
// Pre-pass: Wt[n][k] = half(W[k][n])   (W: [K][N] row-major fp32)
// ---------------------------------------------------------------------------
__global__ __launch_bounds__(256)
void transpose_to_half(const float* __restrict__ W, __half* __restrict__ Wt,
                       int K, int N)
{
    __shared__ float tile[32][33];
    const int n0 = blockIdx.x * 32;
    const int k0 = blockIdx.y * 32;
    const int tx = threadIdx.x;
    const int ty = threadIdx.y;
#pragma unroll
    for (int i = 0; i < 32; i += 8)
        tile[ty + i][tx] = W[(size_t)(k0 + ty + i) * N + n0 + tx];
    __syncthreads();
#pragma unroll
    for (int i = 0; i < 32; i += 8)
        Wt[(size_t)(n0 + ty + i) * K + k0 + tx] = __float2half_rn(tile[tx][ty + i]);
}

// ---------------------------------------------------------------------------
// fp16 GEMM, warp tile 64x64: C[M,N] = A[M,K] @ Bt[N,K]^T + bias[N]  (fp32 acc)
// Block tile 128x128, BK=32 halves, 128 threads (4 warps 2x2), 3-stage cp.async.
// Row stride 40 halves (80 B) -> conflict-free ldmatrix.
// ---------------------------------------------------------------------------
#define GPADH  40
#define STAGES 3
#define GEMM_SMEM (STAGES * 2 * 128 * GPADH * 2)

__global__ __launch_bounds__(128, 2)
void f16_gemm_w64(int M, int N, int K,
                  const __half* __restrict__ A,
                  const __half* __restrict__ Bt,
                  const float* __restrict__ bias,
                  float* __restrict__ C)
{
    extern __shared__ char smraw[];
    __half* As = (__half*)smraw;                       // [STAGES][128][GPADH]
    __half* Bs = As + STAGES * 128 * GPADH;            // [STAGES][128][GPADH]

    const int t    = threadIdx.x;
    const int lane = t & 31;
    const int w    = t >> 5;
    const int wm   = (w >> 1) * 64;
    const int wn   = (w & 1) * 64;
    const int bm   = blockIdx.y * 128;
    const int bn   = blockIdx.x * 128;

    // loader: thread t owns one A row and one B row, 32 halves (64 B) per stage
    const __half* Ag = A  + (size_t)(bm + t) * K;
    const __half* Bg = Bt + (size_t)(bn + t) * K;

    const uint32_t sa = (uint32_t)__cvta_generic_to_shared(As);
    const uint32_t sb = (uint32_t)__cvta_generic_to_shared(Bs);
    const uint32_t buf_stride = 128 * GPADH * 2;
    const uint32_t l_off = t * GPADH * 2;

    const int nk = K / 32;

    // fragment addressing (bytes)
    const int a_row   = wm + (lane & 15);              // + ma*16
    const int a_koff  = (lane >> 4) * 16;              // byte offset within k16
    const int b_row   = wn + ((lane >> 4) << 3) + (lane & 7);   // + nb*16
    const int b_koff  = ((lane >> 3) & 1) * 16;

    float acc[4][8][4];
#pragma unroll
    for (int i = 0; i < 4; i++)
#pragma unroll
        for (int j = 0; j < 8; j++)
#pragma unroll
            for (int r = 0; r < 4; r++) acc[i][j][r] = 0.f;

    // prologue
#pragma unroll
    for (int s = 0; s < STAGES - 1; s++) {
        const __half* ag = Ag + s * 32;
        const __half* bg = Bg + s * 32;
#pragma unroll
        for (int c = 0; c < 4; c++) {
            cp_async16(sa + s * buf_stride + l_off + c * 16, ag + c * 8);
            cp_async16(sb + s * buf_stride + l_off + c * 16, bg + c * 8);
        }
        CP_COMMIT();
    }

    for (int kt = 0; kt < nk; kt++) {
        CP_WAIT(STAGES - 2);
        __syncthreads();

        const int nxt = kt + STAGES - 1;
        if (nxt < nk) {
            const int s = nxt % STAGES;
            const __half* ag = Ag + nxt * 32;
            const __half* bg = Bg + nxt * 32;
#pragma unroll
            for (int c = 0; c < 4; c++) {
                cp_async16(sa + s * buf_stride + l_off + c * 16, ag + c * 8);
                cp_async16(sb + s * buf_stride + l_off + c * 16, bg + c * 8);
            }
        }
        CP_COMMIT();

        const uint32_t abuf = sa + (kt % STAGES) * buf_stride;
        const uint32_t bbuf = sb + (kt % STAGES) * buf_stride;
#pragma unroll
        for (int ks = 0; ks < 2; ks++) {               // two k16 steps
            uint32_t af[4][4];
#pragma unroll
            for (int ma = 0; ma < 4; ma++) {
                uint32_t addr = abuf +
                    ((a_row + ma * 16) * GPADH + ks * 16) * 2 + a_koff;
                ldsm4(af[ma][0], af[ma][1], af[ma][2], af[ma][3], addr);
            }
            uint32_t bf[4][4];
#pragma unroll
            for (int nb = 0; nb < 4; nb++) {
                uint32_t addr = bbuf +
                    ((b_row + nb * 16) * GPADH + ks * 16) * 2 + b_koff;
                ldsm4(bf[nb][0], bf[nb][1], bf[nb][2], bf[nb][3], addr);
            }
#pragma unroll
            for (int ma = 0; ma < 4; ma++) {
#pragma unroll
                for (int nb = 0; nb < 4; nb++) {
                    mma_f16(acc[ma][nb * 2 + 0], af[ma], bf[nb][0], bf[nb][1]);
                    mma_f16(acc[ma][nb * 2 + 1], af[ma], bf[nb][2], bf[nb][3]);
                }
            }
        }
    }

    // epilogue: bias + fp32 store
#pragma unroll
    for (int ma = 0; ma < 4; ma++) {
        const int row0 = bm + wm + ma * 16 + (lane >> 2);
#pragma unroll
        for (int na = 0; na < 8; na++) {
            const int col = bn + wn + na * 8 + (lane & 3) * 2;
            const float b0 = bias[col];
            const float b1 = bias[col + 1];
            float2 v0 = make_float2(acc[ma][na][0] + b0, acc[ma][na][1] + b1);
            float2 v1 = make_float2(acc[ma][na][2] + b0, acc[ma][na][3] + b1);
            *(float2*)(C + (size_t)row0 * N + col)       = v0;
            *(float2*)(C + (size_t)(row0 + 8) * N + col) = v1;
        }
    }
}

// ---------------------------------------------------------------------------
// Flash attention, fp16 tensor cores, 4 heads per block (one KV group).
// Grid: (S/64, NKV, B). Block: 256 threads (8 warps). Warp m-tile 32.
//   Qs[256][72]h  Ps[256][72]h  Ks[64][72]h (key,d)  Vt[64][72]h (d,key)
//   mb[2048]f  — writes ctx as half (feeds Wo GEMM)
// ---------------------------------------------------------------------------
#define FPADH 72
#define FLASH_SMEM ((512 * FPADH + 128 * FPADH) * 2 + SS * 4)

__global__ __launch_bounds__(256)
void flash_attn_f16(const float* __restrict__ qkv,
                    const int* __restrict__ attn_mask,
                    __half* __restrict__ ctx)
{
    extern __shared__ char smraw[];
    __half* Qs = (__half*)smraw;            // 256 x FPADH
    __half* Ps = Qs + 256 * FPADH;          // 256 x FPADH
    __half* Ks = Ps + 256 * FPADH;          // 64  x FPADH
    __half* Vt = Ks + 64 * FPADH;           // 64  x FPADH
    float*  mb = (float*)(Vt + 64 * FPADH); // SS

    const int t    = threadIdx.x;
    const int lane = t & 31;
    const int w    = t >> 5;
    const int q0   = blockIdx.x * 64;
    const int g    = blockIdx.y;
    const int b    = blockIdx.z;
    const int head = g * 4 + (w >> 1);

    const float slope = exp2f(-(float)(head + 1));
    const float scale = 0.125f;

    for (int k = t; k < SS; k += 256)
        mb[k] = (attn_mask[b * SS + k] == 0) ? -1e9f : 0.f;

    // Q load: thread t -> row t of Qs (head_local = t>>6, qrow = t&63)
    {
        const int hl = t >> 6;
        const int qr = t & 63;
        const float* src = qkv + (size_t)(b * SS + q0 + qr) * QKVC + (g * 4 + hl) * DK;
        __half* dst = Qs + t * FPADH;
#pragma unroll
        for (int e = 0; e < 16; e++) {
            float4 v = *(const float4*)(src + e * 4);
            *(__half2*)(dst + e * 4)     = __floats2half2_rn(v.x * scale, v.y * scale);
            *(__half2*)(dst + e * 4 + 2) = __floats2half2_rn(v.z * scale, v.w * scale);
        }
    }
    __syncthreads();

    const uint32_t qs_base = (uint32_t)__cvta_generic_to_shared(Qs);
    const uint32_t ks_base = (uint32_t)__cvta_generic_to_shared(Ks);
    const uint32_t vt_base = (uint32_t)__cvta_generic_to_shared(Vt);
    const uint32_t ps_base = (uint32_t)__cvta_generic_to_shared(Ps);

    const int a_row  = w * 32 + (lane & 15);       // + ma*16
    const int a_koff = (lane >> 4) * 16;           // bytes
    const int b_row  = ((lane >> 4) << 3) + (lane & 7);  // + nb*16
    const int b_koff = ((lane >> 3) & 1) * 16;

    // hoist Q fragments: m32 x k64 per warp, 4 k16 steps
    uint32_t qf[4][2][4];
#pragma unroll
    for (int ks = 0; ks < 4; ks++)
#pragma unroll
        for (int ma = 0; ma < 2; ma++) {
            uint32_t addr = qs_base +
                ((a_row + ma * 16) * FPADH + ks * 16) * 2 + a_koff;
            ldsm4(qf[ks][ma][0], qf[ks][ma][1], qf[ks][ma][2], qf[ks][ma][3], addr);
        }

    float o[2][8][4];
#pragma unroll
    for (int ma = 0; ma < 2; ma++)
#pragma unroll
        for (int nt = 0; nt < 8; nt++)
#pragma unroll
            for (int r = 0; r < 4; r++) o[ma][nt][r] = 0.f;
    float m_[2][2] = {{-1e30f, -1e30f}, {-1e30f, -1e30f}};
    float l_[2][2] = {{0.f, 0.f}, {0.f, 0.f}};

    const float qbase = (float)(q0 + (w & 1) * 32 + (lane >> 2));
    const float qp[2][2] = {{qbase, qbase + 8.f}, {qbase + 16.f, qbase + 24.f}};

    for (int kt = 0; kt < SS / 64; kt++) {
        const int k0 = kt * 64;

        // load K (natural) / V (transposed), half
        {
            const int kr = t >> 2;
            const int dc = (t & 3) * 16;
            const float* srcK = qkv + (size_t)(b * SS + k0 + kr) * QKVC + DM + g * DK + dc;
            const float* srcV = qkv + (size_t)(b * SS + k0 + kr) * QKVC + DM + NKV * DK + g * DK + dc;
            __half* dstK = Ks + kr * FPADH + dc;
#pragma unroll
            for (int e = 0; e < 4; e++) {
                float4 kf = *(const float4*)(srcK + e * 4);
                *(__half2*)(dstK + e * 4)     = __floats2half2_rn(kf.x, kf.y);
                *(__half2*)(dstK + e * 4 + 2) = __floats2half2_rn(kf.z, kf.w);
                float4 vf = *(const float4*)(srcV + e * 4);
                const int d = dc + e * 4;
                Vt[(d + 0) * FPADH + kr] = __float2half_rn(vf.x);
                Vt[(d + 1) * FPADH + kr] = __float2half_rn(vf.y);
                Vt[(d + 2) * FPADH + kr] = __float2half_rn(vf.z);
                Vt[(d + 3) * FPADH + kr] = __float2half_rn(vf.w);
            }
        }
        __syncthreads();

        // ---- scores: S = Q @ K^T (m32 x n64 x k64) ----
        float s[2][8][4];
#pragma unroll
        for (int ma = 0; ma < 2; ma++)
#pragma unroll
            for (int nt = 0; nt < 8; nt++)
#pragma unroll
                for (int r = 0; r < 4; r++) s[ma][nt][r] = 0.f;

#pragma unroll
        for (int ks = 0; ks < 4; ks++) {
            uint32_t bf[4][4];
#pragma unroll
            for (int nb = 0; nb < 4; nb++) {
                uint32_t addr = ks_base +
                    ((b_row + nb * 16) * FPADH + ks * 16) * 2 + b_koff;
                ldsm4(bf[nb][0], bf[nb][1], bf[nb][2], bf[nb][3], addr);
            }
#pragma unroll
            for (int nb = 0; nb < 4; nb++)
#pragma unroll
                for (int ma = 0; ma < 2; ma++) {
                    mma_f16(s[ma][nb * 2 + 0], qf[ks][ma], bf[nb][0], bf[nb][1]);
                    mma_f16(s[ma][nb * 2 + 1], qf[ks][ma], bf[nb][2], bf[nb][3]);
                }
        }

        // ---- ALiBi + mask (fp32) ----
#pragma unroll
        for (int nt = 0; nt < 8; nt++) {
            const int col = k0 + nt * 8 + (lane & 3) * 2;
            float2 c2 = *(const float2*)(mb + col);
            const float c0 = (float)col, c1 = (float)(col + 1);
#pragma unroll
            for (int ma = 0; ma < 2; ma++) {
                s[ma][nt][0] += slope * (qp[ma][0] - c0) + c2.x;
                s[ma][nt][1] += slope * (qp[ma][0] - c1) + c2.y;
                s[ma][nt][2] += slope * (qp[ma][1] - c0) + c2.x;
                s[ma][nt][3] += slope * (qp[ma][1] - c1) + c2.y;
            }
        }

        // ---- online softmax ----
#pragma unroll
        for (int ma = 0; ma < 2; ma++) {
            float mx0 = -1e30f, mx1 = -1e30f;
#pragma unroll
            for (int nt = 0; nt < 8; nt++) {
                mx0 = fmaxf(mx0, fmaxf(s[ma][nt][0], s[ma][nt][1]));
                mx1 = fmaxf(mx1, fmaxf(s[ma][nt][2], s[ma][nt][3]));
            }
            mx0 = fmaxf(mx0, __shfl_xor_sync(0xffffffffu, mx0, 1));
            mx0 = fmaxf(mx0, __shfl_xor_sync(0xffffffffu, mx0, 2));
            mx1 = fmaxf(mx1, __shfl_xor_sync(0xffffffffu, mx1, 1));
            mx1 = fmaxf(mx1, __shfl_xor_sync(0xffffffffu, mx1, 2));

            const float mn0 = fmaxf(m_[ma][0], mx0);
            const float mn1 = fmaxf(m_[ma][1], mx1);
            const float al0 = __expf(m_[ma][0] - mn0);
            const float al1 = __expf(m_[ma][1] - mn1);
            m_[ma][0] = mn0; m_[ma][1] = mn1;

            float rs0 = 0.f, rs1 = 0.f;
#pragma unroll
            for (int nt = 0; nt < 8; nt++) {
                s[ma][nt][0] = __expf(s[ma][nt][0] - mn0);
                s[ma][nt][1] = __expf(s[ma][nt][1] - mn0);
                s[ma][nt][2] = __expf(s[ma][nt][2] - mn1);
                s[ma][nt][3] = __expf(s[ma][nt][3] - mn1);
                rs0 += s[ma][nt][0] + s[ma][nt][1];
                rs1 += s[ma][nt][2] + s[ma][nt][3];
            }
            rs0 += __shfl_xor_sync(0xffffffffu, rs0, 1);
            rs0 += __shfl_xor_sync(0xffffffffu, rs0, 2);
            rs1 += __shfl_xor_sync(0xffffffffu, rs1, 1);
            rs1 += __shfl_xor_sync(0xffffffffu, rs1, 2);
            l_[ma][0] = l_[ma][0] * al0 + rs0;
            l_[ma][1] = l_[ma][1] * al1 + rs1;

#pragma unroll
            for (int nt = 0; nt < 8; nt++) {
                o[ma][nt][0] *= al0; o[ma][nt][1] *= al0;
                o[ma][nt][2] *= al1; o[ma][nt][3] *= al1;
            }
        }

        // ---- P -> half smem (per-warp-private rows) ----
        {
            const int pr = w * 32 + (lane >> 2);
            const int pc = (lane & 3) * 2;
#pragma unroll
            for (int ma = 0; ma < 2; ma++)
#pragma unroll
                for (int nt = 0; nt < 8; nt++) {
                    *(__half2*)(Ps + (pr + ma * 16) * FPADH + nt * 8 + pc) =
                        __floats2half2_rn(s[ma][nt][0], s[ma][nt][1]);
                    *(__half2*)(Ps + (pr + ma * 16 + 8) * FPADH + nt * 8 + pc) =
                        __floats2half2_rn(s[ma][nt][2], s[ma][nt][3]);
                }
        }
        __syncwarp();

        // ---- O += P @ V  (m32 x n64(d) x k64(key)) ----
#pragma unroll
        for (int ks = 0; ks < 4; ks++) {
            uint32_t pf[2][4];
#pragma unroll
            for (int ma = 0; ma < 2; ma++) {
                uint32_t addr = ps_base +
                    ((a_row + ma * 16) * FPADH + ks * 16) * 2 + a_koff;
                ldsm4(pf[ma][0], pf[ma][1], pf[ma][2], pf[ma][3], addr);
            }
            uint32_t vf[4][4];
#pragma unroll
            for (int nb = 0; nb < 4; nb++) {
                uint32_t addr = vt_base +
                    ((b_row + nb * 16) * FPADH + ks * 16) * 2 + b_koff;
                ldsm4(vf[nb][0], vf[nb][1], vf[nb][2], vf[nb][3], addr);
            }
#pragma unroll
            for (int nb = 0; nb < 4; nb++)
#pragma unroll
                for (int ma = 0; ma < 2; ma++) {
                    mma_f16(o[ma][nb * 2 + 0], pf[ma], vf[nb][0], vf[nb][1]);
                    mma_f16(o[ma][nb * 2 + 1], pf[ma], vf[nb][2], vf[nb][3]);
                }
        }
        __syncthreads();
    }

    // ---- normalize + write ctx as half [B,S,H*DK] ----
#pragma unroll
    for (int ma = 0; ma < 2; ma++) {
        const float inv0 = 1.f / l_[ma][0];
        const float inv1 = 1.f / l_[ma][1];
        const int gr = b * SS + q0 + (w & 1) * 32 + ma * 16 + (lane >> 2);
#pragma unroll
        for (int nt = 0; nt < 8; nt++) {
            const int col = head * DK + nt * 8 + (lane & 3) * 2;
            *(__half2*)(ctx + (size_t)gr * DM + col) =
                __floats2half2_rn(o[ma][nt][0] * inv0, o[ma][nt][1] * inv0);
            *(__half2*)(ctx + (size_t)(gr + 8) * DM + col) =
                __floats2half2_rn(o[ma][nt][2] * inv1, o[ma][nt][3] * inv1);
        }
    }
}

// ---------------------------------------------------------------------------
// y = LayerNorm(a + (pad ? 0 : r)) * gamma + beta; optional half copy
// ---------------------------------------------------------------------------
__global__ __launch_bounds__(256)
void add_ln_kernel(const float* __restrict__ a,
                   const float* __restrict__ r,
                   const unsigned char* __restrict__ pad,
                   const float* __restrict__ gamma,
                   const float* __restrict__ beta,
                   float* __restrict__ out,
                   __half* __restrict__ outh)
{
    __shared__ float s_sum[8], s_sq[8];
    const int row = blockIdx.x;
    const int t = threadIdx.x;

    float4 va = *(const float4*)(a + (size_t)row * DM + t * 4);
    float4 vr = *(const float4*)(r + (size_t)row * DM + t * 4);
    if (pad && pad[row]) vr = make_float4(0.f, 0.f, 0.f, 0.f);
    float4 v = make_float4(va.x + vr.x, va.y + vr.y, va.z + vr.z, va.w + vr.w);

    float sum = v.x + v.y + v.z + v.w;
    float sq  = v.x * v.x + v.y * v.y + v.z * v.z + v.w * v.w;
#pragma unroll
    for (int off = 16; off > 0; off >>= 1) {
        sum += __shfl_xor_sync(0xffffffffu, sum, off);
        sq  += __shfl_xor_sync(0xffffffffu, sq, off);
    }
    if ((t & 31) == 0) { s_sum[t >> 5] = sum; s_sq[t >> 5] = sq; }
    __syncthreads();
    sum = 0.f; sq = 0.f;
#pragma unroll
    for (int wv = 0; wv < 8; wv++) { sum += s_sum[wv]; sq += s_sq[wv]; }

    const float mean = sum * (1.f / (float)DM);
    const float var  = sq * (1.f / (float)DM) - mean * mean;
    const float rs   = rsqrtf(var + 1e-5f);

    float4 gg = *(const float4*)(gamma + t * 4);
    float4 bb = *(const float4*)(beta + t * 4);
    float4 y = make_float4((v.x - mean) * rs * gg.x + bb.x,
                           (v.y - mean) * rs * gg.y + bb.y,
                           (v.z - mean) * rs * gg.z + bb.z,
                           (v.w - mean) * rs * gg.w + bb.w);
    *(float4*)(out + (size_t)row * DM + t * 4) = y;
    if (outh) {
        __half2* oh = (__half2*)(outh + (size_t)row * DM + t * 4);
        oh[0] = __floats2half2_rn(y.x, y.y);
        oh[1] = __floats2half2_rn(y.z, y.w);
    }
}

// ---------------------------------------------------------------------------
// SwiGLU -> half: g = silu(h1) * h2, zero where pad
// ---------------------------------------------------------------------------
__global__ __launch_bounds__(256)
void glu_kernel(const float* __restrict__ h,
                const unsigned char* __restrict__ pad,
                __half* __restrict__ g)
{
    const int idx = blockIdx.x * 256 + threadIdx.x;
    const int row = idx / (DFF / 2 / 4);
    const int c4  = idx % (DFF / 2 / 4);
    float4 a = *(const float4*)(h + (size_t)row * DFF + c4 * 4);
    float4 b = *(const float4*)(h + (size_t)row * DFF + DFF / 2 + c4 * 4);
    float4 y;
    y.x = (a.x / (1.f + __expf(-a.x))) * b.x;
    y.y = (a.y / (1.f + __expf(-a.y))) * b.y;
    y.z = (a.z / (1.f + __expf(-a.z))) * b.z;
    y.w = (a.w / (1.f + __expf(-a.w))) * b.w;
    if (pad[row]) y = make_float4(0.f, 0.f, 0.f, 0.f);
    __half2* o = (__half2*)(g + (size_t)row * (DFF / 2) + c4 * 4);
    o[0] = __floats2half2_rn(y.x, y.y);
    o[1] = __floats2half2_rn(y.z, y.w);
}

// ---------------------------------------------------------------------------
// Launch
// ---------------------------------------------------------------------------
extern "C" void kernel_launch(void* const* d_in, const int* in_sizes, int n_in,
                              void* d_out, int out_size)
{
    const float* x          = (const float*)d_in[0];
    const int*   attn_mask  = (const int*)d_in[1];
    const unsigned char* seq_mask = (const unsigned char*)d_in[2];
    const float* Wc  = (const float*)d_in[3];
    const float* bc  = (const float*)d_in[4];
    const float* Wo  = (const float*)d_in[5];
    const float* bo  = (const float*)d_in[6];
    const float* W1  = (const float*)d_in[7];
    const float* b1  = (const float*)d_in[8];
    const float* W2  = (const float*)d_in[9];
    const float* b2  = (const float*)d_in[10];
    const float* g1  = (const float*)d_in[11];
    const float* be1 = (const float*)d_in[12];
    const float* g2  = (const float*)d_in[13];
    const float* be2 = (const float*)d_in[14];
    float* out = (float*)d_out;

    float *qkv, *attnout, *x1, *h, *ffn;
    __half *ctxh, *x1h, *gluh, *xh, *wct, *wot, *w1t, *w2t;
    cudaGetSymbolAddress((void**)&qkv,     g_qkv);
    cudaGetSymbolAddress((void**)&ctxh,    g_ctxh);
    cudaGetSymbolAddress((void**)&attnout, g_attnout);
    cudaGetSymbolAddress((void**)&x1,      g_x1);
    cudaGetSymbolAddress((void**)&x1h,     g_x1h);
    cudaGetSymbolAddress((void**)&h,       g_h);
    cudaGetSymbolAddress((void**)&gluh,    g_gluh);
    cudaGetSymbolAddress((void**)&ffn,     g_ffn);
    cudaGetSymbolAddress((void**)&xh,      g_xh);
    cudaGetSymbolAddress((void**)&wct,     g_wct);
    cudaGetSymbolAddress((void**)&wot,     g_wot);
    cudaGetSymbolAddress((void**)&w1t,     g_w1t);
    cudaGetSymbolAddress((void**)&w2t,     g_w2t);

    cudaFuncSetAttribute(flash_attn_f16, cudaFuncAttributeMaxDynamicSharedMemorySize,
                         FLASH_SMEM);
    cudaFuncSetAttribute(f16_gemm_w64, cudaFuncAttributeMaxDynamicSharedMemorySize,
                         GEMM_SMEM);

    // ---- pre-pass: half conversion + weight transposes ----
    round_to_half<<<(ROWS * DM / 4 + 255) / 256, 256>>>(x, xh, ROWS * DM / 4);
    transpose_to_half<<<dim3(QKVC / 32, DM / 32),    dim3(32, 8)>>>(Wc, wct, DM, QKVC);
    transpose_to_half<<<dim3(DM / 32, DM / 32),      dim3(32, 8)>>>(Wo, wot, DM, DM);
    transpose_to_half<<<dim3(DFF / 32, DM / 32),     dim3(32, 8)>>>(W1, w1t, DM, DFF);
    transpose_to_half<<<dim3(DM / 32, (DFF/2) / 32), dim3(32, 8)>>>(W2, w2t, DFF / 2, DM);

    // 1) qkv = x @ Wc + bc
    f16_gemm_w64<<<dim3(QKVC / 128, ROWS / 128), 128, GEMM_SMEM>>>(ROWS, QKVC, DM, xh, wct, bc, qkv);

    // 2) attention -> ctx (half)
    flash_attn_f16<<<dim3(SS / 64, NKV, BB), 256, FLASH_SMEM>>>(qkv, attn_mask, ctxh);

    // 3) attn_out = ctx @ Wo + bo
    f16_gemm_w64<<<dim3(DM / 128, ROWS / 128), 128, GEMM_SMEM>>>(ROWS, DM, DM, ctxh, wot, bo, attnout);

    // 4) x1 = LN(x + attn_out)  (fp32 + half copies)
    add_ln_kernel<<<ROWS, 256>>>(x, attnout, nullptr, g1, be1, x1, x1h);

    // 5) h = x1 @ W1 + b1
    f16_gemm_w64<<<dim3(DFF / 128, ROWS / 128), 128, GEMM_SMEM>>>(ROWS, DFF, DM, x1h, w1t, b1, h);

    // 6) glu = silu(h1)*h2 (pad-zeroed, half)
    glu_kernel<<<(ROWS * (DFF / 2) / 4) / 256, 256>>>(h, seq_mask, gluh);

    // 7) ffn = glu @ W2 + b2
    f16_gemm_w64<<<dim3(DM / 128, ROWS / 128), 128, GEMM_SMEM>>>(ROWS, DM, DFF / 2, gluh, w2t, b2, ffn);

    // 8) out = LN(x1 + (pad ? 0 : ffn)), fp32
    add_ln_kernel<<<ROWS, 256>>>(x1, ffn, seq_mask, g2, be2, out, nullptr);
}

// round 12
// speedup vs baseline: 4.5106x; 1.0541x over previous
#include <cuda_runtime.h>
#include <cuda_fp16.h>
#include <cstdint>

// ---------------------------------------------------------------------------
// Problem constants (fixed by setup_inputs)
// ---------------------------------------------------------------------------
#define BB      2
#define SS      2048
#define DM      1024
#define NH      16
#define NKV     4
#define DK      64
#define DFF     4096
#define QKVC    1536          // DM + 2*NKV*DK
#define ROWS    (BB*SS)       // 4096

// ---------------------------------------------------------------------------
// Scratch (static device allocations; allowed by harness rules)
// ---------------------------------------------------------------------------
__device__ __half g_qkvh   [ROWS * QKVC];
__device__ __half g_ctxh   [ROWS * DM];
__device__ float  g_attnout[ROWS * DM];
__device__ float  g_x1     [ROWS * DM];
__device__ __half g_x1h    [ROWS * DM];
__device__ __half g_gluh   [ROWS * (DFF/2)];
__device__ float  g_ffn    [ROWS * DM];
// half operands
__device__ __half g_xh     [ROWS * DM];
__device__ __half g_wct    [QKVC * DM];          // Wc^T [n][k]
__device__ __half g_wot    [DM * DM];
__device__ __half g_w1tp   [DFF * DM];           // W1^T, columns pair-interleaved
__device__ __half g_w2t    [DM * (DFF/2)];

// ---------------------------------------------------------------------------
// helpers
// ---------------------------------------------------------------------------
__device__ __forceinline__ void ldsm4(uint32_t& r0, uint32_t& r1,
                                      uint32_t& r2, uint32_t& r3,
                                      uint32_t addr) {
    asm volatile("ldmatrix.sync.aligned.m8n8.x4.shared.b16 {%0,%1,%2,%3}, [%4];"
                 : "=r"(r0), "=r"(r1), "=r"(r2), "=r"(r3) : "r"(addr));
}

__device__ __forceinline__ void mma_f16(float* c, const uint32_t* a,
                                        uint32_t b0, uint32_t b1) {
    asm volatile(
        "mma.sync.aligned.m16n8k16.row.col.f32.f16.f16.f32 "
        "{%0,%1,%2,%3}, {%4,%5,%6,%7}, {%8,%9}, {%0,%1,%2,%3};"
        : "+f"(c[0]), "+f"(c[1]), "+f"(c[2]), "+f"(c[3])
        : "r"(a[0]), "r"(a[1]), "r"(a[2]), "r"(a[3]), "r"(b0), "r"(b1));
}

__device__ __forceinline__ void cp_async16(uint32_t smem_addr, const void* gptr) {
    asm volatile("cp.async.cg.shared.global [%0], [%1], 16;"
                 :: "r"(smem_addr), "l"(gptr));
}
#define CP_COMMIT()  asm volatile("cp.async.commit_group;")
#define CP_WAIT(n)   asm volatile("cp.async.wait_group %0;" :: "n"(n))

// ---------------------------------------------------------------------------
// Pre-pass: f32 -> f16 copy
// ---------------------------------------------------------------------------
__global__ __launch_bounds__(256)
void round_to_half(const float* __restrict__ in, __half* __restrict__ out, int n4)
{
    int i = blockIdx.x * 256 + threadIdx.x;
    if (i >= n4) return;
    float4 v = ((const float4*)in)[i];
    __half2* o = (__half2*)(out + (size_t)i * 4);
    o[0] = __floats2half2_rn(v.x, v.y);
    o[1] = __floats2half2_rn(v.z, v.w);
}

// ---------------------------------------------------------------------------
// Pre-pass: Wt[n][k] = half(W[k][n])   (W: [K][N] row-major fp32)
// ---------------------------------------------------------------------------
__global__ __launch_bounds__(256)
void transpose_to_half(const float* __restrict__ W, __half* __restrict__ Wt,
                       int K, int N)
{
    __shared__ float tile[32][33];
    const int n0 = blockIdx.x * 32;
    const int k0 = blockIdx.y * 32;
    const int tx = threadIdx.x;
    const int ty = threadIdx.y;
#pragma unroll
    for (int i = 0; i < 32; i += 8)
        tile[ty + i][tx] = W[(size_t)(k0 + ty + i) * N + n0 + tx];
    __syncthreads();
#pragma unroll
    for (int i = 0; i < 32; i += 8)
        Wt[(size_t)(n0 + ty + i) * K + k0 + tx] = __float2half_rn(tile[tx][ty + i]);
}

// Same, but destination rows pair-interleaved: raw col n -> row 2n (n<N/2)
// or 2(n-N/2)+1 (n>=N/2). Used for W1 so the GLU pair (j, j+N/2) is adjacent.
__global__ __launch_bounds__(256)
void transpose_to_half_perm(const float* __restrict__ W, __half* __restrict__ Wt,
                            int K, int N)
{
    __shared__ float tile[32][33];
    const int n0 = blockIdx.x * 32;
    const int k0 = blockIdx.y * 32;
    const int tx = threadIdx.x;
    const int ty = threadIdx.y;
#pragma unroll
    for (int i = 0; i < 32; i += 8)
        tile[ty + i][tx] = W[(size_t)(k0 + ty + i) * N + n0 + tx];
    __syncthreads();
#pragma unroll
    for (int i = 0; i < 32; i += 8) {
        const int nr = n0 + ty + i;
        const int n2 = (nr < N / 2) ? (2 * nr) : (2 * (nr - N / 2) + 1);
        Wt[(size_t)n2 * K + k0 + tx] = __float2half_rn(tile[tx][ty + i]);
    }
}

// ---------------------------------------------------------------------------
// fp16 GEMM, warp tile 64x64, templated epilogue.
// C[M,N] = A[M,K] @ Bt[N,K]^T (+ bias), fp32 accumulate.
// Block tile 128x128, BK=32 halves, 128 threads (4 warps 2x2), 3-stage cp.async.
//   EPI 0: fp32 C + bias
//   EPI 1: half C + bias
//   EPI 2: GLU — paired columns (even=h1 orig col/2, odd=h2 orig col/2+N/2);
//          out[row][col/2] = silu(h1)*h2 (half), zero where pad[row]
// ---------------------------------------------------------------------------
#define GPADH  40
#define STAGES 3
#define GEMM_SMEM (STAGES * 2 * 128 * GPADH * 2)
#define EPI_F32  0
#define EPI_HALF 1
#define EPI_GLU  2

template<int EPI>
__global__ __launch_bounds__(128, 2)
void f16_gemm_epi(int M, int N, int K,
                  const __half* __restrict__ A,
                  const __half* __restrict__ Bt,
                  const float* __restrict__ bias,
                  float* __restrict__ Cf,
                  __half* __restrict__ Ch,
                  const unsigned char* __restrict__ pad)
{
    extern __shared__ char smraw[];
    __half* As = (__half*)smraw;                       // [STAGES][128][GPADH]
    __half* Bs = As + STAGES * 128 * GPADH;            // [STAGES][128][GPADH]

    const int t    = threadIdx.x;
    const int lane = t & 31;
    const int w    = t >> 5;
    const int wm   = (w >> 1) * 64;
    const int wn   = (w & 1) * 64;
    const int bm   = blockIdx.y * 128;
    const int bn   = blockIdx.x * 128;

    const __half* Ag = A  + (size_t)(bm + t) * K;
    const __half* Bg = Bt + (size_t)(bn + t) * K;

    const uint32_t sa = (uint32_t)__cvta_generic_to_shared(As);
    const uint32_t sb = (uint32_t)__cvta_generic_to_shared(Bs);
    const uint32_t buf_stride = 128 * GPADH * 2;
    const uint32_t l_off = t * GPADH * 2;

    const int nk = K / 32;

    const int a_row   = wm + (lane & 15);
    const int a_koff  = (lane >> 4) * 16;
    const int b_row   = wn + ((lane >> 4) << 3) + (lane & 7);
    const int b_koff  = ((lane >> 3) & 1) * 16;

    float acc[4][8][4];
#pragma unroll
    for (int i = 0; i < 4; i++)
#pragma unroll
        for (int j = 0; j < 8; j++)
#pragma unroll
            for (int r = 0; r < 4; r++) acc[i][j][r] = 0.f;

#pragma unroll
    for (int s = 0; s < STAGES - 1; s++) {
        const __half* ag = Ag + s * 32;
        const __half* bg = Bg + s * 32;
#pragma unroll
        for (int c = 0; c < 4; c++) {
            cp_async16(sa + s * buf_stride + l_off + c * 16, ag + c * 8);
            cp_async16(sb + s * buf_stride + l_off + c * 16, bg + c * 8);
        }
        CP_COMMIT();
    }

    for (int kt = 0; kt < nk; kt++) {
        CP_WAIT(STAGES - 2);
        __syncthreads();

        const int nxt = kt + STAGES - 1;
        if (nxt < nk) {
            const int s = nxt % STAGES;
            const __half* ag = Ag + nxt * 32;
            const __half* bg = Bg + nxt * 32;
#pragma unroll
            for (int c = 0; c < 4; c++) {
                cp_async16(sa + s * buf_stride + l_off + c * 16, ag + c * 8);
                cp_async16(sb + s * buf_stride + l_off + c * 16, bg + c * 8);
            }
        }
        CP_COMMIT();

        const uint32_t abuf = sa + (kt % STAGES) * buf_stride;
        const uint32_t bbuf = sb + (kt % STAGES) * buf_stride;
#pragma unroll
        for (int ks = 0; ks < 2; ks++) {
            uint32_t af[4][4];
#pragma unroll
            for (int ma = 0; ma < 4; ma++) {
                uint32_t addr = abuf +
                    ((a_row + ma * 16) * GPADH + ks * 16) * 2 + a_koff;
                ldsm4(af[ma][0], af[ma][1], af[ma][2], af[ma][3], addr);
            }
            uint32_t bf[4][4];
#pragma unroll
            for (int nb = 0; nb < 4; nb++) {
                uint32_t addr = bbuf +
                    ((b_row + nb * 16) * GPADH + ks * 16) * 2 + b_koff;
                ldsm4(bf[nb][0], bf[nb][1], bf[nb][2], bf[nb][3], addr);
            }
#pragma unroll
            for (int ma = 0; ma < 4; ma++) {
#pragma unroll
                for (int nb = 0; nb < 4; nb++) {
                    mma_f16(acc[ma][nb * 2 + 0], af[ma], bf[nb][0], bf[nb][1]);
                    mma_f16(acc[ma][nb * 2 + 1], af[ma], bf[nb][2], bf[nb][3]);
                }
            }
        }
    }

    // ---- epilogue ----
#pragma unroll
    for (int ma = 0; ma < 4; ma++) {
        const int row0 = bm + wm + ma * 16 + (lane >> 2);
        bool p0 = false, p1 = false;
        if (EPI == EPI_GLU) { p0 = pad[row0] != 0; p1 = pad[row0 + 8] != 0; }
#pragma unroll
        for (int na = 0; na < 8; na++) {
            const int col = bn + wn + na * 8 + (lane & 3) * 2;
            if (EPI == EPI_F32) {
                const float b0 = bias[col];
                const float b1v = bias[col + 1];
                *(float2*)(Cf + (size_t)row0 * N + col) =
                    make_float2(acc[ma][na][0] + b0, acc[ma][na][1] + b1v);
                *(float2*)(Cf + (size_t)(row0 + 8) * N + col) =
                    make_float2(acc[ma][na][2] + b0, acc[ma][na][3] + b1v);
            } else if (EPI == EPI_HALF) {
                const float b0 = bias[col];
                const float b1v = bias[col + 1];
                *(__half2*)(Ch + (size_t)row0 * N + col) =
                    __floats2half2_rn(acc[ma][na][0] + b0, acc[ma][na][1] + b1v);
                *(__half2*)(Ch + (size_t)(row0 + 8) * N + col) =
                    __floats2half2_rn(acc[ma][na][2] + b0, acc[ma][na][3] + b1v);
            } else {
                const float b0 = bias[col >> 1];            // orig col/2
                const float b1v = bias[(col >> 1) + 2048];  // orig col/2 + DFF/2
                const float h1a = acc[ma][na][0] + b0;
                const float h2a = acc[ma][na][1] + b1v;
                const float h1b = acc[ma][na][2] + b0;
                const float h2b = acc[ma][na][3] + b1v;
                float ga = (h1a / (1.f + __expf(-h1a))) * h2a;
                float gb = (h1b / (1.f + __expf(-h1b))) * h2b;
                if (p0) ga = 0.f;
                if (p1) gb = 0.f;
                Ch[(size_t)row0 * (N >> 1) + (col >> 1)]       = __float2half_rn(ga);
                Ch[(size_t)(row0 + 8) * (N >> 1) + (col >> 1)] = __float2half_rn(gb);
            }
        }
    }
}

// ---------------------------------------------------------------------------
// Flash attention, fp16 tensor cores, 4 heads per block (one KV group).
// Input qkv is HALF. Grid: (S/64, NKV, B). Block: 256 threads (8 warps).
// ---------------------------------------------------------------------------
#define FPADH 72
#define FLASH_SMEM ((512 * FPADH + 128 * FPADH) * 2 + SS * 4)

__global__ __launch_bounds__(256)
void flash_attn_f16(const __half* __restrict__ qkv,
                    const int* __restrict__ attn_mask,
                    __half* __restrict__ ctx)
{
    extern __shared__ char smraw[];
    __half* Qs = (__half*)smraw;            // 256 x FPADH
    __half* Ps = Qs + 256 * FPADH;          // 256 x FPADH
    __half* Ks = Ps + 256 * FPADH;          // 64  x FPADH
    __half* Vt = Ks + 64 * FPADH;           // 64  x FPADH
    float*  mb = (float*)(Vt + 64 * FPADH); // SS

    const int t    = threadIdx.x;
    const int lane = t & 31;
    const int w    = t >> 5;
    const int q0   = blockIdx.x * 64;
    const int g    = blockIdx.y;
    const int b    = blockIdx.z;
    const int head = g * 4 + (w >> 1);

    const float slope = exp2f(-(float)(head + 1));

    for (int k = t; k < SS; k += 256)
        mb[k] = (attn_mask[b * SS + k] == 0) ? -1e9f : 0.f;

    // Q load (half, scaled by 1/8)
    {
        const int hl = t >> 6;
        const int qr = t & 63;
        const __half* src = qkv + (size_t)(b * SS + q0 + qr) * QKVC + (g * 4 + hl) * DK;
        __half* dst = Qs + t * FPADH;
        const __half2 sc2 = __floats2half2_rn(0.125f, 0.125f);
#pragma unroll
        for (int e = 0; e < 8; e++) {
            uint4 raw = *(const uint4*)(src + e * 8);
            __half2* p = (__half2*)&raw;
            p[0] = __hmul2(p[0], sc2);
            p[1] = __hmul2(p[1], sc2);
            p[2] = __hmul2(p[2], sc2);
            p[3] = __hmul2(p[3], sc2);
            *(uint4*)(dst + e * 8) = raw;
        }
    }
    __syncthreads();

    const uint32_t qs_base = (uint32_t)__cvta_generic_to_shared(Qs);
    const uint32_t ks_base = (uint32_t)__cvta_generic_to_shared(Ks);
    const uint32_t vt_base = (uint32_t)__cvta_generic_to_shared(Vt);
    const uint32_t ps_base = (uint32_t)__cvta_generic_to_shared(Ps);

    const int a_row  = w * 32 + (lane & 15);
    const int a_koff = (lane >> 4) * 16;
    const int b_row  = ((lane >> 4) << 3) + (lane & 7);
    const int b_koff = ((lane >> 3) & 1) * 16;

    uint32_t qf[4][2][4];
#pragma unroll
    for (int ks = 0; ks < 4; ks++)
#pragma unroll
        for (int ma = 0; ma < 2; ma++) {
            uint32_t addr = qs_base +
                ((a_row + ma * 16) * FPADH + ks * 16) * 2 + a_koff;
            ldsm4(qf[ks][ma][0], qf[ks][ma][1], qf[ks][ma][2], qf[ks][ma][3], addr);
        }

    float o[2][8][4];
#pragma unroll
    for (int ma = 0; ma < 2; ma++)
#pragma unroll
        for (int nt = 0; nt < 8; nt++)
#pragma unroll
            for (int r = 0; r < 4; r++) o[ma][nt][r] = 0.f;
    float m_[2][2] = {{-1e30f, -1e30f}, {-1e30f, -1e30f}};
    float l_[2][2] = {{0.f, 0.f}, {0.f, 0.f}};

    const float qbase = (float)(q0 + (w & 1) * 32 + (lane >> 2));
    const float qp[2][2] = {{qbase, qbase + 8.f}, {qbase + 16.f, qbase + 24.f}};

    for (int kt = 0; kt < SS / 64; kt++) {
        const int k0 = kt * 64;

        // K copy (half, no conversion) + V transpose (half)
        {
            const int kr = t >> 2;
            const int dc = (t & 3) * 16;
            const __half* srcK = qkv + (size_t)(b * SS + k0 + kr) * QKVC + DM + g * DK + dc;
            const __half* srcV = qkv + (size_t)(b * SS + k0 + kr) * QKVC + DM + NKV * DK + g * DK + dc;
            __half* dstK = Ks + kr * FPADH + dc;
            *(uint4*)(dstK)     = *(const uint4*)(srcK);
            *(uint4*)(dstK + 8) = *(const uint4*)(srcK + 8);
            uint4 rv0 = *(const uint4*)(srcV);
            uint4 rv1 = *(const uint4*)(srcV + 8);
            const __half* vv0 = (const __half*)&rv0;
            const __half* vv1 = (const __half*)&rv1;
#pragma unroll
            for (int d = 0; d < 8; d++) {
                Vt[(dc + d) * FPADH + kr]     = vv0[d];
                Vt[(dc + 8 + d) * FPADH + kr] = vv1[d];
            }
        }
        __syncthreads();

        // scores: S = Q @ K^T (m32 x n64 x k64)
        float s[2][8][4];
#pragma unroll
        for (int ma = 0; ma < 2; ma++)
#pragma unroll
            for (int nt = 0; nt < 8; nt++)
#pragma unroll
                for (int r = 0; r < 4; r++) s[ma][nt][r] = 0.f;

#pragma unroll
        for (int ks = 0; ks < 4; ks++) {
            uint32_t bf[4][4];
#pragma unroll
            for (int nb = 0; nb < 4; nb++) {
                uint32_t addr = ks_base +
                    ((b_row + nb * 16) * FPADH + ks * 16) * 2 + b_koff;
                ldsm4(bf[nb][0], bf[nb][1], bf[nb][2], bf[nb][3], addr);
            }
#pragma unroll
            for (int nb = 0; nb < 4; nb++)
#pragma unroll
                for (int ma = 0; ma < 2; ma++) {
                    mma_f16(s[ma][nb * 2 + 0], qf[ks][ma], bf[nb][0], bf[nb][1]);
                    mma_f16(s[ma][nb * 2 + 1], qf[ks][ma], bf[nb][2], bf[nb][3]);
                }
        }

        // ALiBi + mask
#pragma unroll
        for (int nt = 0; nt < 8; nt++) {
            const int col = k0 + nt * 8 + (lane & 3) * 2;
            float2 c2 = *(const float2*)(mb + col);
            const float c0 = (float)col, c1 = (float)(col + 1);
#pragma unroll
            for (int ma = 0; ma < 2; ma++) {
                s[ma][nt][0] += slope * (qp[ma][0] - c0) + c2.x;
                s[ma][nt][1] += slope * (qp[ma][0] - c1) + c2.y;
                s[ma][nt][2] += slope * (qp[ma][1] - c0) + c2.x;
                s[ma][nt][3] += slope * (qp[ma][1] - c1) + c2.y;
            }
        }

        // online softmax
#pragma unroll
        for (int ma = 0; ma < 2; ma++) {
            float mx0 = -1e30f, mx1 = -1e30f;
#pragma unroll
            for (int nt = 0; nt < 8; nt++) {
                mx0 = fmaxf(mx0, fmaxf(s[ma][nt][0], s[ma][nt][1]));
                mx1 = fmaxf(mx1, fmaxf(s[ma][nt][2], s[ma][nt][3]));
            }
            mx0 = fmaxf(mx0, __shfl_xor_sync(0xffffffffu, mx0, 1));
            mx0 = fmaxf(mx0, __shfl_xor_sync(0xffffffffu, mx0, 2));
            mx1 = fmaxf(mx1, __shfl_xor_sync(0xffffffffu, mx1, 1));
            mx1 = fmaxf(mx1, __shfl_xor_sync(0xffffffffu, mx1, 2));

            const float mn0 = fmaxf(m_[ma][0], mx0);
            const float mn1 = fmaxf(m_[ma][1], mx1);
            const float al0 = __expf(m_[ma][0] - mn0);
            const float al1 = __expf(m_[ma][1] - mn1);
            m_[ma][0] = mn0; m_[ma][1] = mn1;

            float rs0 = 0.f, rs1 = 0.f;
#pragma unroll
            for (int nt = 0; nt < 8; nt++) {
                s[ma][nt][0] = __expf(s[ma][nt][0] - mn0);
                s[ma][nt][1] = __expf(s[ma][nt][1] - mn0);
                s[ma][nt][2] = __expf(s[ma][nt][2] - mn1);
                s[ma][nt][3] = __expf(s[ma][nt][3] - mn1);
                rs0 += s[ma][nt][0] + s[ma][nt][1];
                rs1 += s[ma][nt][2] + s[ma][nt][3];
            }
            rs0 += __shfl_xor_sync(0xffffffffu, rs0, 1);
            rs0 += __shfl_xor_sync(0xffffffffu, rs0, 2);
            rs1 += __shfl_xor_sync(0xffffffffu, rs1, 1);
            rs1 += __shfl_xor_sync(0xffffffffu, rs1, 2);
            l_[ma][0] = l_[ma][0] * al0 + rs0;
            l_[ma][1] = l_[ma][1] * al1 + rs1;

#pragma unroll
            for (int nt = 0; nt < 8; nt++) {
                o[ma][nt][0] *= al0; o[ma][nt][1] *= al0;
                o[ma][nt][2] *= al1; o[ma][nt][3] *= al1;
            }
        }

        // P -> half smem (per-warp-private rows)
        {
            const int pr = w * 32 + (lane >> 2);
            const int pc = (lane & 3) * 2;
#pragma unroll
            for (int ma = 0; ma < 2; ma++)
#pragma unroll
                for (int nt = 0; nt < 8; nt++) {
                    *(__half2*)(Ps + (pr + ma * 16) * FPADH + nt * 8 + pc) =
                        __floats2half2_rn(s[ma][nt][0], s[ma][nt][1]);
                    *(__half2*)(Ps + (pr + ma * 16 + 8) * FPADH + nt * 8 + pc) =
                        __floats2half2_rn(s[ma][nt][2], s[ma][nt][3]);
                }
        }
        __syncwarp();

        // O += P @ V
#pragma unroll
        for (int ks = 0; ks < 4; ks++) {
            uint32_t pf[2][4];
#pragma unroll
            for (int ma = 0; ma < 2; ma++) {
                uint32_t addr = ps_base +
                    ((a_row + ma * 16) * FPADH + ks * 16) * 2 + a_koff;
                ldsm4(pf[ma][0], pf[ma][1], pf[ma][2], pf[ma][3], addr);
            }
            uint32_t vf[4][4];
#pragma unroll
            for (int nb = 0; nb < 4; nb++) {
                uint32_t addr = vt_base +
                    ((b_row + nb * 16) * FPADH + ks * 16) * 2 + b_koff;
                ldsm4(vf[nb][0], vf[nb][1], vf[nb][2], vf[nb][3], addr);
            }
#pragma unroll
            for (int nb = 0; nb < 4; nb++)
#pragma unroll
                for (int ma = 0; ma < 2; ma++) {
                    mma_f16(o[ma][nb * 2 + 0], pf[ma], vf[nb][0], vf[nb][1]);
                    mma_f16(o[ma][nb * 2 + 1], pf[ma], vf[nb][2], vf[nb][3]);
                }
        }
        __syncthreads();
    }

    // normalize + write ctx as half
#pragma unroll
    for (int ma = 0; ma < 2; ma++) {
        const float inv0 = 1.f / l_[ma][0];
        const float inv1 = 1.f / l_[ma][1];
        const int gr = b * SS + q0 + (w & 1) * 32 + ma * 16 + (lane >> 2);
#pragma unroll
        for (int nt = 0; nt < 8; nt++) {
            const int col = head * DK + nt * 8 + (lane & 3) * 2;
            *(__half2*)(ctx + (size_t)gr * DM + col) =
                __floats2half2_rn(o[ma][nt][0] * inv0, o[ma][nt][1] * inv0);
            *(__half2*)(ctx + (size_t)(gr + 8) * DM + col) =
                __floats2half2_rn(o[ma][nt][2] * inv1, o[ma][nt][3] * inv1);
        }
    }
}

// ---------------------------------------------------------------------------
// y = LayerNorm(a + (pad ? 0 : r)) * gamma + beta; optional half copy
// ---------------------------------------------------------------------------
__global__ __launch_bounds__(256)
void add_ln_kernel(const float* __restrict__ a,
                   const float* __restrict__ r,
                   const unsigned char* __restrict__ pad,
                   const float* __restrict__ gamma,
                   const float* __restrict__ beta,
                   float* __restrict__ out,
                   __half* __restrict__ outh)
{
    __shared__ float s_sum[8], s_sq[8];
    const int row = blockIdx.x;
    const int t = threadIdx.x;

    float4 va = *(const float4*)(a + (size_t)row * DM + t * 4);
    float4 vr = *(const float4*)(r + (size_t)row * DM + t * 4);
    if (pad && pad[row]) vr = make_float4(0.f, 0.f, 0.f, 0.f);
    float4 v = make_float4(va.x + vr.x, va.y + vr.y, va.z + vr.z, va.w + vr.w);

    float sum = v.x + v.y + v.z + v.w;
    float sq  = v.x * v.x + v.y * v.y + v.z * v.z + v.w * v.w;
#pragma unroll
    for (int off = 16; off > 0; off >>= 1) {
        sum += __shfl_xor_sync(0xffffffffu, sum, off);
        sq  += __shfl_xor_sync(0xffffffffu, sq, off);
    }
    if ((t & 31) == 0) { s_sum[t >> 5] = sum; s_sq[t >> 5] = sq; }
    __syncthreads();
    sum = 0.f; sq = 0.f;
#pragma unroll
    for (int wv = 0; wv < 8; wv++) { sum += s_sum[wv]; sq += s_sq[wv]; }

    const float mean = sum * (1.f / (float)DM);
    const float var  = sq * (1.f / (float)DM) - mean * mean;
    const float rs   = rsqrtf(var + 1e-5f);

    float4 gg = *(const float4*)(gamma + t * 4);
    float4 bb = *(const float4*)(beta + t * 4);
    float4 y = make_float4((v.x - mean) * rs * gg.x + bb.x,
                           (v.y - mean) * rs * gg.y + bb.y,
                           (v.z - mean) * rs * gg.z + bb.z,
                           (v.w - mean) * rs * gg.w + bb.w);
    *(float4*)(out + (size_t)row * DM + t * 4) = y;
    if (outh) {
        __half2* oh = (__half2*)(outh + (size_t)row * DM + t * 4);
        oh[0] = __floats2half2_rn(y.x, y.y);
        oh[1] = __floats2half2_rn(y.z, y.w);
    }
}

// ---------------------------------------------------------------------------
// Launch
// ---------------------------------------------------------------------------
extern "C" void kernel_launch(void* const* d_in, const int* in_sizes, int n_in,
                              void* d_out, int out_size)
{
    const float* x          = (const float*)d_in[0];
    const int*   attn_mask  = (const int*)d_in[1];
    const unsigned char* seq_mask = (const unsigned char*)d_in[2];
    const float* Wc  = (const float*)d_in[3];
    const float* bc  = (const float*)d_in[4];
    const float* Wo  = (const float*)d_in[5];
    const float* bo  = (const float*)d_in[6];
    const float* W1  = (const float*)d_in[7];
    const float* b1  = (const float*)d_in[8];
    const float* W2  = (const float*)d_in[9];
    const float* b2  = (const float*)d_in[10];
    const float* g1  = (const float*)d_in[11];
    const float* be1 = (const float*)d_in[12];
    const float* g2  = (const float*)d_in[13];
    const float* be2 = (const float*)d_in[14];
    float* out = (float*)d_out;

    float *attnout, *x1, *ffn;
    __half *qkvh, *ctxh, *x1h, *gluh, *xh, *wct, *wot, *w1tp, *w2t;
    cudaGetSymbolAddress((void**)&qkvh,    g_qkvh);
    cudaGetSymbolAddress((void**)&ctxh,    g_ctxh);
    cudaGetSymbolAddress((void**)&attnout, g_attnout);
    cudaGetSymbolAddress((void**)&x1,      g_x1);
    cudaGetSymbolAddress((void**)&x1h,     g_x1h);
    cudaGetSymbolAddress((void**)&gluh,    g_gluh);
    cudaGetSymbolAddress((void**)&ffn,     g_ffn);
    cudaGetSymbolAddress((void**)&xh,      g_xh);
    cudaGetSymbolAddress((void**)&wct,     g_wct);
    cudaGetSymbolAddress((void**)&wot,     g_wot);
    cudaGetSymbolAddress((void**)&w1tp,    g_w1tp);
    cudaGetSymbolAddress((void**)&w2t,     g_w2t);

    cudaFuncSetAttribute(flash_attn_f16, cudaFuncAttributeMaxDynamicSharedMemorySize,
                         FLASH_SMEM);
    cudaFuncSetAttribute(f16_gemm_epi<EPI_F32>,  cudaFuncAttributeMaxDynamicSharedMemorySize, GEMM_SMEM);
    cudaFuncSetAttribute(f16_gemm_epi<EPI_HALF>, cudaFuncAttributeMaxDynamicSharedMemorySize, GEMM_SMEM);
    cudaFuncSetAttribute(f16_gemm_epi<EPI_GLU>,  cudaFuncAttributeMaxDynamicSharedMemorySize, GEMM_SMEM);

    // ---- pre-pass ----
    round_to_half<<<(ROWS * DM / 4 + 255) / 256, 256>>>(x, xh, ROWS * DM / 4);
    transpose_to_half<<<dim3(QKVC / 32, DM / 32),    dim3(32, 8)>>>(Wc, wct, DM, QKVC);
    transpose_to_half<<<dim3(DM / 32, DM / 32),      dim3(32, 8)>>>(Wo, wot, DM, DM);
    transpose_to_half_perm<<<dim3(DFF / 32, DM / 32), dim3(32, 8)>>>(W1, w1tp, DM, DFF);
    transpose_to_half<<<dim3(DM / 32, (DFF/2) / 32), dim3(32, 8)>>>(W2, w2t, DFF / 2, DM);

    // 1) qkv = x @ Wc + bc   (half output)
    f16_gemm_epi<EPI_HALF><<<dim3(QKVC / 128, ROWS / 128), 128, GEMM_SMEM>>>(
        ROWS, QKVC, DM, xh, wct, bc, nullptr, qkvh, nullptr);

    // 2) attention -> ctx (half in, half out)
    flash_attn_f16<<<dim3(SS / 64, NKV, BB), 256, FLASH_SMEM>>>(qkvh, attn_mask, ctxh);

    // 3) attn_out = ctx @ Wo + bo   (fp32)
    f16_gemm_epi<EPI_F32><<<dim3(DM / 128, ROWS / 128), 128, GEMM_SMEM>>>(
        ROWS, DM, DM, ctxh, wot, bo, attnout, nullptr, nullptr);

    // 4) x1 = LN(x + attn_out)  (fp32 + half)
    add_ln_kernel<<<ROWS, 256>>>(x, attnout, nullptr, g1, be1, x1, x1h);

    // 5+6) glu = SwiGLU(x1 @ W1 + b1) fused in epilogue (half out, pad-zeroed)
    f16_gemm_epi<EPI_GLU><<<dim3(DFF / 128, ROWS / 128), 128, GEMM_SMEM>>>(
        ROWS, DFF, DM, x1h, w1tp, b1, nullptr, gluh, seq_mask);

    // 7) ffn = glu @ W2 + b2   (fp32)
    f16_gemm_epi<EPI_F32><<<dim3(DM / 128, ROWS / 128), 128, GEMM_SMEM>>>(
        ROWS, DM, DFF / 2, gluh, w2t, b2, ffn, nullptr, nullptr);

    // 8) out = LN(x1 + (pad ? 0 : ffn)), fp32
    add_ln_kernel<<<ROWS, 256>>>(x1, ffn, seq_mask, g2, be2, out, nullptr);
}

// round 14
// speedup vs baseline: 4.6254x; 1.0255x over previous
#include <cuda_runtime.h>
#include <cuda_fp16.h>
#include <cstdint>

// ---------------------------------------------------------------------------
// Problem constants (fixed by setup_inputs)
// ---------------------------------------------------------------------------
#define BB      2
#define SS      2048
#define DM      1024
#define NH      16
#define NKV     4
#define DK      64
#define DFF     4096
#define QKVC    1536          // DM + 2*NKV*DK
#define ROWS    (BB*SS)       // 4096

// ---------------------------------------------------------------------------
// Scratch (static device allocations; allowed by harness rules)
// ---------------------------------------------------------------------------
__device__ __half g_qkvh   [ROWS * QKVC];
__device__ __half g_ctxh   [ROWS * DM];
__device__ float  g_attnout[ROWS * DM];
__device__ float  g_x1     [ROWS * DM];
__device__ __half g_x1h    [ROWS * DM];
__device__ __half g_gluh   [ROWS * (DFF/2)];
__device__ float  g_ffn    [ROWS * DM];
// half operands
__device__ __half g_xh     [ROWS * DM];
__device__ __half g_wct    [QKVC * DM];          // Wc^T [n][k]
__device__ __half g_wot    [DM * DM];
__device__ __half g_w1tp   [DFF * DM];           // W1^T, columns pair-interleaved
__device__ __half g_w2t    [DM * (DFF/2)];

// ---------------------------------------------------------------------------
// helpers
// ---------------------------------------------------------------------------
__device__ __forceinline__ void ldsm4(uint32_t& r0, uint32_t& r1,
                                      uint32_t& r2, uint32_t& r3,
                                      uint32_t addr) {
    asm volatile("ldmatrix.sync.aligned.m8n8.x4.shared.b16 {%0,%1,%2,%3}, [%4];"
                 : "=r"(r0), "=r"(r1), "=r"(r2), "=r"(r3) : "r"(addr));
}

__device__ __forceinline__ void mma_f16(float* c, const uint32_t* a,
                                        uint32_t b0, uint32_t b1) {
    asm volatile(
        "mma.sync.aligned.m16n8k16.row.col.f32.f16.f16.f32 "
        "{%0,%1,%2,%3}, {%4,%5,%6,%7}, {%8,%9}, {%0,%1,%2,%3};"
        : "+f"(c[0]), "+f"(c[1]), "+f"(c[2]), "+f"(c[3])
        : "r"(a[0]), "r"(a[1]), "r"(a[2]), "r"(a[3]), "r"(b0), "r"(b1));
}

__device__ __forceinline__ void cp_async16(uint32_t smem_addr, const void* gptr) {
    asm volatile("cp.async.cg.shared.global [%0], [%1], 16;"
                 :: "r"(smem_addr), "l"(gptr));
}
#define CP_COMMIT()  asm volatile("cp.async.commit_group;")
#define CP_WAIT(n)   asm volatile("cp.async.wait_group %0;" :: "n"(n))

// ---------------------------------------------------------------------------
// Pre-pass: f32 -> f16 copy
// ---------------------------------------------------------------------------
__global__ __launch_bounds__(256)
void round_to_half(const float* __restrict__ in, __half* __restrict__ out, int n4)
{
    int i = blockIdx.x * 256 + threadIdx.x;
    if (i >= n4) return;
    float4 v = ((const float4*)in)[i];
    __half2* o = (__half2*)(out + (size_t)i * 4);
    o[0] = __floats2half2_rn(v.x, v.y);
    o[1] = __floats2half2_rn(v.z, v.w);
}

// ---------------------------------------------------------------------------
// Pre-pass: Wt[n][k] = half(W[k][n])   (W: [K][N] row-major fp32)
// ---------------------------------------------------------------------------
__global__ __launch_bounds__(256)
void transpose_to_half(const float* __restrict__ W, __half* __restrict__ Wt,
                       int K, int N)
{
    __shared__ float tile[32][33];
    const int n0 = blockIdx.x * 32;
    const int k0 = blockIdx.y * 32;
    const int tx = threadIdx.x;
    const int ty = threadIdx.y;
#pragma unroll
    for (int i = 0; i < 32; i += 8)
        tile[ty + i][tx] = W[(size_t)(k0 + ty + i) * N + n0 + tx];
    __syncthreads();
#pragma unroll
    for (int i = 0; i < 32; i += 8)
        Wt[(size_t)(n0 + ty + i) * K + k0 + tx] = __float2half_rn(tile[tx][ty + i]);
}

// Pair-interleaved destination rows: raw col n -> 2n (n<N/2) else 2(n-N/2)+1.
__global__ __launch_bounds__(256)
void transpose_to_half_perm(const float* __restrict__ W, __half* __restrict__ Wt,
                            int K, int N)
{
    __shared__ float tile[32][33];
    const int n0 = blockIdx.x * 32;
    const int k0 = blockIdx.y * 32;
    const int tx = threadIdx.x;
    const int ty = threadIdx.y;
#pragma unroll
    for (int i = 0; i < 32; i += 8)
        tile[ty + i][tx] = W[(size_t)(k0 + ty + i) * N + n0 + tx];
    __syncthreads();
#pragma unroll
    for (int i = 0; i < 32; i += 8) {
        const int nr = n0 + ty + i;
        const int n2 = (nr < N / 2) ? (2 * nr) : (2 * (nr - N / 2) + 1);
        Wt[(size_t)n2 * K + k0 + tx] = __float2half_rn(tile[tx][ty + i]);
    }
}

// ---------------------------------------------------------------------------
// fp16 GEMM, warp tile 64x64, templated epilogue.
// C[M,N] = A[M,K] @ Bt[N,K]^T (+ bias), fp32 accumulate.
// Block tile 128x128, BK=32 halves, 128 threads (4 warps 2x2), 4-stage cp.async.
// ---------------------------------------------------------------------------
#define GPADH  40
#define STAGES 4
#define GEMM_SMEM (STAGES * 2 * 128 * GPADH * 2)
#define EPI_F32  0
#define EPI_HALF 1
#define EPI_GLU  2

template<int EPI>
__global__ __launch_bounds__(128, 2)
void f16_gemm_epi(int M, int N, int K,
                  const __half* __restrict__ A,
                  const __half* __restrict__ Bt,
                  const float* __restrict__ bias,
                  float* __restrict__ Cf,
                  __half* __restrict__ Ch,
                  const unsigned char* __restrict__ pad)
{
    extern __shared__ char smraw[];
    __half* As = (__half*)smraw;                       // [STAGES][128][GPADH]
    __half* Bs = As + STAGES * 128 * GPADH;            // [STAGES][128][GPADH]

    const int t    = threadIdx.x;
    const int lane = t & 31;
    const int w    = t >> 5;
    const int wm   = (w >> 1) * 64;
    const int wn   = (w & 1) * 64;
    const int bm   = blockIdx.y * 128;
    const int bn   = blockIdx.x * 128;

    const __half* Ag = A  + (size_t)(bm + t) * K;
    const __half* Bg = Bt + (size_t)(bn + t) * K;

    const uint32_t sa = (uint32_t)__cvta_generic_to_shared(As);
    const uint32_t sb = (uint32_t)__cvta_generic_to_shared(Bs);
    const uint32_t buf_stride = 128 * GPADH * 2;
    const uint32_t l_off = t * GPADH * 2;

    const int nk = K / 32;

    const int a_row   = wm + (lane & 15);
    const int a_koff  = (lane >> 4) * 16;
    const int b_row   = wn + ((lane >> 4) << 3) + (lane & 7);
    const int b_koff  = ((lane >> 3) & 1) * 16;

    float acc[4][8][4];
#pragma unroll
    for (int i = 0; i < 4; i++)
#pragma unroll
        for (int j = 0; j < 8; j++)
#pragma unroll
            for (int r = 0; r < 4; r++) acc[i][j][r] = 0.f;

#pragma unroll
    for (int s = 0; s < STAGES - 1; s++) {
        const __half* ag = Ag + s * 32;
        const __half* bg = Bg + s * 32;
#pragma unroll
        for (int c = 0; c < 4; c++) {
            cp_async16(sa + s * buf_stride + l_off + c * 16, ag + c * 8);
            cp_async16(sb + s * buf_stride + l_off + c * 16, bg + c * 8);
        }
        CP_COMMIT();
    }

    for (int kt = 0; kt < nk; kt++) {
        CP_WAIT(STAGES - 2);
        __syncthreads();

        const int nxt = kt + STAGES - 1;
        if (nxt < nk) {
            const int s = nxt % STAGES;
            const __half* ag = Ag + nxt * 32;
            const __half* bg = Bg + nxt * 32;
#pragma unroll
            for (int c = 0; c < 4; c++) {
                cp_async16(sa + s * buf_stride + l_off + c * 16, ag + c * 8);
                cp_async16(sb + s * buf_stride + l_off + c * 16, bg + c * 8);
            }
        }
        CP_COMMIT();

        const uint32_t abuf = sa + (kt % STAGES) * buf_stride;
        const uint32_t bbuf = sb + (kt % STAGES) * buf_stride;
#pragma unroll
        for (int ks = 0; ks < 2; ks++) {
            uint32_t af[4][4];
#pragma unroll
            for (int ma = 0; ma < 4; ma++) {
                uint32_t addr = abuf +
                    ((a_row + ma * 16) * GPADH + ks * 16) * 2 + a_koff;
                ldsm4(af[ma][0], af[ma][1], af[ma][2], af[ma][3], addr);
            }
            uint32_t bf[4][4];
#pragma unroll
            for (int nb = 0; nb < 4; nb++) {
                uint32_t addr = bbuf +
                    ((b_row + nb * 16) * GPADH + ks * 16) * 2 + b_koff;
                ldsm4(bf[nb][0], bf[nb][1], bf[nb][2], bf[nb][3], addr);
            }
#pragma unroll
            for (int ma = 0; ma < 4; ma++) {
#pragma unroll
                for (int nb = 0; nb < 4; nb++) {
                    mma_f16(acc[ma][nb * 2 + 0], af[ma], bf[nb][0], bf[nb][1]);
                    mma_f16(acc[ma][nb * 2 + 1], af[ma], bf[nb][2], bf[nb][3]);
                }
            }
        }
    }

    // ---- epilogue ----
#pragma unroll
    for (int ma = 0; ma < 4; ma++) {
        const int row0 = bm + wm + ma * 16 + (lane >> 2);
        bool p0 = false, p1 = false;
        if (EPI == EPI_GLU) { p0 = pad[row0] != 0; p1 = pad[row0 + 8] != 0; }
#pragma unroll
        for (int na = 0; na < 8; na++) {
            const int col = bn + wn + na * 8 + (lane & 3) * 2;
            if (EPI == EPI_F32) {
                const float b0 = bias[col];
                const float b1v = bias[col + 1];
                *(float2*)(Cf + (size_t)row0 * N + col) =
                    make_float2(acc[ma][na][0] + b0, acc[ma][na][1] + b1v);
                *(float2*)(Cf + (size_t)(row0 + 8) * N + col) =
                    make_float2(acc[ma][na][2] + b0, acc[ma][na][3] + b1v);
            } else if (EPI == EPI_HALF) {
                const float b0 = bias[col];
                const float b1v = bias[col + 1];
                *(__half2*)(Ch + (size_t)row0 * N + col) =
                    __floats2half2_rn(acc[ma][na][0] + b0, acc[ma][na][1] + b1v);
                *(__half2*)(Ch + (size_t)(row0 + 8) * N + col) =
                    __floats2half2_rn(acc[ma][na][2] + b0, acc[ma][na][3] + b1v);
            } else {
                const float b0 = bias[col >> 1];            // orig col/2
                const float b1v = bias[(col >> 1) + 2048];  // orig col/2 + DFF/2
                const float h1a = acc[ma][na][0] + b0;
                const float h2a = acc[ma][na][1] + b1v;
                const float h1b = acc[ma][na][2] + b0;
                const float h2b = acc[ma][na][3] + b1v;
                float ga = (h1a / (1.f + __expf(-h1a))) * h2a;
                float gb = (h1b / (1.f + __expf(-h1b))) * h2b;
                if (p0) ga = 0.f;
                if (p1) gb = 0.f;
                Ch[(size_t)row0 * (N >> 1) + (col >> 1)]       = __float2half_rn(ga);
                Ch[(size_t)(row0 + 8) * (N >> 1) + (col >> 1)] = __float2half_rn(gb);
            }
        }
    }
}

// ---------------------------------------------------------------------------
// Flash attention, fp16 tensor cores, 4 heads per block (one KV group).
// Input qkv is HALF. Grid: (S/64, NKV, B). Block: 256 threads (8 warps).
// K tile: cp.async double-buffered; V tile: register-prefetched, scattered.
// ---------------------------------------------------------------------------
#define FPADH 72
#define KBUF_HALVES (64 * FPADH)
#define FLASH_SMEM (((512 + 3 * 64) * FPADH) * 2 + SS * 4)

__global__ __launch_bounds__(256)
void flash_attn_f16(const __half* __restrict__ qkv,
                    const int* __restrict__ attn_mask,
                    __half* __restrict__ ctx)
{
    extern __shared__ char smraw[];
    __half* Qs  = (__half*)smraw;             // 256 x FPADH
    __half* Ps  = Qs + 256 * FPADH;           // 256 x FPADH
    __half* Ks0 = Ps + 256 * FPADH;           // 64 x FPADH (buffer 0)
    __half* Ks1 = Ks0 + KBUF_HALVES;          // 64 x FPADH (buffer 1)
    __half* Vt  = Ks1 + KBUF_HALVES;          // 64 x FPADH
    float*  mb  = (float*)(Vt + 64 * FPADH);  // SS

    const int t    = threadIdx.x;
    const int lane = t & 31;
    const int w    = t >> 5;
    const int q0   = blockIdx.x * 64;
    const int g    = blockIdx.y;
    const int b    = blockIdx.z;
    const int head = g * 4 + (w >> 1);

    const float slope = exp2f(-(float)(head + 1));

    for (int k = t; k < SS; k += 256)
        mb[k] = (attn_mask[b * SS + k] == 0) ? -1e9f : 0.f;

    // Q load (half, scaled by 1/8)
    {
        const int hl = t >> 6;
        const int qr = t & 63;
        const __half* src = qkv + (size_t)(b * SS + q0 + qr) * QKVC + (g * 4 + hl) * DK;
        __half* dst = Qs + t * FPADH;
        const __half2 sc2 = __floats2half2_rn(0.125f, 0.125f);
#pragma unroll
        for (int e = 0; e < 8; e++) {
            uint4 raw = *(const uint4*)(src + e * 8);
            __half2* p = (__half2*)&raw;
            p[0] = __hmul2(p[0], sc2);
            p[1] = __hmul2(p[1], sc2);
            p[2] = __hmul2(p[2], sc2);
            p[3] = __hmul2(p[3], sc2);
            *(uint4*)(dst + e * 8) = raw;
        }
    }

    const uint32_t qs_base = (uint32_t)__cvta_generic_to_shared(Qs);
    const uint32_t vt_base = (uint32_t)__cvta_generic_to_shared(Vt);
    const uint32_t ps_base = (uint32_t)__cvta_generic_to_shared(Ps);
    const uint32_t ks_b0   = (uint32_t)__cvta_generic_to_shared(Ks0);
    const uint32_t ks_b1   = (uint32_t)__cvta_generic_to_shared(Ks1);

    // loader mapping for K/V tiles: thread -> row kr, 16-half column chunk dc
    const int kr = t >> 2;
    const int dc = (t & 3) * 16;

    // prologue: K tile 0 via cp.async, V tile 0 into registers
    {
        const __half* srcK = qkv + (size_t)(b * SS + kr) * QKVC + DM + g * DK + dc;
        uint32_t d = ks_b0 + (kr * FPADH + dc) * 2;
        cp_async16(d, srcK);
        cp_async16(d + 16, srcK + 8);
        CP_COMMIT();
    }
    uint4 rv0, rv1;
    {
        const __half* srcV = qkv + (size_t)(b * SS + kr) * QKVC + DM + NKV * DK + g * DK + dc;
        rv0 = *(const uint4*)(srcV);
        rv1 = *(const uint4*)(srcV + 8);
    }
    __syncthreads();   // Qs visible to all

    const int a_row  = w * 32 + (lane & 15);
    const int a_koff = (lane >> 4) * 16;
    const int b_row  = ((lane >> 4) << 3) + (lane & 7);
    const int b_koff = ((lane >> 3) & 1) * 16;

    uint32_t qf[4][2][4];
#pragma unroll
    for (int ks = 0; ks < 4; ks++)
#pragma unroll
        for (int ma = 0; ma < 2; ma++) {
            uint32_t addr = qs_base +
                ((a_row + ma * 16) * FPADH + ks * 16) * 2 + a_koff;
            ldsm4(qf[ks][ma][0], qf[ks][ma][1], qf[ks][ma][2], qf[ks][ma][3], addr);
        }

    float o[2][8][4];
#pragma unroll
    for (int ma = 0; ma < 2; ma++)
#pragma unroll
        for (int nt = 0; nt < 8; nt++)
#pragma unroll
            for (int r = 0; r < 4; r++) o[ma][nt][r] = 0.f;
    float m_[2][2] = {{-1e30f, -1e30f}, {-1e30f, -1e30f}};
    float l_[2][2] = {{0.f, 0.f}, {0.f, 0.f}};

    const float qbase = (float)(q0 + (w & 1) * 32 + (lane >> 2));
    const float qp[2][2] = {{qbase, qbase + 8.f}, {qbase + 16.f, qbase + 24.f}};

    const int NT = SS / 64;
    for (int kt = 0; kt < NT; kt++) {
        const int k0 = kt * 64;

        // K(kt) cp.async must have landed; scatter V(kt) registers into Vt
        CP_WAIT(0);
        {
            const __half* vv0 = (const __half*)&rv0;
            const __half* vv1 = (const __half*)&rv1;
#pragma unroll
            for (int d = 0; d < 8; d++) {
                Vt[(dc + d) * FPADH + kr]     = vv0[d];
                Vt[(dc + 8 + d) * FPADH + kr] = vv1[d];
            }
        }
        __syncthreads();

        // prefetch next tile: K via cp.async (other buffer), V into registers
        if (kt + 1 < NT) {
            const __half* srcK = qkv + (size_t)(b * SS + k0 + 64 + kr) * QKVC + DM + g * DK + dc;
            uint32_t d = (((kt + 1) & 1) ? ks_b1 : ks_b0) + (kr * FPADH + dc) * 2;
            cp_async16(d, srcK);
            cp_async16(d + 16, srcK + 8);
            CP_COMMIT();
            const __half* srcV = qkv + (size_t)(b * SS + k0 + 64 + kr) * QKVC + DM + NKV * DK + g * DK + dc;
            rv0 = *(const uint4*)(srcV);
            rv1 = *(const uint4*)(srcV + 8);
        }

        const uint32_t ks_base = (kt & 1) ? ks_b1 : ks_b0;

        // scores: S = Q @ K^T (m32 x n64 x k64)
        float s[2][8][4];
#pragma unroll
        for (int ma = 0; ma < 2; ma++)
#pragma unroll
            for (int nt = 0; nt < 8; nt++)
#pragma unroll
                for (int r = 0; r < 4; r++) s[ma][nt][r] = 0.f;

#pragma unroll
        for (int ks = 0; ks < 4; ks++) {
            uint32_t bf[4][4];
#pragma unroll
            for (int nb = 0; nb < 4; nb++) {
                uint32_t addr = ks_base +
                    ((b_row + nb * 16) * FPADH + ks * 16) * 2 + b_koff;
                ldsm4(bf[nb][0], bf[nb][1], bf[nb][2], bf[nb][3], addr);
            }
#pragma unroll
            for (int nb = 0; nb < 4; nb++)
#pragma unroll
                for (int ma = 0; ma < 2; ma++) {
                    mma_f16(s[ma][nb * 2 + 0], qf[ks][ma], bf[nb][0], bf[nb][1]);
                    mma_f16(s[ma][nb * 2 + 1], qf[ks][ma], bf[nb][2], bf[nb][3]);
                }
        }

        // ALiBi + mask
#pragma unroll
        for (int nt = 0; nt < 8; nt++) {
            const int col = k0 + nt * 8 + (lane & 3) * 2;
            float2 c2 = *(const float2*)(mb + col);
            const float c0 = (float)col, c1 = (float)(col + 1);
#pragma unroll
            for (int ma = 0; ma < 2; ma++) {
                s[ma][nt][0] += slope * (qp[ma][0] - c0) + c2.x;
                s[ma][nt][1] += slope * (qp[ma][0] - c1) + c2.y;
                s[ma][nt][2] += slope * (qp[ma][1] - c0) + c2.x;
                s[ma][nt][3] += slope * (qp[ma][1] - c1) + c2.y;
            }
        }

        // online softmax
#pragma unroll
        for (int ma = 0; ma < 2; ma++) {
            float mx0 = -1e30f, mx1 = -1e30f;
#pragma unroll
            for (int nt = 0; nt < 8; nt++) {
                mx0 = fmaxf(mx0, fmaxf(s[ma][nt][0], s[ma][nt][1]));
                mx1 = fmaxf(mx1, fmaxf(s[ma][nt][2], s[ma][nt][3]));
            }
            mx0 = fmaxf(mx0, __shfl_xor_sync(0xffffffffu, mx0, 1));
            mx0 = fmaxf(mx0, __shfl_xor_sync(0xffffffffu, mx0, 2));
            mx1 = fmaxf(mx1, __shfl_xor_sync(0xffffffffu, mx1, 1));
            mx1 = fmaxf(mx1, __shfl_xor_sync(0xffffffffu, mx1, 2));

            const float mn0 = fmaxf(m_[ma][0], mx0);
            const float mn1 = fmaxf(m_[ma][1], mx1);
            const float al0 = __expf(m_[ma][0] - mn0);
            const float al1 = __expf(m_[ma][1] - mn1);
            m_[ma][0] = mn0; m_[ma][1] = mn1;

            float rs0 = 0.f, rs1 = 0.f;
#pragma unroll
            for (int nt = 0; nt < 8; nt++) {
                s[ma][nt][0] = __expf(s[ma][nt][0] - mn0);
                s[ma][nt][1] = __expf(s[ma][nt][1] - mn0);
                s[ma][nt][2] = __expf(s[ma][nt][2] - mn1);
                s[ma][nt][3] = __expf(s[ma][nt][3] - mn1);
                rs0 += s[ma][nt][0] + s[ma][nt][1];
                rs1 += s[ma][nt][2] + s[ma][nt][3];
            }
            rs0 += __shfl_xor_sync(0xffffffffu, rs0, 1);
            rs0 += __shfl_xor_sync(0xffffffffu, rs0, 2);
            rs1 += __shfl_xor_sync(0xffffffffu, rs1, 1);
            rs1 += __shfl_xor_sync(0xffffffffu, rs1, 2);
            l_[ma][0] = l_[ma][0] * al0 + rs0;
            l_[ma][1] = l_[ma][1] * al1 + rs1;

#pragma unroll
            for (int nt = 0; nt < 8; nt++) {
                o[ma][nt][0] *= al0; o[ma][nt][1] *= al0;
                o[ma][nt][2] *= al1; o[ma][nt][3] *= al1;
            }
        }

        // P -> half smem (per-warp-private rows)
        {
            const int pr = w * 32 + (lane >> 2);
            const int pc = (lane & 3) * 2;
#pragma unroll
            for (int ma = 0; ma < 2; ma++)
#pragma unroll
                for (int nt = 0; nt < 8; nt++) {
                    *(__half2*)(Ps + (pr + ma * 16) * FPADH + nt * 8 + pc) =
                        __floats2half2_rn(s[ma][nt][0], s[ma][nt][1]);
                    *(__half2*)(Ps + (pr + ma * 16 + 8) * FPADH + nt * 8 + pc) =
                        __floats2half2_rn(s[ma][nt][2], s[ma][nt][3]);
                }
        }
        __syncwarp();

        // O += P @ V
#pragma unroll
        for (int ks = 0; ks < 4; ks++) {
            uint32_t pf[2][4];
#pragma unroll
            for (int ma = 0; ma < 2; ma++) {
                uint32_t addr = ps_base +
                    ((a_row + ma * 16) * FPADH + ks * 16) * 2 + a_koff;
                ldsm4(pf[ma][0], pf[ma][1], pf[ma][2], pf[ma][3], addr);
            }
            uint32_t vf[4][4];
#pragma unroll
            for (int nb = 0; nb < 4; nb++) {
                uint32_t addr = vt_base +
                    ((b_row + nb * 16) * FPADH + ks * 16) * 2 + b_koff;
                ldsm4(vf[nb][0], vf[nb][1], vf[nb][2], vf[nb][3], addr);
            }
#pragma unroll
            for (int nb = 0; nb < 4; nb++)
#pragma unroll
                for (int ma = 0; ma < 2; ma++) {
                    mma_f16(o[ma][nb * 2 + 0], pf[ma], vf[nb][0], vf[nb][1]);
                    mma_f16(o[ma][nb * 2 + 1], pf[ma], vf[nb][2], vf[nb][3]);
                }
        }
        __syncthreads();   // Vt / Ks[buf] reads complete before next overwrite
    }

    // normalize + write ctx as half
#pragma unroll
    for (int ma = 0; ma < 2; ma++) {
        const float inv0 = 1.f / l_[ma][0];
        const float inv1 = 1.f / l_[ma][1];
        const int gr = b * SS + q0 + (w & 1) * 32 + ma * 16 + (lane >> 2);
#pragma unroll
        for (int nt = 0; nt < 8; nt++) {
            const int col = head * DK + nt * 8 + (lane & 3) * 2;
            *(__half2*)(ctx + (size_t)gr * DM + col) =
                __floats2half2_rn(o[ma][nt][0] * inv0, o[ma][nt][1] * inv0);
            *(__half2*)(ctx + (size_t)(gr + 8) * DM + col) =
                __floats2half2_rn(o[ma][nt][2] * inv1, o[ma][nt][3] * inv1);
        }
    }
}

// ---------------------------------------------------------------------------
// y = LayerNorm(a + (pad ? 0 : r)) * gamma + beta; optional half copy
// ---------------------------------------------------------------------------
__global__ __launch_bounds__(256)
void add_ln_kernel(const float* __restrict__ a,
                   const float* __restrict__ r,
                   const unsigned char* __restrict__ pad,
                   const float* __restrict__ gamma,
                   const float* __restrict__ beta,
                   float* __restrict__ out,
                   __half* __restrict__ outh)
{
    __shared__ float s_sum[8], s_sq[8];
    const int row = blockIdx.x;
    const int t = threadIdx.x;

    float4 va = *(const float4*)(a + (size_t)row * DM + t * 4);
    float4 vr = *(const float4*)(r + (size_t)row * DM + t * 4);
    if (pad && pad[row]) vr = make_float4(0.f, 0.f, 0.f, 0.f);
    float4 v = make_float4(va.x + vr.x, va.y + vr.y, va.z + vr.z, va.w + vr.w);

    float sum = v.x + v.y + v.z + v.w;
    float sq  = v.x * v.x + v.y * v.y + v.z * v.z + v.w * v.w;
#pragma unroll
    for (int off = 16; off > 0; off >>= 1) {
        sum += __shfl_xor_sync(0xffffffffu, sum, off);
        sq  += __shfl_xor_sync(0xffffffffu, sq, off);
    }
    if ((t & 31) == 0) { s_sum[t >> 5] = sum; s_sq[t >> 5] = sq; }
    __syncthreads();
    sum = 0.f; sq = 0.f;
#pragma unroll
    for (int wv = 0; wv < 8; wv++) { sum += s_sum[wv]; sq += s_sq[wv]; }

    const float mean = sum * (1.f / (float)DM);
    const float var  = sq * (1.f / (float)DM) - mean * mean;
    const float rs   = rsqrtf(var + 1e-5f);

    float4 gg = *(const float4*)(gamma + t * 4);
    float4 bb = *(const float4*)(beta + t * 4);
    float4 y = make_float4((v.x - mean) * rs * gg.x + bb.x,
                           (v.y - mean) * rs * gg.y + bb.y,
                           (v.z - mean) * rs * gg.z + bb.z,
                           (v.w - mean) * rs * gg.w + bb.w);
    *(float4*)(out + (size_t)row * DM + t * 4) = y;
    if (outh) {
        __half2* oh = (__half2*)(outh + (size_t)row * DM + t * 4);
        oh[0] = __floats2half2_rn(y.x, y.y);
        oh[1] = __floats2half2_rn(y.z, y.w);
    }
}

// ---------------------------------------------------------------------------
// Launch
// ---------------------------------------------------------------------------
extern "C" void kernel_launch(void* const* d_in, const int* in_sizes, int n_in,
                              void* d_out, int out_size)
{
    const float* x          = (const float*)d_in[0];
    const int*   attn_mask  = (const int*)d_in[1];
    const unsigned char* seq_mask = (const unsigned char*)d_in[2];
    const float* Wc  = (const float*)d_in[3];
    const float* bc  = (const float*)d_in[4];
    const float* Wo  = (const float*)d_in[5];
    const float* bo  = (const float*)d_in[6];
    const float* W1  = (const float*)d_in[7];
    const float* b1  = (const float*)d_in[8];
    const float* W2  = (const float*)d_in[9];
    const float* b2  = (const float*)d_in[10];
    const float* g1  = (const float*)d_in[11];
    const float* be1 = (const float*)d_in[12];
    const float* g2  = (const float*)d_in[13];
    const float* be2 = (const float*)d_in[14];
    float* out = (float*)d_out;

    float *attnout, *x1, *ffn;
    __half *qkvh, *ctxh, *x1h, *gluh, *xh, *wct, *wot, *w1tp, *w2t;
    cudaGetSymbolAddress((void**)&qkvh,    g_qkvh);
    cudaGetSymbolAddress((void**)&ctxh,    g_ctxh);
    cudaGetSymbolAddress((void**)&attnout, g_attnout);
    cudaGetSymbolAddress((void**)&x1,      g_x1);
    cudaGetSymbolAddress((void**)&x1h,     g_x1h);
    cudaGetSymbolAddress((void**)&gluh,    g_gluh);
    cudaGetSymbolAddress((void**)&ffn,     g_ffn);
    cudaGetSymbolAddress((void**)&xh,      g_xh);
    cudaGetSymbolAddress((void**)&wct,     g_wct);
    cudaGetSymbolAddress((void**)&wot,     g_wot);
    cudaGetSymbolAddress((void**)&w1tp,    g_w1tp);
    cudaGetSymbolAddress((void**)&w2t,     g_w2t);

    cudaFuncSetAttribute(flash_attn_f16, cudaFuncAttributeMaxDynamicSharedMemorySize,
                         FLASH_SMEM);
    cudaFuncSetAttribute(f16_gemm_epi<EPI_F32>,  cudaFuncAttributeMaxDynamicSharedMemorySize, GEMM_SMEM);
    cudaFuncSetAttribute(f16_gemm_epi<EPI_HALF>, cudaFuncAttributeMaxDynamicSharedMemorySize, GEMM_SMEM);
    cudaFuncSetAttribute(f16_gemm_epi<EPI_GLU>,  cudaFuncAttributeMaxDynamicSharedMemorySize, GEMM_SMEM);

    // ---- pre-pass ----
    round_to_half<<<(ROWS * DM / 4 + 255) / 256, 256>>>(x, xh, ROWS * DM / 4);
    transpose_to_half<<<dim3(QKVC / 32, DM / 32),    dim3(32, 8)>>>(Wc, wct, DM, QKVC);
    transpose_to_half<<<dim3(DM / 32, DM / 32),      dim3(32, 8)>>>(Wo, wot, DM, DM);
    transpose_to_half_perm<<<dim3(DFF / 32, DM / 32), dim3(32, 8)>>>(W1, w1tp, DM, DFF);
    transpose_to_half<<<dim3(DM / 32, (DFF/2) / 32), dim3(32, 8)>>>(W2, w2t, DFF / 2, DM);

    // 1) qkv = x @ Wc + bc   (half output)
    f16_gemm_epi<EPI_HALF><<<dim3(QKVC / 128, ROWS / 128), 128, GEMM_SMEM>>>(
        ROWS, QKVC, DM, xh, wct, bc, nullptr, qkvh, nullptr);

    // 2) attention -> ctx (half in, half out)
    flash_attn_f16<<<dim3(SS / 64, NKV, BB), 256, FLASH_SMEM>>>(qkvh, attn_mask, ctxh);

    // 3) attn_out = ctx @ Wo + bo   (fp32)
    f16_gemm_epi<EPI_F32><<<dim3(DM / 128, ROWS / 128), 128, GEMM_SMEM>>>(
        ROWS, DM, DM, ctxh, wot, bo, attnout, nullptr, nullptr);

    // 4) x1 = LN(x + attn_out)  (fp32 + half)
    add_ln_kernel<<<ROWS, 256>>>(x, attnout, nullptr, g1, be1, x1, x1h);

    // 5+6) glu = SwiGLU(x1 @ W1 + b1) fused in epilogue (half out, pad-zeroed)
    f16_gemm_epi<EPI_GLU><<<dim3(DFF / 128, ROWS / 128), 128, GEMM_SMEM>>>(
        ROWS, DFF, DM, x1h, w1tp, b1, nullptr, gluh, seq_mask);

    // 7) ffn = glu @ W2 + b2   (fp32)
    f16_gemm_epi<EPI_F32><<<dim3(DM / 128, ROWS / 128), 128, GEMM_SMEM>>>(
        ROWS, DM, DFF / 2, gluh, w2t, b2, ffn, nullptr, nullptr);

    // 8) out = LN(x1 + (pad ? 0 : ffn)), fp32
    add_ln_kernel<<<ROWS, 256>>>(x1, ffn, seq_mask, g2, be2, out, nullptr);
}

// round 17
// speedup vs baseline: 4.7688x; 1.0310x over previous
#include <cuda_runtime.h>
#include <cuda_fp16.h>
#include <cstdint>

// ---------------------------------------------------------------------------
// Problem constants (fixed by setup_inputs)
// ---------------------------------------------------------------------------
#define BB      2
#define SS      2048
#define DM      1024
#define NH      16
#define NKV     4
#define DK      64
#define DFF     4096
#define QKVC    1536          // DM + 2*NKV*DK
#define ROWS    (BB*SS)       // 4096

// ---------------------------------------------------------------------------
// Scratch (static device allocations; allowed by harness rules)
// ---------------------------------------------------------------------------
__device__ __half g_qkvh   [ROWS * QKVC];
__device__ __half g_ctxh   [ROWS * DM];
__device__ float  g_attnout[ROWS * DM];
__device__ float  g_x1     [ROWS * DM];
__device__ __half g_x1h    [ROWS * DM];
__device__ __half g_gluh   [ROWS * (DFF/2)];
__device__ float  g_ffn    [ROWS * DM];
// half operands
__device__ __half g_xh     [ROWS * DM];
__device__ __half g_wct    [QKVC * DM];          // Wc^T [n][k]
__device__ __half g_wot    [DM * DM];
__device__ __half g_w1tp   [DFF * DM];           // W1^T, columns pair-interleaved
__device__ __half g_w2t    [DM * (DFF/2)];

// ---------------------------------------------------------------------------
// helpers
// ---------------------------------------------------------------------------
__device__ __forceinline__ void ldsm4(uint32_t& r0, uint32_t& r1,
                                      uint32_t& r2, uint32_t& r3,
                                      uint32_t addr) {
    asm volatile("ldmatrix.sync.aligned.m8n8.x4.shared.b16 {%0,%1,%2,%3}, [%4];"
                 : "=r"(r0), "=r"(r1), "=r"(r2), "=r"(r3) : "r"(addr));
}

__device__ __forceinline__ void mma_f16(float* c, const uint32_t* a,
                                        uint32_t b0, uint32_t b1) {
    asm volatile(
        "mma.sync.aligned.m16n8k16.row.col.f32.f16.f16.f32 "
        "{%0,%1,%2,%3}, {%4,%5,%6,%7}, {%8,%9}, {%0,%1,%2,%3};"
        : "+f"(c[0]), "+f"(c[1]), "+f"(c[2]), "+f"(c[3])
        : "r"(a[0]), "r"(a[1]), "r"(a[2]), "r"(a[3]), "r"(b0), "r"(b1));
}

__device__ __forceinline__ void cp_async16(uint32_t smem_addr, const void* gptr) {
    asm volatile("cp.async.cg.shared.global [%0], [%1], 16;"
                 :: "r"(smem_addr), "l"(gptr));
}
#define CP_COMMIT()  asm volatile("cp.async.commit_group;")
#define CP_WAIT(n)   asm volatile("cp.async.wait_group %0;" :: "n"(n))

__device__ __forceinline__ float ex2(float x) {
    float r;
    asm("ex2.approx.f32 %0, %1;" : "=f"(r) : "f"(x));
    return r;
}

__device__ __forceinline__ uint32_t pack_h2(float a, float b) {
    __half2 h = __floats2half2_rn(a, b);
    return *(uint32_t*)&h;
}

// ---------------------------------------------------------------------------
// Pre-pass: f32 -> f16 copy
// ---------------------------------------------------------------------------
__global__ __launch_bounds__(256)
void round_to_half(const float* __restrict__ in, __half* __restrict__ out, int n4)
{
    int i = blockIdx.x * 256 + threadIdx.x;
    if (i >= n4) return;
    float4 v = ((const float4*)in)[i];
    __half2* o = (__half2*)(out + (size_t)i * 4);
    o[0] = __floats2half2_rn(v.x, v.y);
    o[1] = __floats2half2_rn(v.z, v.w);
}

// ---------------------------------------------------------------------------
// Pre-pass: Wt[n][k] = half(W[k][n])   (W: [K][N] row-major fp32)
// ---------------------------------------------------------------------------
__global__ __launch_bounds__(256)
void transpose_to_half(const float* __restrict__ W, __half* __restrict__ Wt,
                       int K, int N)
{
    __shared__ float tile[32][33];
    const int n0 = blockIdx.x * 32;
    const int k0 = blockIdx.y * 32;
    const int tx = threadIdx.x;
    const int ty = threadIdx.y;
#pragma unroll
    for (int i = 0; i < 32; i += 8)
        tile[ty + i][tx] = W[(size_t)(k0 + ty + i) * N + n0 + tx];
    __syncthreads();
#pragma unroll
    for (int i = 0; i < 32; i += 8)
        Wt[(size_t)(n0 + ty + i) * K + k0 + tx] = __float2half_rn(tile[tx][ty + i]);
}

// Pair-interleaved destination rows: raw col n -> 2n (n<N/2) else 2(n-N/2)+1.
__global__ __launch_bounds__(256)
void transpose_to_half_perm(const float* __restrict__ W, __half* __restrict__ Wt,
                            int K, int N)
{
    __shared__ float tile[32][33];
    const int n0 = blockIdx.x * 32;
    const int k0 = blockIdx.y * 32;
    const int tx = threadIdx.x;
    const int ty = threadIdx.y;
#pragma unroll
    for (int i = 0; i < 32; i += 8)
        tile[ty + i][tx] = W[(size_t)(k0 + ty + i) * N + n0 + tx];
    __syncthreads();
#pragma unroll
    for (int i = 0; i < 32; i += 8) {
        const int nr = n0 + ty + i;
        const int n2 = (nr < N / 2) ? (2 * nr) : (2 * (nr - N / 2) + 1);
        Wt[(size_t)n2 * K + k0 + tx] = __float2half_rn(tile[tx][ty + i]);
    }
}

// ---------------------------------------------------------------------------
// fp16 GEMM, warp tile 64x64, templated epilogue.
// C[M,N] = A[M,K] @ Bt[N,K]^T (+ bias), fp32 accumulate.
// Block tile 128x128, BK=32 halves, 128 threads (4 warps 2x2), 4-stage cp.async.
// ---------------------------------------------------------------------------
#define GPADH  40
#define STAGES 4
#define GEMM_SMEM (STAGES * 2 * 128 * GPADH * 2)
#define EPI_F32  0
#define EPI_HALF 1
#define EPI_GLU  2

template<int EPI>
__global__ __launch_bounds__(128, 2)
void f16_gemm_epi(int M, int N, int K,
                  const __half* __restrict__ A,
                  const __half* __restrict__ Bt,
                  const float* __restrict__ bias,
                  float* __restrict__ Cf,
                  __half* __restrict__ Ch,
                  const unsigned char* __restrict__ pad)
{
    extern __shared__ char smraw[];
    __half* As = (__half*)smraw;                       // [STAGES][128][GPADH]
    __half* Bs = As + STAGES * 128 * GPADH;            // [STAGES][128][GPADH]

    const int t    = threadIdx.x;
    const int lane = t & 31;
    const int w    = t >> 5;
    const int wm   = (w >> 1) * 64;
    const int wn   = (w & 1) * 64;
    const int bm   = blockIdx.y * 128;
    const int bn   = blockIdx.x * 128;

    const __half* Ag = A  + (size_t)(bm + t) * K;
    const __half* Bg = Bt + (size_t)(bn + t) * K;

    const uint32_t sa = (uint32_t)__cvta_generic_to_shared(As);
    const uint32_t sb = (uint32_t)__cvta_generic_to_shared(Bs);
    const uint32_t buf_stride = 128 * GPADH * 2;
    const uint32_t l_off = t * GPADH * 2;

    const int nk = K / 32;

    const int a_row   = wm + (lane & 15);
    const int a_koff  = (lane >> 4) * 16;
    const int b_row   = wn + ((lane >> 4) << 3) + (lane & 7);
    const int b_koff  = ((lane >> 3) & 1) * 16;

    float acc[4][8][4];
#pragma unroll
    for (int i = 0; i < 4; i++)
#pragma unroll
        for (int j = 0; j < 8; j++)
#pragma unroll
            for (int r = 0; r < 4; r++) acc[i][j][r] = 0.f;

#pragma unroll
    for (int s = 0; s < STAGES - 1; s++) {
        const __half* ag = Ag + s * 32;
        const __half* bg = Bg + s * 32;
#pragma unroll
        for (int c = 0; c < 4; c++) {
            cp_async16(sa + s * buf_stride + l_off + c * 16, ag + c * 8);
            cp_async16(sb + s * buf_stride + l_off + c * 16, bg + c * 8);
        }
        CP_COMMIT();
    }

    for (int kt = 0; kt < nk; kt++) {
        CP_WAIT(STAGES - 2);
        __syncthreads();

        const int nxt = kt + STAGES - 1;
        if (nxt < nk) {
            const int s = nxt % STAGES;
            const __half* ag = Ag + nxt * 32;
            const __half* bg = Bg + nxt * 32;
#pragma unroll
            for (int c = 0; c < 4; c++) {
                cp_async16(sa + s * buf_stride + l_off + c * 16, ag + c * 8);
                cp_async16(sb + s * buf_stride + l_off + c * 16, bg + c * 8);
            }
        }
        CP_COMMIT();

        const uint32_t abuf = sa + (kt % STAGES) * buf_stride;
        const uint32_t bbuf = sb + (kt % STAGES) * buf_stride;
#pragma unroll
        for (int ks = 0; ks < 2; ks++) {
            uint32_t af[4][4];
#pragma unroll
            for (int ma = 0; ma < 4; ma++) {
                uint32_t addr = abuf +
                    ((a_row + ma * 16) * GPADH + ks * 16) * 2 + a_koff;
                ldsm4(af[ma][0], af[ma][1], af[ma][2], af[ma][3], addr);
            }
            uint32_t bf[4][4];
#pragma unroll
            for (int nb = 0; nb < 4; nb++) {
                uint32_t addr = bbuf +
                    ((b_row + nb * 16) * GPADH + ks * 16) * 2 + b_koff;
                ldsm4(bf[nb][0], bf[nb][1], bf[nb][2], bf[nb][3], addr);
            }
#pragma unroll
            for (int ma = 0; ma < 4; ma++) {
#pragma unroll
                for (int nb = 0; nb < 4; nb++) {
                    mma_f16(acc[ma][nb * 2 + 0], af[ma], bf[nb][0], bf[nb][1]);
                    mma_f16(acc[ma][nb * 2 + 1], af[ma], bf[nb][2], bf[nb][3]);
                }
            }
        }
    }

    // ---- epilogue ----
#pragma unroll
    for (int ma = 0; ma < 4; ma++) {
        const int row0 = bm + wm + ma * 16 + (lane >> 2);
        bool p0 = false, p1 = false;
        if (EPI == EPI_GLU) { p0 = pad[row0] != 0; p1 = pad[row0 + 8] != 0; }
#pragma unroll
        for (int na = 0; na < 8; na++) {
            const int col = bn + wn + na * 8 + (lane & 3) * 2;
            if (EPI == EPI_F32) {
                const float b0 = bias[col];
                const float b1v = bias[col + 1];
                *(float2*)(Cf + (size_t)row0 * N + col) =
                    make_float2(acc[ma][na][0] + b0, acc[ma][na][1] + b1v);
                *(float2*)(Cf + (size_t)(row0 + 8) * N + col) =
                    make_float2(acc[ma][na][2] + b0, acc[ma][na][3] + b1v);
            } else if (EPI == EPI_HALF) {
                const float b0 = bias[col];
                const float b1v = bias[col + 1];
                *(__half2*)(Ch + (size_t)row0 * N + col) =
                    __floats2half2_rn(acc[ma][na][0] + b0, acc[ma][na][1] + b1v);
                *(__half2*)(Ch + (size_t)(row0 + 8) * N + col) =
                    __floats2half2_rn(acc[ma][na][2] + b0, acc[ma][na][3] + b1v);
            } else {
                const float b0 = bias[col >> 1];            // orig col/2
                const float b1v = bias[(col >> 1) + 2048];  // orig col/2 + DFF/2
                const float h1a = acc[ma][na][0] + b0;
                const float h2a = acc[ma][na][1] + b1v;
                const float h1b = acc[ma][na][2] + b0;
                const float h2b = acc[ma][na][3] + b1v;
                float ga = (h1a / (1.f + __expf(-h1a))) * h2a;
                float gb = (h1b / (1.f + __expf(-h1b))) * h2b;
                if (p0) ga = 0.f;
                if (p1) gb = 0.f;
                Ch[(size_t)row0 * (N >> 1) + (col >> 1)]       = __float2half_rn(ga);
                Ch[(size_t)(row0 + 8) * (N >> 1) + (col >> 1)] = __float2half_rn(gb);
            }
        }
    }
}

// ---------------------------------------------------------------------------
// Flash attention, fp16 tensor cores, 4 heads per block (one KV group).
// Base-2 softmax (log2e folded into Q scale / slope / mask bias).
// P never touches smem: score accumulators are repacked to half2 and used
// directly as the PV mma A-fragments (FA2 layout identity).
// Grid: (S/64, NKV, B). Block: 256 threads (8 warps). Warp m-tile 32.
// ---------------------------------------------------------------------------
#define FPADH 72
#define KBUF_HALVES (64 * FPADH)
#define FLASH_SMEM (((256 + 3 * 64) * FPADH) * 2 + SS * 4)
#define LOG2E 1.44269504f

__global__ __launch_bounds__(256)
void flash_attn_f16(const __half* __restrict__ qkv,
                    const int* __restrict__ attn_mask,
                    __half* __restrict__ ctx)
{
    extern __shared__ char smraw[];
    __half* Qs  = (__half*)smraw;             // 256 x FPADH
    __half* Ks0 = Qs + 256 * FPADH;           // 64 x FPADH (buffer 0)
    __half* Ks1 = Ks0 + KBUF_HALVES;          // 64 x FPADH (buffer 1)
    __half* Vt  = Ks1 + KBUF_HALVES;          // 64 x FPADH
    float*  mb  = (float*)(Vt + 64 * FPADH);  // SS

    const int t    = threadIdx.x;
    const int lane = t & 31;
    const int w    = t >> 5;
    const int q0   = blockIdx.x * 64;
    const int g    = blockIdx.y;
    const int b    = blockIdx.z;
    const int head = g * 4 + (w >> 1);

    const float slope2 = exp2f(-(float)(head + 1)) * LOG2E;

    // mask bias already in base-2 domain
    for (int k = t; k < SS; k += 256)
        mb[k] = (attn_mask[b * SS + k] == 0) ? -1.5e9f : 0.f;

    // Q load (half, scaled by log2e/8)
    {
        const int hl = t >> 6;
        const int qr = t & 63;
        const __half* src = qkv + (size_t)(b * SS + q0 + qr) * QKVC + (g * 4 + hl) * DK;
        __half* dst = Qs + t * FPADH;
        const __half2 sc2 = __floats2half2_rn(0.125f * LOG2E, 0.125f * LOG2E);
#pragma unroll
        for (int e = 0; e < 8; e++) {
            uint4 raw = *(const uint4*)(src + e * 8);
            __half2* p = (__half2*)&raw;
            p[0] = __hmul2(p[0], sc2);
            p[1] = __hmul2(p[1], sc2);
            p[2] = __hmul2(p[2], sc2);
            p[3] = __hmul2(p[3], sc2);
            *(uint4*)(dst + e * 8) = raw;
        }
    }

    const uint32_t qs_base = (uint32_t)__cvta_generic_to_shared(Qs);
    const uint32_t vt_base = (uint32_t)__cvta_generic_to_shared(Vt);
    const uint32_t ks_b0   = (uint32_t)__cvta_generic_to_shared(Ks0);
    const uint32_t ks_b1   = (uint32_t)__cvta_generic_to_shared(Ks1);

    // loader mapping for K/V tiles: thread -> row kr, 16-half column chunk dc
    const int kr = t >> 2;
    const int dc = (t & 3) * 16;

    // prologue: K tile 0 via cp.async, V tile 0 into registers
    {
        const __half* srcK = qkv + (size_t)(b * SS + kr) * QKVC + DM + g * DK + dc;
        uint32_t d = ks_b0 + (kr * FPADH + dc) * 2;
        cp_async16(d, srcK);
        cp_async16(d + 16, srcK + 8);
        CP_COMMIT();
    }
    uint4 rv0, rv1;
    {
        const __half* srcV = qkv + (size_t)(b * SS + kr) * QKVC + DM + NKV * DK + g * DK + dc;
        rv0 = *(const uint4*)(srcV);
        rv1 = *(const uint4*)(srcV + 8);
    }
    __syncthreads();   // Qs visible to all

    const int a_row  = w * 32 + (lane & 15);
    const int a_koff = (lane >> 4) * 16;
    const int b_row  = ((lane >> 4) << 3) + (lane & 7);
    const int b_koff = ((lane >> 3) & 1) * 16;

    uint32_t qf[4][2][4];
#pragma unroll
    for (int ks = 0; ks < 4; ks++)
#pragma unroll
        for (int ma = 0; ma < 2; ma++) {
            uint32_t addr = qs_base +
                ((a_row + ma * 16) * FPADH + ks * 16) * 2 + a_koff;
            ldsm4(qf[ks][ma][0], qf[ks][ma][1], qf[ks][ma][2], qf[ks][ma][3], addr);
        }

    float o[2][8][4];
#pragma unroll
    for (int ma = 0; ma < 2; ma++)
#pragma unroll
        for (int nt = 0; nt < 8; nt++)
#pragma unroll
            for (int r = 0; r < 4; r++) o[ma][nt][r] = 0.f;
    float m_[2][2] = {{-1e30f, -1e30f}, {-1e30f, -1e30f}};
    float l_[2][2] = {{0.f, 0.f}, {0.f, 0.f}};

    const float qbase = (float)(q0 + (w & 1) * 32 + (lane >> 2));
    const float qp[2][2] = {{qbase, qbase + 8.f}, {qbase + 16.f, qbase + 24.f}};

    const int NT = SS / 64;
    for (int kt = 0; kt < NT; kt++) {
        const int k0 = kt * 64;

        // K(kt) cp.async must have landed; scatter V(kt) registers into Vt
        CP_WAIT(0);
        {
            const __half* vv0 = (const __half*)&rv0;
            const __half* vv1 = (const __half*)&rv1;
#pragma unroll
            for (int d = 0; d < 8; d++) {
                Vt[(dc + d) * FPADH + kr]     = vv0[d];
                Vt[(dc + 8 + d) * FPADH + kr] = vv1[d];
            }
        }
        __syncthreads();

        // prefetch next tile: K via cp.async (other buffer), V into registers
        if (kt + 1 < NT) {
            const __half* srcK = qkv + (size_t)(b * SS + k0 + 64 + kr) * QKVC + DM + g * DK + dc;
            uint32_t d = (((kt + 1) & 1) ? ks_b1 : ks_b0) + (kr * FPADH + dc) * 2;
            cp_async16(d, srcK);
            cp_async16(d + 16, srcK + 8);
            CP_COMMIT();
            const __half* srcV = qkv + (size_t)(b * SS + k0 + 64 + kr) * QKVC + DM + NKV * DK + g * DK + dc;
            rv0 = *(const uint4*)(srcV);
            rv1 = *(const uint4*)(srcV + 8);
        }

        const uint32_t ks_base = (kt & 1) ? ks_b1 : ks_b0;

        // scores: S = Q @ K^T (m32 x n64 x k64), base-2 domain
        float s[2][8][4];
#pragma unroll
        for (int ma = 0; ma < 2; ma++)
#pragma unroll
            for (int nt = 0; nt < 8; nt++)
#pragma unroll
                for (int r = 0; r < 4; r++) s[ma][nt][r] = 0.f;

#pragma unroll
        for (int ks = 0; ks < 4; ks++) {
            uint32_t bf[4][4];
#pragma unroll
            for (int nb = 0; nb < 4; nb++) {
                uint32_t addr = ks_base +
                    ((b_row + nb * 16) * FPADH + ks * 16) * 2 + b_koff;
                ldsm4(bf[nb][0], bf[nb][1], bf[nb][2], bf[nb][3], addr);
            }
#pragma unroll
            for (int nb = 0; nb < 4; nb++)
#pragma unroll
                for (int ma = 0; ma < 2; ma++) {
                    mma_f16(s[ma][nb * 2 + 0], qf[ks][ma], bf[nb][0], bf[nb][1]);
                    mma_f16(s[ma][nb * 2 + 1], qf[ks][ma], bf[nb][2], bf[nb][3]);
                }
        }

        // ALiBi + mask (base-2)
#pragma unroll
        for (int nt = 0; nt < 8; nt++) {
            const int col = k0 + nt * 8 + (lane & 3) * 2;
            float2 c2 = *(const float2*)(mb + col);
            const float c0 = (float)col, c1 = (float)(col + 1);
#pragma unroll
            for (int ma = 0; ma < 2; ma++) {
                s[ma][nt][0] += slope2 * (qp[ma][0] - c0) + c2.x;
                s[ma][nt][1] += slope2 * (qp[ma][0] - c1) + c2.y;
                s[ma][nt][2] += slope2 * (qp[ma][1] - c0) + c2.x;
                s[ma][nt][3] += slope2 * (qp[ma][1] - c1) + c2.y;
            }
        }

        // online softmax (base-2) + direct P-fragment packing
        uint32_t ph[2][8][2];
#pragma unroll
        for (int ma = 0; ma < 2; ma++) {
            float mx0 = -1e30f, mx1 = -1e30f;
#pragma unroll
            for (int nt = 0; nt < 8; nt++) {
                mx0 = fmaxf(mx0, fmaxf(s[ma][nt][0], s[ma][nt][1]));
                mx1 = fmaxf(mx1, fmaxf(s[ma][nt][2], s[ma][nt][3]));
            }
            mx0 = fmaxf(mx0, __shfl_xor_sync(0xffffffffu, mx0, 1));
            mx0 = fmaxf(mx0, __shfl_xor_sync(0xffffffffu, mx0, 2));
            mx1 = fmaxf(mx1, __shfl_xor_sync(0xffffffffu, mx1, 1));
            mx1 = fmaxf(mx1, __shfl_xor_sync(0xffffffffu, mx1, 2));

            const float mn0 = fmaxf(m_[ma][0], mx0);
            const float mn1 = fmaxf(m_[ma][1], mx1);
            const float al0 = ex2(m_[ma][0] - mn0);
            const float al1 = ex2(m_[ma][1] - mn1);
            m_[ma][0] = mn0; m_[ma][1] = mn1;

            float rs0 = 0.f, rs1 = 0.f;
#pragma unroll
            for (int nt = 0; nt < 8; nt++) {
                const float e0 = ex2(s[ma][nt][0] - mn0);
                const float e1 = ex2(s[ma][nt][1] - mn0);
                const float e2 = ex2(s[ma][nt][2] - mn1);
                const float e3 = ex2(s[ma][nt][3] - mn1);
                rs0 += e0 + e1;
                rs1 += e2 + e3;
                ph[ma][nt][0] = pack_h2(e0, e1);
                ph[ma][nt][1] = pack_h2(e2, e3);
            }
            rs0 += __shfl_xor_sync(0xffffffffu, rs0, 1);
            rs0 += __shfl_xor_sync(0xffffffffu, rs0, 2);
            rs1 += __shfl_xor_sync(0xffffffffu, rs1, 1);
            rs1 += __shfl_xor_sync(0xffffffffu, rs1, 2);
            l_[ma][0] = l_[ma][0] * al0 + rs0;
            l_[ma][1] = l_[ma][1] * al1 + rs1;

#pragma unroll
            for (int nt = 0; nt < 8; nt++) {
                o[ma][nt][0] *= al0; o[ma][nt][1] *= al0;
                o[ma][nt][2] *= al1; o[ma][nt][3] *= al1;
            }
        }

        // O += P @ V — P fragments come straight from ph (no smem round-trip)
#pragma unroll
        for (int ks = 0; ks < 4; ks++) {
            uint32_t vf[4][4];
#pragma unroll
            for (int nb = 0; nb < 4; nb++) {
                uint32_t addr = vt_base +
                    ((b_row + nb * 16) * FPADH + ks * 16) * 2 + b_koff;
                ldsm4(vf[nb][0], vf[nb][1], vf[nb][2], vf[nb][3], addr);
            }
#pragma unroll
            for (int ma = 0; ma < 2; ma++) {
                uint32_t pf[4];
                pf[0] = ph[ma][2 * ks + 0][0];   // rows g,   keys 0-7 of k16
                pf[1] = ph[ma][2 * ks + 0][1];   // rows g+8, keys 0-7
                pf[2] = ph[ma][2 * ks + 1][0];   // rows g,   keys 8-15
                pf[3] = ph[ma][2 * ks + 1][1];   // rows g+8, keys 8-15
#pragma unroll
                for (int nb = 0; nb < 4; nb++) {
                    mma_f16(o[ma][nb * 2 + 0], pf, vf[nb][0], vf[nb][1]);
                    mma_f16(o[ma][nb * 2 + 1], pf, vf[nb][2], vf[nb][3]);
                }
            }
        }
        __syncthreads();   // Vt / Ks[buf] reads complete before next overwrite
    }

    // normalize + write ctx as half
#pragma unroll
    for (int ma = 0; ma < 2; ma++) {
        const float inv0 = 1.f / l_[ma][0];
        const float inv1 = 1.f / l_[ma][1];
        const int gr = b * SS + q0 + (w & 1) * 32 + ma * 16 + (lane >> 2);
#pragma unroll
        for (int nt = 0; nt < 8; nt++) {
            const int col = head * DK + nt * 8 + (lane & 3) * 2;
            *(__half2*)(ctx + (size_t)gr * DM + col) =
                __floats2half2_rn(o[ma][nt][0] * inv0, o[ma][nt][1] * inv0);
            *(__half2*)(ctx + (size_t)(gr + 8) * DM + col) =
                __floats2half2_rn(o[ma][nt][2] * inv1, o[ma][nt][3] * inv1);
        }
    }
}

// ---------------------------------------------------------------------------
// y = LayerNorm(a + (pad ? 0 : r)) * gamma + beta; optional half copy
// ---------------------------------------------------------------------------
__global__ __launch_bounds__(256)
void add_ln_kernel(const float* __restrict__ a,
                   const float* __restrict__ r,
                   const unsigned char* __restrict__ pad,
                   const float* __restrict__ gamma,
                   const float* __restrict__ beta,
                   float* __restrict__ out,
                   __half* __restrict__ outh)
{
    __shared__ float s_sum[8], s_sq[8];
    const int row = blockIdx.x;
    const int t = threadIdx.x;

    float4 va = *(const float4*)(a + (size_t)row * DM + t * 4);
    float4 vr = *(const float4*)(r + (size_t)row * DM + t * 4);
    if (pad && pad[row]) vr = make_float4(0.f, 0.f, 0.f, 0.f);
    float4 v = make_float4(va.x + vr.x, va.y + vr.y, va.z + vr.z, va.w + vr.w);

    float sum = v.x + v.y + v.z + v.w;
    float sq  = v.x * v.x + v.y * v.y + v.z * v.z + v.w * v.w;
#pragma unroll
    for (int off = 16; off > 0; off >>= 1) {
        sum += __shfl_xor_sync(0xffffffffu, sum, off);
        sq  += __shfl_xor_sync(0xffffffffu, sq, off);
    }
    if ((t & 31) == 0) { s_sum[t >> 5] = sum; s_sq[t >> 5] = sq; }
    __syncthreads();
    sum = 0.f; sq = 0.f;
#pragma unroll
    for (int wv = 0; wv < 8; wv++) { sum += s_sum[wv]; sq += s_sq[wv]; }

    const float mean = sum * (1.f / (float)DM);
    const float var  = sq * (1.f / (float)DM) - mean * mean;
    const float rs   = rsqrtf(var + 1e-5f);

    float4 gg = *(const float4*)(gamma + t * 4);
    float4 bb = *(const float4*)(beta + t * 4);
    float4 y = make_float4((v.x - mean) * rs * gg.x + bb.x,
                           (v.y - mean) * rs * gg.y + bb.y,
                           (v.z - mean) * rs * gg.z + bb.z,
                           (v.w - mean) * rs * gg.w + bb.w);
    *(float4*)(out + (size_t)row * DM + t * 4) = y;
    if (outh) {
        __half2* oh = (__half2*)(outh + (size_t)row * DM + t * 4);
        oh[0] = __floats2half2_rn(y.x, y.y);
        oh[1] = __floats2half2_rn(y.z, y.w);
    }
}

// ---------------------------------------------------------------------------
// Launch
// ---------------------------------------------------------------------------
extern "C" void kernel_launch(void* const* d_in, const int* in_sizes, int n_in,
                              void* d_out, int out_size)
{
    const float* x          = (const float*)d_in[0];
    const int*   attn_mask  = (const int*)d_in[1];
    const unsigned char* seq_mask = (const unsigned char*)d_in[2];
    const float* Wc  = (const float*)d_in[3];
    const float* bc  = (const float*)d_in[4];
    const float* Wo  = (const float*)d_in[5];
    const float* bo  = (const float*)d_in[6];
    const float* W1  = (const float*)d_in[7];
    const float* b1  = (const float*)d_in[8];
    const float* W2  = (const float*)d_in[9];
    const float* b2  = (const float*)d_in[10];
    const float* g1  = (const float*)d_in[11];
    const float* be1 = (const float*)d_in[12];
    const float* g2  = (const float*)d_in[13];
    const float* be2 = (const float*)d_in[14];
    float* out = (float*)d_out;

    float *attnout, *x1, *ffn;
    __half *qkvh, *ctxh, *x1h, *gluh, *xh, *wct, *wot, *w1tp, *w2t;
    cudaGetSymbolAddress((void**)&qkvh,    g_qkvh);
    cudaGetSymbolAddress((void**)&ctxh,    g_ctxh);
    cudaGetSymbolAddress((void**)&attnout, g_attnout);
    cudaGetSymbolAddress((void**)&x1,      g_x1);
    cudaGetSymbolAddress((void**)&x1h,     g_x1h);
    cudaGetSymbolAddress((void**)&gluh,    g_gluh);
    cudaGetSymbolAddress((void**)&ffn,     g_ffn);
    cudaGetSymbolAddress((void**)&xh,      g_xh);
    cudaGetSymbolAddress((void**)&wct,     g_wct);
    cudaGetSymbolAddress((void**)&wot,     g_wot);
    cudaGetSymbolAddress((void**)&w1tp,    g_w1tp);
    cudaGetSymbolAddress((void**)&w2t,     g_w2t);

    cudaFuncSetAttribute(flash_attn_f16, cudaFuncAttributeMaxDynamicSharedMemorySize,
                         FLASH_SMEM);
    cudaFuncSetAttribute(f16_gemm_epi<EPI_F32>,  cudaFuncAttributeMaxDynamicSharedMemorySize, GEMM_SMEM);
    cudaFuncSetAttribute(f16_gemm_epi<EPI_HALF>, cudaFuncAttributeMaxDynamicSharedMemorySize, GEMM_SMEM);
    cudaFuncSetAttribute(f16_gemm_epi<EPI_GLU>,  cudaFuncAttributeMaxDynamicSharedMemorySize, GEMM_SMEM);

    // ---- pre-pass ----
    round_to_half<<<(ROWS * DM / 4 + 255) / 256, 256>>>(x, xh, ROWS * DM / 4);
    transpose_to_half<<<dim3(QKVC / 32, DM / 32),    dim3(32, 8)>>>(Wc, wct, DM, QKVC);
    transpose_to_half<<<dim3(DM / 32, DM / 32),      dim3(32, 8)>>>(Wo, wot, DM, DM);
    transpose_to_half_perm<<<dim3(DFF / 32, DM / 32), dim3(32, 8)>>>(W1, w1tp, DM, DFF);
    transpose_to_half<<<dim3(DM / 32, (DFF/2) / 32), dim3(32, 8)>>>(W2, w2t, DFF / 2, DM);

    // 1) qkv = x @ Wc + bc   (half output)
    f16_gemm_epi<EPI_HALF><<<dim3(QKVC / 128, ROWS / 128), 128, GEMM_SMEM>>>(
        ROWS, QKVC, DM, xh, wct, bc, nullptr, qkvh, nullptr);

    // 2) attention -> ctx (half in, half out)
    flash_attn_f16<<<dim3(SS / 64, NKV, BB), 256, FLASH_SMEM>>>(qkvh, attn_mask, ctxh);

    // 3) attn_out = ctx @ Wo + bo   (fp32)
    f16_gemm_epi<EPI_F32><<<dim3(DM / 128, ROWS / 128), 128, GEMM_SMEM>>>(
        ROWS, DM, DM, ctxh, wot, bo, attnout, nullptr, nullptr);

    // 4) x1 = LN(x + attn_out)  (fp32 + half)
    add_ln_kernel<<<ROWS, 256>>>(x, attnout, nullptr, g1, be1, x1, x1h);

    // 5+6) glu = SwiGLU(x1 @ W1 + b1) fused in epilogue (half out, pad-zeroed)
    f16_gemm_epi<EPI_GLU><<<dim3(DFF / 128, ROWS / 128), 128, GEMM_SMEM>>>(
        ROWS, DFF, DM, x1h, w1tp, b1, nullptr, gluh, seq_mask);

    // 7) ffn = glu @ W2 + b2   (fp32)
    f16_gemm_epi<EPI_F32><<<dim3(DM / 128, ROWS / 128), 128, GEMM_SMEM>>>(
        ROWS, DM, DFF / 2, gluh, w2t, b2, ffn, nullptr, nullptr);

    // 8) out = LN(x1 + (pad ? 0 : ffn)), fp32
    add_ln_kernel<<<ROWS, 256>>>(x1, ffn, seq_mask, g2, be2, out, nullptr);
}